// round 1
// baseline (speedup 1.0000x reference)
#include <cuda_runtime.h>
#include <cuda_bf16.h>
#include <cstdint>

#define SQ    2048   // sequence length
#define HDM   2048   // hidden dim
#define NH    32     // q heads
#define NKV   4      // kv heads
#define HD    128    // head dim
#define NE    16     // experts
#define ID    768    // expert intermediate
#define TOPK  4
#define NSLOT (SQ*TOPK)   // 8192

// ---------------- device scratch (static: no runtime allocation) -------------
__device__ float g_xn[SQ*HDM];
__device__ float g_qlin[SQ*NH*HD];
__device__ float g_klin[SQ*NKV*HD];
__device__ float g_vlin[SQ*NKV*HD];
__device__ float g_qh[(size_t)NH*SQ*HD];
__device__ float g_kh[(size_t)NKV*SQ*HD];
__device__ float g_vt[(size_t)NKV*HD*SQ];
__device__ float g_scores[(size_t)NH*SQ*SQ];   // 512 MB
__device__ float g_ao[SQ*NH*HD];
__device__ float g_res[SQ*HDM];
__device__ float g_h2[SQ*HDM];
__device__ int   g_tidx[NSLOT];
__device__ float g_trw[NSLOT];
__device__ int   g_counts[NE];
__device__ int   g_offs[NE];
__device__ int   g_token_of[NSLOT];
__device__ int   g_slot_of[NSLOT];
__device__ float g_gbuf[(size_t)NSLOT*ID];
__device__ float g_ubuf[(size_t)NSLOT*ID];
__device__ float g_ybuf[(size_t)NSLOT*HDM];    // 64 MB

// ---------------- reductions -------------------------------------------------
__device__ __forceinline__ float blockReduceSum(float v) {
    __shared__ float sh[8];
    int lane = threadIdx.x & 31, w = threadIdx.x >> 5;
    #pragma unroll
    for (int o = 16; o; o >>= 1) v += __shfl_xor_sync(0xffffffffu, v, o);
    if (lane == 0) sh[w] = v;
    __syncthreads();
    float r = (threadIdx.x < (blockDim.x >> 5)) ? sh[threadIdx.x] : 0.f;
    if (w == 0) {
        #pragma unroll
        for (int o = 4; o; o >>= 1) r += __shfl_xor_sync(0xffffffffu, r, o);
        if (lane == 0) sh[0] = r;
    }
    __syncthreads();
    r = sh[0];
    __syncthreads();
    return r;
}

__device__ __forceinline__ float blockReduceMax(float v) {
    __shared__ float sh[8];
    int lane = threadIdx.x & 31, w = threadIdx.x >> 5;
    #pragma unroll
    for (int o = 16; o; o >>= 1) v = fmaxf(v, __shfl_xor_sync(0xffffffffu, v, o));
    if (lane == 0) sh[w] = v;
    __syncthreads();
    float r = (threadIdx.x < (blockDim.x >> 5)) ? sh[threadIdx.x] : -3.4e38f;
    if (w == 0) {
        #pragma unroll
        for (int o = 4; o; o >>= 1) r = fmaxf(r, __shfl_xor_sync(0xffffffffu, r, o));
        if (lane == 0) sh[0] = r;
    }
    __syncthreads();
    r = sh[0];
    __syncthreads();
    return r;
}

// ---------------- rms norm ----------------------------------------------------
__global__ void rmsnorm_kernel(const float* __restrict__ x, const float* __restrict__ w,
                               float* __restrict__ out, int ncols) {
    size_t base = (size_t)blockIdx.x * ncols;
    float ss = 0.f;
    for (int i = threadIdx.x; i < ncols; i += blockDim.x) { float v = x[base + i]; ss += v * v; }
    ss = blockReduceSum(ss);
    float r = rsqrtf(ss / ncols + 1e-6f);
    for (int i = threadIdx.x; i < ncols; i += blockDim.x) out[base + i] = w[i] * x[base + i] * r;
}

// ---------------- per-head rmsnorm + rope + head-major transpose ---------------
__global__ void norm_rope_kernel(const float* __restrict__ lin, const float* __restrict__ nw,
                                 const float* __restrict__ pe, float* __restrict__ outh,
                                 int nheads) {
    int t = blockIdx.x, h = blockIdx.y, d = threadIdx.x;
    float v = lin[((size_t)t * nheads + h) * HD + d];
    float ss = v * v;
    #pragma unroll
    for (int o = 16; o; o >>= 1) ss += __shfl_xor_sync(0xffffffffu, ss, o);
    __shared__ float wsum[4];
    if ((d & 31) == 0) wsum[d >> 5] = ss;
    __syncthreads();
    float tot = wsum[0] + wsum[1] + wsum[2] + wsum[3];
    float xn = nw[d] * v * rsqrtf(tot * (1.f / HD) + 1e-6f);
    __shared__ float sh[HD];
    sh[d] = xn;
    __syncthreads();
    float c = pe[(size_t)t * HD + d];
    float s = pe[(size_t)SQ * HD + (size_t)t * HD + d];
    float rot = (d < HD / 2) ? -sh[d + HD / 2] : sh[d - HD / 2];
    outh[((size_t)h * SQ + t) * HD + d] = xn * c + rot * s;
}

// ---------------- V transpose: vt[kv][d][t] = vlin[t][kv*HD+d] -----------------
__global__ void vtrans_kernel(const float* __restrict__ vlin, float* __restrict__ vt) {
    int i = blockIdx.x * blockDim.x + threadIdx.x;
    int t = i & (SQ - 1);
    int d = (i >> 11) & (HD - 1);
    int kv = i >> 18;
    vt[i] = vlin[(size_t)t * (NKV * HD) + kv * HD + d];
}

// ---------------- generic dense batched NT SGEMM -------------------------------
// C[z][m,n] = sum_k A[z][m,k] * B[z/bdiv][n,k] ; full 128-multiple tiles assumed.
// EPI 0: store. 1: acc*scale + epi[m*lde+n] (mask). 2: acc + epi[m*lde+n] (residual).
#define BM 128
#define BN 128
#define BK 8

template<int EPI>
__global__ void __launch_bounds__(256) gemm_nt(
    const float* __restrict__ Ab, int lda, long sAz,
    const float* __restrict__ Bb, int ldb, long sBz, int bdiv,
    float* __restrict__ Cb, int ldc, long sCz,
    int K, float scale, const float* __restrict__ epi, int lde)
{
    int z = blockIdx.z;
    const float* A = Ab + (size_t)z * sAz;
    const float* B = Bb + (size_t)(z / bdiv) * sBz;
    float* C = Cb + (size_t)z * sCz;
    int m0 = blockIdx.y * BM, n0 = blockIdx.x * BN;

    __shared__ float As[BK][BM + 4];
    __shared__ float Bs[BK][BN + 4];

    int tid = threadIdx.x;
    int loadRow = tid >> 1;
    int loadK = (tid & 1) << 2;
    const float* Aload = A + (size_t)(m0 + loadRow) * lda + loadK;
    const float* Bload = B + (size_t)(n0 + loadRow) * ldb + loadK;
    int tx = tid & 15, ty = tid >> 4;

    float acc[8][8];
    #pragma unroll
    for (int i = 0; i < 8; i++)
        #pragma unroll
        for (int j = 0; j < 8; j++) acc[i][j] = 0.f;

    for (int k0 = 0; k0 < K; k0 += BK) {
        float4 av = *(const float4*)(Aload + k0);
        float4 bv = *(const float4*)(Bload + k0);
        As[loadK + 0][loadRow] = av.x; As[loadK + 1][loadRow] = av.y;
        As[loadK + 2][loadRow] = av.z; As[loadK + 3][loadRow] = av.w;
        Bs[loadK + 0][loadRow] = bv.x; Bs[loadK + 1][loadRow] = bv.y;
        Bs[loadK + 2][loadRow] = bv.z; Bs[loadK + 3][loadRow] = bv.w;
        __syncthreads();
        #pragma unroll
        for (int kk = 0; kk < BK; kk++) {
            float4 a0 = *(const float4*)&As[kk][ty * 8];
            float4 a1 = *(const float4*)&As[kk][ty * 8 + 4];
            float4 b0 = *(const float4*)&Bs[kk][tx * 8];
            float4 b1 = *(const float4*)&Bs[kk][tx * 8 + 4];
            float a[8] = {a0.x, a0.y, a0.z, a0.w, a1.x, a1.y, a1.z, a1.w};
            float b[8] = {b0.x, b0.y, b0.z, b0.w, b1.x, b1.y, b1.z, b1.w};
            #pragma unroll
            for (int i = 0; i < 8; i++)
                #pragma unroll
                for (int j = 0; j < 8; j++) acc[i][j] += a[i] * b[j];
        }
        __syncthreads();
    }

    #pragma unroll
    for (int i = 0; i < 8; i++) {
        int m = m0 + ty * 8 + i;
        float* crow = C + (size_t)m * ldc + n0 + tx * 8;
        const float* erow = (EPI != 0) ? (epi + (size_t)m * lde + n0 + tx * 8) : nullptr;
        #pragma unroll
        for (int j = 0; j < 8; j++) {
            float v = acc[i][j];
            if (EPI == 1) v = v * scale + erow[j];
            if (EPI == 2) v = v + erow[j];
            crow[j] = v;
        }
    }
}

// ---------------- ragged expert NT SGEMM (optional row gather) ------------------
template<int GATHER>
__global__ void __launch_bounds__(256) gemm_expert(
    const float* __restrict__ Ab, int lda,
    const float* __restrict__ Bb, long sBz, int ldb,
    float* __restrict__ Cb, int ldc,
    int K,
    const int* __restrict__ counts, const int* __restrict__ offs,
    const int* __restrict__ token_of)
{
    int z = blockIdx.z;
    int Me = counts[z];
    int m0 = blockIdx.y * BM;
    if (m0 >= Me) return;
    int off = offs[z];
    const float* B = Bb + (size_t)z * sBz;

    __shared__ float As[BK][BM + 4];
    __shared__ float Bs[BK][BN + 4];

    int tid = threadIdx.x;
    int loadRow = tid >> 1;
    int loadK = (tid & 1) << 2;
    int n0 = blockIdx.x * BN;

    int rlocal = m0 + loadRow;
    bool avalid = rlocal < Me;
    int arow = 0;
    if (avalid) arow = GATHER ? token_of[off + rlocal] : (off + rlocal);
    const float* Aload = Ab + (size_t)arow * lda + loadK;
    const float* Bload = B + (size_t)(n0 + loadRow) * ldb + loadK;
    int tx = tid & 15, ty = tid >> 4;

    float acc[8][8];
    #pragma unroll
    for (int i = 0; i < 8; i++)
        #pragma unroll
        for (int j = 0; j < 8; j++) acc[i][j] = 0.f;

    for (int k0 = 0; k0 < K; k0 += BK) {
        float4 av = avalid ? *(const float4*)(Aload + k0) : make_float4(0.f, 0.f, 0.f, 0.f);
        float4 bv = *(const float4*)(Bload + k0);
        As[loadK + 0][loadRow] = av.x; As[loadK + 1][loadRow] = av.y;
        As[loadK + 2][loadRow] = av.z; As[loadK + 3][loadRow] = av.w;
        Bs[loadK + 0][loadRow] = bv.x; Bs[loadK + 1][loadRow] = bv.y;
        Bs[loadK + 2][loadRow] = bv.z; Bs[loadK + 3][loadRow] = bv.w;
        __syncthreads();
        #pragma unroll
        for (int kk = 0; kk < BK; kk++) {
            float4 a0 = *(const float4*)&As[kk][ty * 8];
            float4 a1 = *(const float4*)&As[kk][ty * 8 + 4];
            float4 b0 = *(const float4*)&Bs[kk][tx * 8];
            float4 b1 = *(const float4*)&Bs[kk][tx * 8 + 4];
            float a[8] = {a0.x, a0.y, a0.z, a0.w, a1.x, a1.y, a1.z, a1.w};
            float b[8] = {b0.x, b0.y, b0.z, b0.w, b1.x, b1.y, b1.z, b1.w};
            #pragma unroll
            for (int i = 0; i < 8; i++)
                #pragma unroll
                for (int j = 0; j < 8; j++) acc[i][j] += a[i] * b[j];
        }
        __syncthreads();
    }

    #pragma unroll
    for (int i = 0; i < 8; i++) {
        int mloc = m0 + ty * 8 + i;
        if (mloc < Me) {
            float* crow = Cb + (size_t)(off + mloc) * ldc + n0 + tx * 8;
            #pragma unroll
            for (int j = 0; j < 8; j++) crow[j] = acc[i][j];
        }
    }
}

// ---------------- row softmax over 2048-wide rows ------------------------------
__global__ void softmax_kernel(float* __restrict__ data) {
    size_t base = (size_t)blockIdx.x * SQ;
    float v[8];
    float mx = -3.4e38f;
    #pragma unroll
    for (int j = 0; j < 8; j++) {
        v[j] = data[base + threadIdx.x + j * 256];
        mx = fmaxf(mx, v[j]);
    }
    mx = blockReduceMax(mx);
    float sum = 0.f;
    #pragma unroll
    for (int j = 0; j < 8; j++) { v[j] = __expf(v[j] - mx); sum += v[j]; }
    sum = blockReduceSum(sum);
    float inv = 1.f / sum;
    #pragma unroll
    for (int j = 0; j < 8; j++) data[base + threadIdx.x + j * 256] = v[j] * inv;
}

// ---------------- router: logits -> softmax -> top4 ----------------------------
__global__ void gate_topk_kernel(const float* __restrict__ h2, const float* __restrict__ gw,
                                 int* __restrict__ oidx, float* __restrict__ orw) {
    int t = blockIdx.x;
    int e = threadIdx.x >> 4, l = threadIdx.x & 15;
    const float* hr = h2 + (size_t)t * HDM;
    const float* wr = gw + (size_t)e * HDM;
    float p = 0.f;
    for (int k = l; k < HDM; k += 16) p += hr[k] * wr[k];
    #pragma unroll
    for (int o = 8; o; o >>= 1) p += __shfl_xor_sync(0xffffffffu, p, o);
    __shared__ float slog[NE];
    if (l == 0) slog[e] = p;
    __syncthreads();
    if (threadIdx.x == 0) {
        float pr[NE];
        float mx = -3.4e38f;
        for (int i = 0; i < NE; i++) { pr[i] = slog[i]; mx = fmaxf(mx, pr[i]); }
        float sum = 0.f;
        for (int i = 0; i < NE; i++) { pr[i] = __expf(pr[i] - mx); sum += pr[i]; }
        float inv = 1.f / sum;
        for (int i = 0; i < NE; i++) pr[i] *= inv;
        int sel[TOPK]; float sv[TOPK]; float wsum = 0.f;
        for (int k = 0; k < TOPK; k++) {
            int best = 0; float bv = -1.f;
            for (int i = 0; i < NE; i++)
                if (pr[i] > bv) { bv = pr[i]; best = i; }
            sel[k] = best; sv[k] = bv; wsum += bv; pr[best] = -2.f;
        }
        float winv = 1.f / wsum;
        for (int k = 0; k < TOPK; k++) { oidx[t * TOPK + k] = sel[k]; orw[t * TOPK + k] = sv[k] * winv; }
    }
}

// ---------------- deterministic stable counting sort into expert lists ---------
__global__ void route_kernel(const int* __restrict__ idx, int* __restrict__ counts,
                             int* __restrict__ offs, int* __restrict__ token_of,
                             int* __restrict__ slot_of) {
    int c = threadIdx.x;  // 32 threads, 256 entries each
    int start = c * (NSLOT / 32);
    int cnt[NE];
    #pragma unroll
    for (int e = 0; e < NE; e++) cnt[e] = 0;
    for (int i = 0; i < NSLOT / 32; i++) cnt[idx[start + i]]++;
    __shared__ int scnt[32][NE];
    __shared__ int sbase[32][NE];
    for (int e = 0; e < NE; e++) scnt[c][e] = cnt[e];
    __syncthreads();
    if (c == 0) {
        int off = 0;
        for (int e = 0; e < NE; e++) {
            offs[e] = off;
            int run = off;
            for (int cc = 0; cc < 32; cc++) { sbase[cc][e] = run; run += scnt[cc][e]; }
            counts[e] = run - off;
            off = run;
        }
    }
    __syncthreads();
    int base[NE];
    #pragma unroll
    for (int e = 0; e < NE; e++) base[e] = sbase[c][e];
    for (int i = 0; i < NSLOT / 32; i++) {
        int entry = start + i;
        int e = idx[entry];
        int pos = base[e]++;
        token_of[pos] = entry >> 2;
        slot_of[entry] = pos;
    }
}

// ---------------- silu(g)*u elementwise ----------------------------------------
__global__ void silu_mul_kernel(float* __restrict__ g, const float* __restrict__ u) {
    size_t i = (size_t)blockIdx.x * blockDim.x + threadIdx.x;
    float x = g[i];
    float s = x / (1.f + __expf(-x));
    g[i] = s * u[i];
}

// ---------------- final combine: out = res + sum_k rw_k * y[slot_k] ------------
__global__ void combine_kernel(const float* __restrict__ res, const float* __restrict__ ybuf,
                               const int* __restrict__ slot_of, const float* __restrict__ rw,
                               float* __restrict__ out) {
    int t = blockIdx.x;
    int s0 = slot_of[t * 4 + 0], s1 = slot_of[t * 4 + 1], s2 = slot_of[t * 4 + 2], s3 = slot_of[t * 4 + 3];
    float w0 = rw[t * 4 + 0], w1 = rw[t * 4 + 1], w2 = rw[t * 4 + 2], w3 = rw[t * 4 + 3];
    const float* y0 = ybuf + (size_t)s0 * HDM;
    const float* y1 = ybuf + (size_t)s1 * HDM;
    const float* y2 = ybuf + (size_t)s2 * HDM;
    const float* y3 = ybuf + (size_t)s3 * HDM;
    size_t base = (size_t)t * HDM;
    for (int i = threadIdx.x; i < HDM; i += blockDim.x)
        out[base + i] = res[base + i] + w0 * y0[i] + w1 * y1[i] + w2 * y2[i] + w3 * y3[i];
}

// =================================================================================
extern "C" void kernel_launch(void* const* d_in, const int* in_sizes, int n_in,
                              void* d_out, int out_size) {
    const float* x    = (const float*)d_in[0];
    const float* pe   = (const float*)d_in[1];
    const float* mask = (const float*)d_in[2];
    const float* q_w  = (const float*)d_in[3];
    const float* k_w  = (const float*)d_in[4];
    const float* v_w  = (const float*)d_in[5];
    const float* o_w  = (const float*)d_in[6];
    const float* q_nw = (const float*)d_in[7];
    const float* k_nw = (const float*)d_in[8];
    const float* ln1  = (const float*)d_in[9];
    const float* ln2  = (const float*)d_in[10];
    const float* gw   = (const float*)d_in[11];
    const float* gpw  = (const float*)d_in[12];
    const float* upw  = (const float*)d_in[13];
    const float* dpw  = (const float*)d_in[14];
    float* out = (float*)d_out;

    float *xn, *qlin, *klin, *vlin, *qh, *kh, *vt, *scores, *ao, *res, *h2, *gbuf, *ubuf, *ybuf, *trw;
    int *tidx, *counts, *offs, *token_of, *slot_of;
    cudaGetSymbolAddress((void**)&xn, g_xn);
    cudaGetSymbolAddress((void**)&qlin, g_qlin);
    cudaGetSymbolAddress((void**)&klin, g_klin);
    cudaGetSymbolAddress((void**)&vlin, g_vlin);
    cudaGetSymbolAddress((void**)&qh, g_qh);
    cudaGetSymbolAddress((void**)&kh, g_kh);
    cudaGetSymbolAddress((void**)&vt, g_vt);
    cudaGetSymbolAddress((void**)&scores, g_scores);
    cudaGetSymbolAddress((void**)&ao, g_ao);
    cudaGetSymbolAddress((void**)&res, g_res);
    cudaGetSymbolAddress((void**)&h2, g_h2);
    cudaGetSymbolAddress((void**)&gbuf, g_gbuf);
    cudaGetSymbolAddress((void**)&ubuf, g_ubuf);
    cudaGetSymbolAddress((void**)&ybuf, g_ybuf);
    cudaGetSymbolAddress((void**)&trw, g_trw);
    cudaGetSymbolAddress((void**)&tidx, g_tidx);
    cudaGetSymbolAddress((void**)&counts, g_counts);
    cudaGetSymbolAddress((void**)&offs, g_offs);
    cudaGetSymbolAddress((void**)&token_of, g_token_of);
    cudaGetSymbolAddress((void**)&slot_of, g_slot_of);

    const float scale = 0.08838834764831845f;  // 1/sqrt(128)

    // 1. ln1
    rmsnorm_kernel<<<SQ, 256>>>(x, ln1, xn, HDM);
    // 2-4. QKV projections (NT: weights are [out,in])
    gemm_nt<0><<<dim3(NH * HD / BN, SQ / BM, 1), 256>>>(xn, HDM, 0, q_w, HDM, 0, 1, qlin, NH * HD, 0, HDM, 0.f, nullptr, 0);
    gemm_nt<0><<<dim3(NKV * HD / BN, SQ / BM, 1), 256>>>(xn, HDM, 0, k_w, HDM, 0, 1, klin, NKV * HD, 0, HDM, 0.f, nullptr, 0);
    gemm_nt<0><<<dim3(NKV * HD / BN, SQ / BM, 1), 256>>>(xn, HDM, 0, v_w, HDM, 0, 1, vlin, NKV * HD, 0, HDM, 0.f, nullptr, 0);
    // 5-6. per-head rmsnorm + rope, transpose to head-major
    norm_rope_kernel<<<dim3(SQ, NH), HD>>>(qlin, q_nw, pe, qh, NH);
    norm_rope_kernel<<<dim3(SQ, NKV), HD>>>(klin, k_nw, pe, kh, NKV);
    // 7. V transpose -> vt[kv][d][t]
    vtrans_kernel<<<(NKV * HD * SQ) / 256, 256>>>(vlin, vt);
    // 8. scores = q @ k^T * scale + mask   (batched over 32 heads, GQA bdiv=8)
    gemm_nt<1><<<dim3(SQ / BN, SQ / BM, NH), 256>>>(qh, HD, (long)SQ * HD, kh, HD, (long)SQ * HD, 8,
                                                    scores, SQ, (long)SQ * SQ, HD, scale, mask, SQ);
    // 9. softmax rows
    softmax_kernel<<<NH * SQ, 256>>>(scores);
    // 10. ao = P @ V  (B = vt viewed as [HD, SQ] NT)
    gemm_nt<0><<<dim3(1, SQ / BM, NH), 256>>>(scores, SQ, (long)SQ * SQ, vt, SQ, (long)HD * SQ, 8,
                                              ao, NH * HD, 128, SQ, 0.f, nullptr, 0);
    // 11. O projection + residual
    gemm_nt<2><<<dim3(HDM / BN, SQ / BM, 1), 256>>>(ao, NH * HD, 0, o_w, NH * HD, 0, 1,
                                                    res, HDM, 0, NH * HD, 0.f, x, HDM);
    // 12. ln2
    rmsnorm_kernel<<<SQ, 256>>>(res, ln2, h2, HDM);
    // 13. router
    gate_topk_kernel<<<SQ, 256>>>(h2, gw, tidx, trw);
    // 14. deterministic routing sort
    route_kernel<<<1, 32>>>(tidx, counts, offs, token_of, slot_of);
    // 15-16. expert gate/up projections (gathered rows)
    gemm_expert<1><<<dim3(ID / BN, SQ / BM, NE), 256>>>(h2, HDM, gpw, (long)ID * HDM, HDM, gbuf, ID, HDM, counts, offs, token_of);
    gemm_expert<1><<<dim3(ID / BN, SQ / BM, NE), 256>>>(h2, HDM, upw, (long)ID * HDM, HDM, ubuf, ID, HDM, counts, offs, token_of);
    // 17. silu(g)*u
    silu_mul_kernel<<<(NSLOT * ID) / 256, 256>>>(gbuf, ubuf);
    // 18. expert down projection -> per-slot outputs
    gemm_expert<0><<<dim3(HDM / BN, SQ / BM, NE), 256>>>(gbuf, ID, dpw, (long)HDM * ID, ID, ybuf, HDM, ID, counts, offs, token_of);
    // 19. weighted combine + residual
    combine_kernel<<<SQ, 256>>>(res, ybuf, slot_of, trw, out);
}

// round 2
// speedup vs baseline: 2.2471x; 2.2471x over previous
#include <cuda_runtime.h>
#include <cuda_bf16.h>
#include <cstdint>

#define SQ    2048
#define HDM   2048
#define NH    32
#define NKV   4
#define HD    128
#define NE    16
#define ID    768
#define TOPK  4
#define NSLOT (SQ*TOPK)
#define QKVN  (NH*HD + 2*NKV*HD)   // 5120
#define GUN   (2*ID)               // 1536

typedef __nv_bfloat16 bf16;

// ---------------- device scratch -------------------------------------------
// weights (split bf16)
__device__ bf16 g_wqkv_h[(size_t)QKVN*HDM],      g_wqkv_l[(size_t)QKVN*HDM];
__device__ bf16 g_wo_h[(size_t)HDM*NH*HD],       g_wo_l[(size_t)HDM*NH*HD];
__device__ bf16 g_wgu_h[(size_t)NE*GUN*HDM],     g_wgu_l[(size_t)NE*GUN*HDM];
__device__ bf16 g_wd_h[(size_t)NE*HDM*ID],       g_wd_l[(size_t)NE*HDM*ID];
// activations
__device__ bf16 g_xn_h[(size_t)SQ*HDM],          g_xn_l[(size_t)SQ*HDM];
__device__ float g_qkvlin[(size_t)SQ*QKVN];
__device__ bf16 g_qh_h[(size_t)NH*SQ*HD],        g_qh_l[(size_t)NH*SQ*HD];
__device__ bf16 g_kh_h[(size_t)NKV*SQ*HD],       g_kh_l[(size_t)NKV*SQ*HD];
__device__ bf16 g_vt_h[(size_t)NKV*HD*SQ],       g_vt_l[(size_t)NKV*HD*SQ];
__device__ float g_scores[(size_t)NH*SQ*SQ];     // 512 MB
__device__ bf16 g_p_h[(size_t)NH*SQ*SQ],         g_p_l[(size_t)NH*SQ*SQ];   // 512 MB
__device__ bf16 g_ao_h[(size_t)SQ*NH*HD],        g_ao_l[(size_t)SQ*NH*HD];
__device__ float g_res[SQ*HDM];
__device__ float g_h2f[SQ*HDM];
__device__ bf16 g_h2_h[(size_t)SQ*HDM],          g_h2_l[(size_t)SQ*HDM];
__device__ float g_gu[(size_t)NSLOT*GUN];
__device__ bf16 g_g_h[(size_t)NSLOT*ID],         g_g_l[(size_t)NSLOT*ID];
__device__ float g_ybuf[(size_t)NSLOT*HDM];
// routing
__device__ int   g_tidx[NSLOT];
__device__ float g_trw[NSLOT];
__device__ int   g_counts[NE];
__device__ int   g_offs[NE];
__device__ int   g_token_of[NSLOT];
__device__ int   g_slot_of[NSLOT];

// ---------------- helpers ----------------------------------------------------
__device__ __forceinline__ void splitf(float v, bf16& h, bf16& l) {
    h = __float2bfloat16(v);
    l = __float2bfloat16(v - __bfloat162float(h));
}

__device__ __forceinline__ void ldsm4(uint32_t r[4], uint32_t addr) {
    asm volatile("ldmatrix.sync.aligned.m8n8.x4.shared.b16 {%0,%1,%2,%3},[%4];"
        : "=r"(r[0]), "=r"(r[1]), "=r"(r[2]), "=r"(r[3]) : "r"(addr));
}

__device__ __forceinline__ void mma16816(float c[4], const uint32_t a[4], const uint32_t b[2]) {
    asm volatile("mma.sync.aligned.m16n8k16.row.col.f32.bf16.bf16.f32 "
        "{%0,%1,%2,%3},{%4,%5,%6,%7},{%8,%9},{%0,%1,%2,%3};"
        : "+f"(c[0]), "+f"(c[1]), "+f"(c[2]), "+f"(c[3])
        : "r"(a[0]), "r"(a[1]), "r"(a[2]), "r"(a[3]), "r"(b[0]), "r"(b[1]));
}

__device__ __forceinline__ float blockReduceSum(float v) {
    __shared__ float sh[8];
    int lane = threadIdx.x & 31, w = threadIdx.x >> 5;
    #pragma unroll
    for (int o = 16; o; o >>= 1) v += __shfl_xor_sync(0xffffffffu, v, o);
    if (lane == 0) sh[w] = v;
    __syncthreads();
    float r = (threadIdx.x < (blockDim.x >> 5)) ? sh[threadIdx.x] : 0.f;
    if (w == 0) {
        #pragma unroll
        for (int o = 4; o; o >>= 1) r += __shfl_xor_sync(0xffffffffu, r, o);
        if (lane == 0) sh[0] = r;
    }
    __syncthreads();
    r = sh[0];
    __syncthreads();
    return r;
}

__device__ __forceinline__ float blockReduceMax(float v) {
    __shared__ float sh[8];
    int lane = threadIdx.x & 31, w = threadIdx.x >> 5;
    #pragma unroll
    for (int o = 16; o; o >>= 1) v = fmaxf(v, __shfl_xor_sync(0xffffffffu, v, o));
    if (lane == 0) sh[w] = v;
    __syncthreads();
    float r = (threadIdx.x < (blockDim.x >> 5)) ? sh[threadIdx.x] : -3.4e38f;
    if (w == 0) {
        #pragma unroll
        for (int o = 4; o; o >>= 1) r = fmaxf(r, __shfl_xor_sync(0xffffffffu, r, o));
        if (lane == 0) sh[0] = r;
    }
    __syncthreads();
    r = sh[0];
    __syncthreads();
    return r;
}

// ---------------- weight split conversions ------------------------------------
__global__ void split_kernel(const float* __restrict__ in, bf16* __restrict__ hi,
                             bf16* __restrict__ lo, size_t n) {
    size_t i = ((size_t)blockIdx.x * blockDim.x + threadIdx.x) * 4;
    if (i >= n) return;
    float4 v = *(const float4*)(in + i);
    bf16 h0, l0, h1, l1, h2, l2, h3, l3;
    splitf(v.x, h0, l0); splitf(v.y, h1, l1); splitf(v.z, h2, l2); splitf(v.w, h3, l3);
    *(__nv_bfloat162*)(hi + i)     = __nv_bfloat162(h0, h1);
    *(__nv_bfloat162*)(hi + i + 2) = __nv_bfloat162(h2, h3);
    *(__nv_bfloat162*)(lo + i)     = __nv_bfloat162(l0, l1);
    *(__nv_bfloat162*)(lo + i + 2) = __nv_bfloat162(l2, l3);
}

// gate_proj_w + up_proj_w -> interleaved per-expert [gate rows | up rows]
__global__ void split_gu_kernel(const float* __restrict__ gp, const float* __restrict__ up,
                                bf16* __restrict__ hi, bf16* __restrict__ lo) {
    size_t i = ((size_t)blockIdx.x * blockDim.x + threadIdx.x) * 4;   // over NE*ID*HDM
    if (i >= (size_t)NE * ID * HDM) return;
    size_t e = i / ((size_t)ID * HDM);
    size_t rem = i - e * (size_t)ID * HDM;
    size_t dg = e * (size_t)GUN * HDM + rem;
    size_t du = dg + (size_t)ID * HDM;
    float4 vg = *(const float4*)(gp + i);
    float4 vu = *(const float4*)(up + i);
    bf16 h, l;
    splitf(vg.x, h, l); hi[dg] = h; lo[dg] = l;
    splitf(vg.y, h, l); hi[dg+1] = h; lo[dg+1] = l;
    splitf(vg.z, h, l); hi[dg+2] = h; lo[dg+2] = l;
    splitf(vg.w, h, l); hi[dg+3] = h; lo[dg+3] = l;
    splitf(vu.x, h, l); hi[du] = h; lo[du] = l;
    splitf(vu.y, h, l); hi[du+1] = h; lo[du+1] = l;
    splitf(vu.z, h, l); hi[du+2] = h; lo[du+2] = l;
    splitf(vu.w, h, l); hi[du+3] = h; lo[du+3] = l;
}

// ---------------- rms norm ------------------------------------------------------
__global__ void rmsnorm_kernel(const float* __restrict__ x, const float* __restrict__ w,
                               float* __restrict__ outf, bf16* __restrict__ oh,
                               bf16* __restrict__ ol, int ncols) {
    size_t base = (size_t)blockIdx.x * ncols;
    float ss = 0.f;
    for (int i = threadIdx.x; i < ncols; i += blockDim.x) { float v = x[base + i]; ss += v * v; }
    ss = blockReduceSum(ss);
    float r = rsqrtf(ss / ncols + 1e-6f);
    for (int i = threadIdx.x; i < ncols; i += blockDim.x) {
        float v = w[i] * x[base + i] * r;
        if (outf) outf[base + i] = v;
        if (oh) { bf16 h, l; splitf(v, h, l); oh[base + i] = h; ol[base + i] = l; }
    }
}

// ---------------- per-head rmsnorm + rope, split output -------------------------
__global__ void norm_rope_kernel(const float* __restrict__ lin, int colbase,
                                 const float* __restrict__ nw, const float* __restrict__ pe,
                                 bf16* __restrict__ oh, bf16* __restrict__ ol) {
    int t = blockIdx.x, h = blockIdx.y, d = threadIdx.x;
    float v = lin[(size_t)t * QKVN + colbase + h * HD + d];
    float ss = v * v;
    #pragma unroll
    for (int o = 16; o; o >>= 1) ss += __shfl_xor_sync(0xffffffffu, ss, o);
    __shared__ float wsum[4];
    if ((d & 31) == 0) wsum[d >> 5] = ss;
    __syncthreads();
    float tot = wsum[0] + wsum[1] + wsum[2] + wsum[3];
    float xn = nw[d] * v * rsqrtf(tot * (1.f / HD) + 1e-6f);
    __shared__ float sh[HD];
    sh[d] = xn;
    __syncthreads();
    float c = pe[(size_t)t * HD + d];
    float s = pe[(size_t)SQ * HD + (size_t)t * HD + d];
    float rot = (d < HD / 2) ? -sh[d + HD / 2] : sh[d - HD / 2];
    float o = xn * c + rot * s;
    size_t idx = ((size_t)h * SQ + t) * HD + d;
    bf16 hh, ll; splitf(o, hh, ll);
    oh[idx] = hh; ol[idx] = ll;
}

// ---------------- V transpose + split -------------------------------------------
__global__ void vtrans_kernel(const float* __restrict__ qkvlin, bf16* __restrict__ vh,
                              bf16* __restrict__ vl) {
    int i = blockIdx.x * blockDim.x + threadIdx.x;
    int t = i & (SQ - 1);
    int d = (i >> 11) & (HD - 1);
    int kv = i >> 18;
    float v = qkvlin[(size_t)t * QKVN + (NH * HD + NKV * HD) + kv * HD + d];
    bf16 h, l; splitf(v, h, l);
    vh[i] = h; vl[i] = l;
}

// ---------------- bf16x3 tensor-core GEMM ---------------------------------------
// C[z][m,n] = sum_k A[z][m,k]*B[z/bdiv][n,k] with A,B as (hi,lo) bf16 pairs.
// MODE 0: dense. 1: ragged A rows gathered via token_of. 2: ragged direct rows.
// EPI  0: fp32 store. 1: fp32 acc*scale+mask. 2: fp32 acc+residual. 3: bf16 hi/lo out.
#define BM 128
#define BN 128
#define BK 32
#define BKP 40   // padded smem row (bf16 elems); stride 80B is ldmatrix conflict-free

template<int EPI, int MODE>
__global__ void __launch_bounds__(256, 1) gemm_mma(
    const bf16* __restrict__ Ah, const bf16* __restrict__ Al, int lda, long sAz,
    const bf16* __restrict__ Bh, const bf16* __restrict__ Bl, int ldb, long sBz, int bdiv,
    float* __restrict__ Cf, bf16* __restrict__ Ch, bf16* __restrict__ Cl, int ldc, long sCz,
    int K, float scale, const float* __restrict__ epi, int lde,
    const int* __restrict__ counts, const int* __restrict__ offs,
    const int* __restrict__ token_of)
{
    int z = blockIdx.z;
    int m0 = blockIdx.y * BM, n0 = blockIdx.x * BN;
    int Me = 0x7fffffff, off = 0;
    if (MODE != 0) { Me = counts[z]; if (m0 >= Me) return; off = offs[z]; }

    const bf16* Ahp = Ah; const bf16* Alp = Al;
    if (MODE == 0) { Ahp += (size_t)z * sAz; Alp += (size_t)z * sAz; }
    const bf16* Bhp = Bh + (size_t)(z / bdiv) * sBz;
    const bf16* Blp = Bl + (size_t)(z / bdiv) * sBz;

    __shared__ bf16 sA[2][BM * BKP];
    __shared__ bf16 sB[2][BN * BKP];

    int tid = threadIdx.x;
    int lr = tid >> 2;            // 0..63
    int lc = (tid & 3) * 8;       // k element offset of this thread's uint4

    // A row setup (rows lr and lr+64)
    int rl0 = m0 + lr, rl1 = m0 + lr + 64;
    bool av0 = true, av1 = true;
    size_t ar0, ar1;
    if (MODE == 1) {
        av0 = rl0 < Me; av1 = rl1 < Me;
        ar0 = av0 ? (size_t)token_of[off + rl0] : 0;
        ar1 = av1 ? (size_t)token_of[off + rl1] : 0;
    } else if (MODE == 2) {
        av0 = rl0 < Me; av1 = rl1 < Me;
        ar0 = av0 ? (size_t)(off + rl0) : 0;
        ar1 = av1 ? (size_t)(off + rl1) : 0;
    } else { ar0 = rl0; ar1 = rl1; }
    size_t offA0 = ar0 * (size_t)lda + lc;
    size_t offA1 = ar1 * (size_t)lda + lc;
    size_t offB0 = (size_t)(n0 + lr) * ldb + lc;
    size_t offB1 = (size_t)(n0 + lr + 64) * ldb + lc;

    const int warp = tid >> 5, lane = tid & 31;
    const int wm = (warp >> 1) * 32;
    const int wn = (warp & 1) * 64;
    const int ldr = lane & 15;
    const int ldc8 = (lane >> 4) * 8;

    uint32_t sAh = (uint32_t)__cvta_generic_to_shared(&sA[0][0]);
    uint32_t sAl = (uint32_t)__cvta_generic_to_shared(&sA[1][0]);
    uint32_t sBh = (uint32_t)__cvta_generic_to_shared(&sB[0][0]);
    uint32_t sBl = (uint32_t)__cvta_generic_to_shared(&sB[1][0]);

    float acc[2][8][4];
    #pragma unroll
    for (int i = 0; i < 2; i++)
        #pragma unroll
        for (int j = 0; j < 8; j++)
            #pragma unroll
            for (int q = 0; q < 4; q++) acc[i][j][q] = 0.f;

    const uint4 z4 = make_uint4(0u, 0u, 0u, 0u);
    uint4 rAh0, rAh1, rAl0, rAl1, rBh0, rBh1, rBl0, rBl1;

    // initial fetch (k0 = 0)
    rAh0 = av0 ? *(const uint4*)(Ahp + offA0) : z4;
    rAh1 = av1 ? *(const uint4*)(Ahp + offA1) : z4;
    rAl0 = av0 ? *(const uint4*)(Alp + offA0) : z4;
    rAl1 = av1 ? *(const uint4*)(Alp + offA1) : z4;
    rBh0 = *(const uint4*)(Bhp + offB0);
    rBh1 = *(const uint4*)(Bhp + offB1);
    rBl0 = *(const uint4*)(Blp + offB0);
    rBl1 = *(const uint4*)(Blp + offB1);

    for (int k0 = 0; k0 < K; k0 += BK) {
        // store prefetched tile
        *(uint4*)&sA[0][lr * BKP + lc] = rAh0;
        *(uint4*)&sA[0][(lr + 64) * BKP + lc] = rAh1;
        *(uint4*)&sA[1][lr * BKP + lc] = rAl0;
        *(uint4*)&sA[1][(lr + 64) * BKP + lc] = rAl1;
        *(uint4*)&sB[0][lr * BKP + lc] = rBh0;
        *(uint4*)&sB[0][(lr + 64) * BKP + lc] = rBh1;
        *(uint4*)&sB[1][lr * BKP + lc] = rBl0;
        *(uint4*)&sB[1][(lr + 64) * BKP + lc] = rBl1;
        __syncthreads();

        if (k0 + BK < K) {
            int kn = k0 + BK;
            rAh0 = av0 ? *(const uint4*)(Ahp + offA0 + kn) : z4;
            rAh1 = av1 ? *(const uint4*)(Ahp + offA1 + kn) : z4;
            rAl0 = av0 ? *(const uint4*)(Alp + offA0 + kn) : z4;
            rAl1 = av1 ? *(const uint4*)(Alp + offA1 + kn) : z4;
            rBh0 = *(const uint4*)(Bhp + offB0 + kn);
            rBh1 = *(const uint4*)(Bhp + offB1 + kn);
            rBl0 = *(const uint4*)(Blp + offB0 + kn);
            rBl1 = *(const uint4*)(Blp + offB1 + kn);
        }

        #pragma unroll
        for (int ks = 0; ks < 2; ks++) {
            int kk = ks * 16 + ldc8;
            uint32_t ah[2][4], al[2][4], bh[8][2], bl[8][2];
            #pragma unroll
            for (int mt = 0; mt < 2; mt++) {
                uint32_t adr = ((wm + mt * 16 + ldr) * BKP + kk) * 2;
                ldsm4(ah[mt], sAh + adr);
                ldsm4(al[mt], sAl + adr);
            }
            #pragma unroll
            for (int np = 0; np < 4; np++) {
                uint32_t adr = ((wn + np * 16 + ldr) * BKP + kk) * 2;
                uint32_t r[4];
                ldsm4(r, sBh + adr);
                bh[np*2][0] = r[0]; bh[np*2+1][0] = r[1]; bh[np*2][1] = r[2]; bh[np*2+1][1] = r[3];
                ldsm4(r, sBl + adr);
                bl[np*2][0] = r[0]; bl[np*2+1][0] = r[1]; bl[np*2][1] = r[2]; bl[np*2+1][1] = r[3];
            }
            #pragma unroll
            for (int mt = 0; mt < 2; mt++)
                #pragma unroll
                for (int nt = 0; nt < 8; nt++) {
                    mma16816(acc[mt][nt], ah[mt], bh[nt]);
                    mma16816(acc[mt][nt], ah[mt], bl[nt]);
                    mma16816(acc[mt][nt], al[mt], bh[nt]);
                }
        }
        __syncthreads();
    }

    // ---------------- epilogue ----------------
    int er = lane >> 2;
    int ec = (lane & 3) * 2;
    #pragma unroll
    for (int mt = 0; mt < 2; mt++) {
        #pragma unroll
        for (int h = 0; h < 2; h++) {
            int mloc = m0 + wm + mt * 16 + h * 8 + er;   // local row (== global row if dense)
            bool mvalid = (MODE == 0) || (mloc < Me);
            if (!mvalid) continue;
            size_t crow = (MODE == 0) ? (size_t)mloc : (size_t)(off + mloc);
            #pragma unroll
            for (int nt = 0; nt < 8; nt++) {
                int col = n0 + wn + nt * 8 + ec;
                float v0 = acc[mt][nt][h * 2 + 0];
                float v1 = acc[mt][nt][h * 2 + 1];
                if (EPI == 1) {
                    float2 mk = *(const float2*)(epi + (size_t)mloc * lde + col);
                    v0 = v0 * scale + mk.x;
                    v1 = v1 * scale + mk.y;
                } else if (EPI == 2) {
                    float2 rr = *(const float2*)(epi + (size_t)mloc * lde + col);
                    v0 += rr.x; v1 += rr.y;
                }
                if (EPI == 3) {
                    bf16 h0, l0, h1, l1;
                    splitf(v0, h0, l0); splitf(v1, h1, l1);
                    size_t ci = (size_t)z * sCz + crow * ldc + col;
                    *(__nv_bfloat162*)(Ch + ci) = __nv_bfloat162(h0, h1);
                    *(__nv_bfloat162*)(Cl + ci) = __nv_bfloat162(l0, l1);
                } else {
                    size_t ci = (size_t)z * sCz + crow * ldc + col;
                    *(float2*)(Cf + ci) = make_float2(v0, v1);
                }
            }
        }
    }
}

// ---------------- softmax: fp32 scores -> bf16 hi/lo P ---------------------------
__global__ void softmax_kernel(const float* __restrict__ data, bf16* __restrict__ ph,
                               bf16* __restrict__ pl) {
    size_t base = (size_t)blockIdx.x * SQ;
    float v[8];
    float mx = -3.4e38f;
    #pragma unroll
    for (int j = 0; j < 8; j++) {
        v[j] = data[base + threadIdx.x + j * 256];
        mx = fmaxf(mx, v[j]);
    }
    mx = blockReduceMax(mx);
    float sum = 0.f;
    #pragma unroll
    for (int j = 0; j < 8; j++) { v[j] = __expf(v[j] - mx); sum += v[j]; }
    sum = blockReduceSum(sum);
    float inv = 1.f / sum;
    #pragma unroll
    for (int j = 0; j < 8; j++) {
        float p = v[j] * inv;
        bf16 h, l; splitf(p, h, l);
        ph[base + threadIdx.x + j * 256] = h;
        pl[base + threadIdx.x + j * 256] = l;
    }
}

// ---------------- router -----------------------------------------------------------
__global__ void gate_topk_kernel(const float* __restrict__ h2, const float* __restrict__ gw,
                                 int* __restrict__ oidx, float* __restrict__ orw) {
    int t = blockIdx.x;
    int e = threadIdx.x >> 4, l = threadIdx.x & 15;
    const float* hr = h2 + (size_t)t * HDM;
    const float* wr = gw + (size_t)e * HDM;
    float p = 0.f;
    for (int k = l; k < HDM; k += 16) p += hr[k] * wr[k];
    #pragma unroll
    for (int o = 8; o; o >>= 1) p += __shfl_xor_sync(0xffffffffu, p, o);
    __shared__ float slog[NE];
    if (l == 0) slog[e] = p;
    __syncthreads();
    if (threadIdx.x == 0) {
        float pr[NE];
        float mx = -3.4e38f;
        for (int i = 0; i < NE; i++) { pr[i] = slog[i]; mx = fmaxf(mx, pr[i]); }
        float sum = 0.f;
        for (int i = 0; i < NE; i++) { pr[i] = __expf(pr[i] - mx); sum += pr[i]; }
        float inv = 1.f / sum;
        for (int i = 0; i < NE; i++) pr[i] *= inv;
        int sel[TOPK]; float sv[TOPK]; float wsum = 0.f;
        for (int k = 0; k < TOPK; k++) {
            int best = 0; float bv = -1.f;
            for (int i = 0; i < NE; i++)
                if (pr[i] > bv) { bv = pr[i]; best = i; }
            sel[k] = best; sv[k] = bv; wsum += bv; pr[best] = -2.f;
        }
        float winv = 1.f / wsum;
        for (int k = 0; k < TOPK; k++) { oidx[t * TOPK + k] = sel[k]; orw[t * TOPK + k] = sv[k] * winv; }
    }
}

// ---------------- deterministic routing sort ----------------------------------------
__global__ void route_kernel(const int* __restrict__ idx, int* __restrict__ counts,
                             int* __restrict__ offs, int* __restrict__ token_of,
                             int* __restrict__ slot_of) {
    int c = threadIdx.x;  // 32 threads
    int start = c * (NSLOT / 32);
    int cnt[NE];
    #pragma unroll
    for (int e = 0; e < NE; e++) cnt[e] = 0;
    for (int i = 0; i < NSLOT / 32; i++) cnt[idx[start + i]]++;
    __shared__ int scnt[32][NE];
    __shared__ int sbase[32][NE];
    for (int e = 0; e < NE; e++) scnt[c][e] = cnt[e];
    __syncthreads();
    if (c == 0) {
        int off = 0;
        for (int e = 0; e < NE; e++) {
            offs[e] = off;
            int run = off;
            for (int cc = 0; cc < 32; cc++) { sbase[cc][e] = run; run += scnt[cc][e]; }
            counts[e] = run - off;
            off = run;
        }
    }
    __syncthreads();
    int base[NE];
    #pragma unroll
    for (int e = 0; e < NE; e++) base[e] = sbase[c][e];
    for (int i = 0; i < NSLOT / 32; i++) {
        int entry = start + i;
        int e = idx[entry];
        int pos = base[e]++;
        token_of[pos] = entry >> 2;
        slot_of[entry] = pos;
    }
}

// ---------------- silu(g)*u, split output --------------------------------------------
__global__ void silu_mul_kernel(const float* __restrict__ gu, bf16* __restrict__ gh,
                                bf16* __restrict__ gl) {
    int s = blockIdx.x;
    const float* row = gu + (size_t)s * GUN;
    for (int i = threadIdx.x; i < ID; i += blockDim.x) {
        float x = row[i];
        float u = row[ID + i];
        float v = (x / (1.f + __expf(-x))) * u;
        bf16 h, l; splitf(v, h, l);
        gh[(size_t)s * ID + i] = h;
        gl[(size_t)s * ID + i] = l;
    }
}

// ---------------- final combine -------------------------------------------------------
__global__ void combine_kernel(const float* __restrict__ res, const float* __restrict__ ybuf,
                               const int* __restrict__ slot_of, const float* __restrict__ rw,
                               float* __restrict__ out) {
    int t = blockIdx.x;
    int s0 = slot_of[t*4+0], s1 = slot_of[t*4+1], s2 = slot_of[t*4+2], s3 = slot_of[t*4+3];
    float w0 = rw[t*4+0], w1 = rw[t*4+1], w2 = rw[t*4+2], w3 = rw[t*4+3];
    const float* y0 = ybuf + (size_t)s0 * HDM;
    const float* y1 = ybuf + (size_t)s1 * HDM;
    const float* y2 = ybuf + (size_t)s2 * HDM;
    const float* y3 = ybuf + (size_t)s3 * HDM;
    size_t base = (size_t)t * HDM;
    for (int i = threadIdx.x; i < HDM; i += blockDim.x)
        out[base + i] = res[base + i] + w0 * y0[i] + w1 * y1[i] + w2 * y2[i] + w3 * y3[i];
}

// ========================================================================================
extern "C" void kernel_launch(void* const* d_in, const int* in_sizes, int n_in,
                              void* d_out, int out_size) {
    const float* x    = (const float*)d_in[0];
    const float* pe   = (const float*)d_in[1];
    const float* mask = (const float*)d_in[2];
    const float* q_w  = (const float*)d_in[3];
    const float* k_w  = (const float*)d_in[4];
    const float* v_w  = (const float*)d_in[5];
    const float* o_w  = (const float*)d_in[6];
    const float* q_nw = (const float*)d_in[7];
    const float* k_nw = (const float*)d_in[8];
    const float* ln1  = (const float*)d_in[9];
    const float* ln2  = (const float*)d_in[10];
    const float* gw   = (const float*)d_in[11];
    const float* gpw  = (const float*)d_in[12];
    const float* upw  = (const float*)d_in[13];
    const float* dpw  = (const float*)d_in[14];
    float* out = (float*)d_out;

    #define SYM(T, p, s) T p; cudaGetSymbolAddress((void**)&p, s)
    SYM(bf16*, wqkv_h, g_wqkv_h); SYM(bf16*, wqkv_l, g_wqkv_l);
    SYM(bf16*, wo_h, g_wo_h);     SYM(bf16*, wo_l, g_wo_l);
    SYM(bf16*, wgu_h, g_wgu_h);   SYM(bf16*, wgu_l, g_wgu_l);
    SYM(bf16*, wd_h, g_wd_h);     SYM(bf16*, wd_l, g_wd_l);
    SYM(bf16*, xn_h, g_xn_h);     SYM(bf16*, xn_l, g_xn_l);
    SYM(float*, qkvlin, g_qkvlin);
    SYM(bf16*, qh_h, g_qh_h);     SYM(bf16*, qh_l, g_qh_l);
    SYM(bf16*, kh_h, g_kh_h);     SYM(bf16*, kh_l, g_kh_l);
    SYM(bf16*, vt_h, g_vt_h);     SYM(bf16*, vt_l, g_vt_l);
    SYM(float*, scores, g_scores);
    SYM(bf16*, p_h, g_p_h);       SYM(bf16*, p_l, g_p_l);
    SYM(bf16*, ao_h, g_ao_h);     SYM(bf16*, ao_l, g_ao_l);
    SYM(float*, res, g_res);
    SYM(float*, h2f, g_h2f);
    SYM(bf16*, h2_h, g_h2_h);     SYM(bf16*, h2_l, g_h2_l);
    SYM(float*, gu, g_gu);
    SYM(bf16*, gg_h, g_g_h);      SYM(bf16*, gg_l, g_g_l);
    SYM(float*, ybuf, g_ybuf);
    SYM(int*, tidx, g_tidx);      SYM(float*, trw, g_trw);
    SYM(int*, counts, g_counts);  SYM(int*, offs, g_offs);
    SYM(int*, token_of, g_token_of); SYM(int*, slot_of, g_slot_of);
    #undef SYM

    const float scale = 0.08838834764831845f;  // 1/sqrt(128)

    // ---- weight conversions (fp32 -> bf16 hi/lo) ----
    {
        size_t nq = (size_t)NH*HD*HDM, nk = (size_t)NKV*HD*HDM;
        split_kernel<<<(unsigned)((nq/4+255)/256), 256>>>(q_w, wqkv_h, wqkv_l, nq);
        split_kernel<<<(unsigned)((nk/4+255)/256), 256>>>(k_w, wqkv_h + nq, wqkv_l + nq, nk);
        split_kernel<<<(unsigned)((nk/4+255)/256), 256>>>(v_w, wqkv_h + nq + nk, wqkv_l + nq + nk, nk);
        size_t no = (size_t)HDM*NH*HD;
        split_kernel<<<(unsigned)((no/4+255)/256), 256>>>(o_w, wo_h, wo_l, no);
        size_t ngu = (size_t)NE*ID*HDM;
        split_gu_kernel<<<(unsigned)((ngu/4+255)/256), 256>>>(gpw, upw, wgu_h, wgu_l);
        size_t nd = (size_t)NE*HDM*ID;
        split_kernel<<<(unsigned)((nd/4+255)/256), 256>>>(dpw, wd_h, wd_l, nd);
    }

    // ---- attention ----
    rmsnorm_kernel<<<SQ, 256>>>(x, ln1, nullptr, xn_h, xn_l, HDM);
    // QKV fused: [2048 x 5120] = xn @ wqkv^T
    gemm_mma<0,0><<<dim3(QKVN/BN, SQ/BM, 1), 256>>>(
        xn_h, xn_l, HDM, 0, wqkv_h, wqkv_l, HDM, 0, 1,
        qkvlin, nullptr, nullptr, QKVN, 0, HDM, 0.f, nullptr, 0, nullptr, nullptr, nullptr);
    norm_rope_kernel<<<dim3(SQ, NH), HD>>>(qkvlin, 0, q_nw, pe, qh_h, qh_l);
    norm_rope_kernel<<<dim3(SQ, NKV), HD>>>(qkvlin, NH*HD, k_nw, pe, kh_h, kh_l);
    vtrans_kernel<<<(NKV*HD*SQ)/256, 256>>>(qkvlin, vt_h, vt_l);
    // scores = q @ k^T * scale + mask
    gemm_mma<1,0><<<dim3(SQ/BN, SQ/BM, NH), 256>>>(
        qh_h, qh_l, HD, (long)SQ*HD, kh_h, kh_l, HD, (long)SQ*HD, 8,
        scores, nullptr, nullptr, SQ, (long)SQ*SQ, HD, scale, mask, SQ, nullptr, nullptr, nullptr);
    softmax_kernel<<<NH*SQ, 256>>>(scores, p_h, p_l);
    // ao = P @ V  (output split bf16)
    gemm_mma<3,0><<<dim3(1, SQ/BM, NH), 256>>>(
        p_h, p_l, SQ, (long)SQ*SQ, vt_h, vt_l, SQ, (long)HD*SQ, 8,
        nullptr, ao_h, ao_l, NH*HD, HD, SQ, 0.f, nullptr, 0, nullptr, nullptr, nullptr);
    // O projection + residual
    gemm_mma<2,0><<<dim3(HDM/BN, SQ/BM, 1), 256>>>(
        ao_h, ao_l, NH*HD, 0, wo_h, wo_l, NH*HD, 0, 1,
        res, nullptr, nullptr, HDM, 0, NH*HD, 0.f, x, HDM, nullptr, nullptr, nullptr);

    // ---- MoE ----
    rmsnorm_kernel<<<SQ, 256>>>(res, ln2, h2f, h2_h, h2_l, HDM);
    gate_topk_kernel<<<SQ, 256>>>(h2f, gw, tidx, trw);
    route_kernel<<<1, 32>>>(tidx, counts, offs, token_of, slot_of);
    // gate+up fused: [slots x 1536]
    gemm_mma<0,1><<<dim3(GUN/BN, NSLOT/BM, NE), 256>>>(
        h2_h, h2_l, HDM, 0, wgu_h, wgu_l, HDM, (long)GUN*HDM, 1,
        gu, nullptr, nullptr, GUN, 0, HDM, 0.f, nullptr, 0, counts, offs, token_of);
    silu_mul_kernel<<<NSLOT, 256>>>(gu, gg_h, gg_l);
    // down: [slots x 2048]
    gemm_mma<0,2><<<dim3(HDM/BN, NSLOT/BM, NE), 256>>>(
        gg_h, gg_l, ID, 0, wd_h, wd_l, ID, (long)HDM*ID, 1,
        ybuf, nullptr, nullptr, HDM, 0, ID, 0.f, nullptr, 0, counts, offs, token_of);
    combine_kernel<<<SQ, 256>>>(res, ybuf, slot_of, trw, out);
}

// round 3
// speedup vs baseline: 2.4561x; 1.0930x over previous
#include <cuda_runtime.h>
#include <cuda_bf16.h>
#include <cstdint>

#define SQ    2048
#define HDM   2048
#define NH    32
#define NKV   4
#define HD    128
#define NE    16
#define ID    768
#define TOPK  4
#define NSLOT (SQ*TOPK)
#define QKVN  (NH*HD + 2*NKV*HD)   // 5120
#define GUN   (2*ID)               // 1536

typedef __nv_bfloat16 bf16;

// ---------------- device scratch -------------------------------------------
__device__ __align__(16) bf16 g_wqkv_h[(size_t)QKVN*HDM],  g_wqkv_l[(size_t)QKVN*HDM];
__device__ __align__(16) bf16 g_wo_h[(size_t)HDM*NH*HD],   g_wo_l[(size_t)HDM*NH*HD];
__device__ __align__(16) bf16 g_wgu_h[(size_t)NE*GUN*HDM], g_wgu_l[(size_t)NE*GUN*HDM];
__device__ __align__(16) bf16 g_wd_h[(size_t)NE*HDM*ID],   g_wd_l[(size_t)NE*HDM*ID];
__device__ __align__(16) bf16 g_xn_h[(size_t)SQ*HDM],      g_xn_l[(size_t)SQ*HDM];
__device__ __align__(16) float g_qkvlin[(size_t)SQ*QKVN];
__device__ __align__(16) bf16 g_qh_h[(size_t)NH*SQ*HD],    g_qh_l[(size_t)NH*SQ*HD];
__device__ __align__(16) bf16 g_kh_h[(size_t)NKV*SQ*HD],   g_kh_l[(size_t)NKV*SQ*HD];
__device__ __align__(16) bf16 g_vt_h[(size_t)NKV*HD*SQ],   g_vt_l[(size_t)NKV*HD*SQ];
__device__ __align__(16) float g_scores[(size_t)NH*SQ*SQ];
__device__ __align__(16) bf16 g_p_h[(size_t)NH*SQ*SQ],     g_p_l[(size_t)NH*SQ*SQ];
__device__ __align__(16) bf16 g_ao_h[(size_t)SQ*NH*HD],    g_ao_l[(size_t)SQ*NH*HD];
__device__ __align__(16) float g_res[SQ*HDM];
__device__ __align__(16) float g_h2f[SQ*HDM];
__device__ __align__(16) bf16 g_h2_h[(size_t)SQ*HDM],      g_h2_l[(size_t)SQ*HDM];
__device__ __align__(16) float g_gu[(size_t)NSLOT*GUN];
__device__ __align__(16) bf16 g_g_h[(size_t)NSLOT*ID],     g_g_l[(size_t)NSLOT*ID];
__device__ __align__(16) float g_ybuf[(size_t)NSLOT*HDM];
__device__ int   g_tidx[NSLOT];
__device__ float g_trw[NSLOT];
__device__ int   g_counts[NE];
__device__ int   g_offs[NE];
__device__ int   g_token_of[NSLOT];
__device__ int   g_slot_of[NSLOT];

// ---------------- helpers ----------------------------------------------------
__device__ __forceinline__ void splitf(float v, bf16& h, bf16& l) {
    h = __float2bfloat16(v);
    l = __float2bfloat16(v - __bfloat162float(h));
}

__device__ __forceinline__ void ldsm4(uint32_t r[4], uint32_t addr) {
    asm volatile("ldmatrix.sync.aligned.m8n8.x4.shared.b16 {%0,%1,%2,%3},[%4];"
        : "=r"(r[0]), "=r"(r[1]), "=r"(r[2]), "=r"(r[3]) : "r"(addr));
}

__device__ __forceinline__ void mma16816(float c[4], const uint32_t a[4], const uint32_t b[2]) {
    asm volatile("mma.sync.aligned.m16n8k16.row.col.f32.bf16.bf16.f32 "
        "{%0,%1,%2,%3},{%4,%5,%6,%7},{%8,%9},{%0,%1,%2,%3};"
        : "+f"(c[0]), "+f"(c[1]), "+f"(c[2]), "+f"(c[3])
        : "r"(a[0]), "r"(a[1]), "r"(a[2]), "r"(a[3]), "r"(b[0]), "r"(b[1]));
}

__device__ __forceinline__ void cp16(uint32_t dst, const void* src, int sz) {
    asm volatile("cp.async.cg.shared.global [%0],[%1],16,%2;\n" :: "r"(dst), "l"(src), "r"(sz));
}
__device__ __forceinline__ void cp_commit() { asm volatile("cp.async.commit_group;\n"); }
__device__ __forceinline__ void cp_wait1() { asm volatile("cp.async.wait_group 1;\n"); }

__device__ __forceinline__ float blockReduceSum(float v) {
    __shared__ float sh[8];
    int lane = threadIdx.x & 31, w = threadIdx.x >> 5;
    #pragma unroll
    for (int o = 16; o; o >>= 1) v += __shfl_xor_sync(0xffffffffu, v, o);
    if (lane == 0) sh[w] = v;
    __syncthreads();
    float r = (threadIdx.x < (blockDim.x >> 5)) ? sh[threadIdx.x] : 0.f;
    if (w == 0) {
        #pragma unroll
        for (int o = 4; o; o >>= 1) r += __shfl_xor_sync(0xffffffffu, r, o);
        if (lane == 0) sh[0] = r;
    }
    __syncthreads();
    r = sh[0];
    __syncthreads();
    return r;
}

__device__ __forceinline__ float blockReduceMax(float v) {
    __shared__ float sh[8];
    int lane = threadIdx.x & 31, w = threadIdx.x >> 5;
    #pragma unroll
    for (int o = 16; o; o >>= 1) v = fmaxf(v, __shfl_xor_sync(0xffffffffu, v, o));
    if (lane == 0) sh[w] = v;
    __syncthreads();
    float r = (threadIdx.x < (blockDim.x >> 5)) ? sh[threadIdx.x] : -3.4e38f;
    if (w == 0) {
        #pragma unroll
        for (int o = 4; o; o >>= 1) r = fmaxf(r, __shfl_xor_sync(0xffffffffu, r, o));
        if (lane == 0) sh[0] = r;
    }
    __syncthreads();
    r = sh[0];
    __syncthreads();
    return r;
}

// ---------------- weight split conversions ------------------------------------
__global__ void split_kernel(const float* __restrict__ in, bf16* __restrict__ hi,
                             bf16* __restrict__ lo, size_t n) {
    size_t i = ((size_t)blockIdx.x * blockDim.x + threadIdx.x) * 4;
    if (i >= n) return;
    float4 v = *(const float4*)(in + i);
    bf16 h0, l0, h1, l1, h2, l2, h3, l3;
    splitf(v.x, h0, l0); splitf(v.y, h1, l1); splitf(v.z, h2, l2); splitf(v.w, h3, l3);
    *(__nv_bfloat162*)(hi + i)     = __nv_bfloat162(h0, h1);
    *(__nv_bfloat162*)(hi + i + 2) = __nv_bfloat162(h2, h3);
    *(__nv_bfloat162*)(lo + i)     = __nv_bfloat162(l0, l1);
    *(__nv_bfloat162*)(lo + i + 2) = __nv_bfloat162(l2, l3);
}

__global__ void split_gu_kernel(const float* __restrict__ gp, const float* __restrict__ up,
                                bf16* __restrict__ hi, bf16* __restrict__ lo) {
    size_t i = ((size_t)blockIdx.x * blockDim.x + threadIdx.x) * 4;
    if (i >= (size_t)NE * ID * HDM) return;
    size_t e = i / ((size_t)ID * HDM);
    size_t rem = i - e * (size_t)ID * HDM;
    size_t dg = e * (size_t)GUN * HDM + rem;
    size_t du = dg + (size_t)ID * HDM;
    float4 vg = *(const float4*)(gp + i);
    float4 vu = *(const float4*)(up + i);
    bf16 h, l;
    splitf(vg.x, h, l); hi[dg] = h; lo[dg] = l;
    splitf(vg.y, h, l); hi[dg+1] = h; lo[dg+1] = l;
    splitf(vg.z, h, l); hi[dg+2] = h; lo[dg+2] = l;
    splitf(vg.w, h, l); hi[dg+3] = h; lo[dg+3] = l;
    splitf(vu.x, h, l); hi[du] = h; lo[du] = l;
    splitf(vu.y, h, l); hi[du+1] = h; lo[du+1] = l;
    splitf(vu.z, h, l); hi[du+2] = h; lo[du+2] = l;
    splitf(vu.w, h, l); hi[du+3] = h; lo[du+3] = l;
}

// ---------------- rms norm ------------------------------------------------------
__global__ void rmsnorm_kernel(const float* __restrict__ x, const float* __restrict__ w,
                               float* __restrict__ outf, bf16* __restrict__ oh,
                               bf16* __restrict__ ol, int ncols) {
    size_t base = (size_t)blockIdx.x * ncols;
    float ss = 0.f;
    for (int i = threadIdx.x; i < ncols; i += blockDim.x) { float v = x[base + i]; ss += v * v; }
    ss = blockReduceSum(ss);
    float r = rsqrtf(ss / ncols + 1e-6f);
    for (int i = threadIdx.x; i < ncols; i += blockDim.x) {
        float v = w[i] * x[base + i] * r;
        if (outf) outf[base + i] = v;
        if (oh) { bf16 h, l; splitf(v, h, l); oh[base + i] = h; ol[base + i] = l; }
    }
}

// ---------------- per-head rmsnorm + rope --------------------------------------
__global__ void norm_rope_kernel(const float* __restrict__ lin, int colbase,
                                 const float* __restrict__ nw, const float* __restrict__ pe,
                                 bf16* __restrict__ oh, bf16* __restrict__ ol) {
    int t = blockIdx.x, h = blockIdx.y, d = threadIdx.x;
    float v = lin[(size_t)t * QKVN + colbase + h * HD + d];
    float ss = v * v;
    #pragma unroll
    for (int o = 16; o; o >>= 1) ss += __shfl_xor_sync(0xffffffffu, ss, o);
    __shared__ float wsum[4];
    if ((d & 31) == 0) wsum[d >> 5] = ss;
    __syncthreads();
    float tot = wsum[0] + wsum[1] + wsum[2] + wsum[3];
    float xn = nw[d] * v * rsqrtf(tot * (1.f / HD) + 1e-6f);
    __shared__ float sh[HD];
    sh[d] = xn;
    __syncthreads();
    float c = pe[(size_t)t * HD + d];
    float s = pe[(size_t)SQ * HD + (size_t)t * HD + d];
    float rot = (d < HD / 2) ? -sh[d + HD / 2] : sh[d - HD / 2];
    float o = xn * c + rot * s;
    size_t idx = ((size_t)h * SQ + t) * HD + d;
    bf16 hh, ll; splitf(o, hh, ll);
    oh[idx] = hh; ol[idx] = ll;
}

// ---------------- V transpose + split -------------------------------------------
__global__ void vtrans_kernel(const float* __restrict__ qkvlin, bf16* __restrict__ vh,
                              bf16* __restrict__ vl) {
    int i = blockIdx.x * blockDim.x + threadIdx.x;
    int t = i & (SQ - 1);
    int d = (i >> 11) & (HD - 1);
    int kv = i >> 18;
    float v = qkvlin[(size_t)t * QKVN + (NH * HD + NKV * HD) + kv * HD + d];
    bf16 h, l; splitf(v, h, l);
    vh[i] = h; vl[i] = l;
}

// ---------------- bf16x3 tensor-core GEMM, cp.async double-buffered -------------
// MODE 0: dense. 1: ragged gathered rows. 2: ragged direct rows.
// EPI  0: fp32 store. 1: fp32 acc*scale+mask. 2: fp32 acc+residual. 3: bf16 hi/lo.
// causal 0: none. 1: skip blocks fully above diagonal (scores). 2: K-bound m0+BM (AV).
#define BM 128
#define BN 128
#define BK 32
#define BKP 40
#define TILE_HALF (BM * BKP)                 // elems per (matrix,half)
#define STAGE_ELEMS (4 * TILE_HALF)          // Ah,Al,Bh,Bl
#define SMEM_BYTES (2 * STAGE_ELEMS * 2)     // 2 stages, bf16

template<int EPI, int MODE>
__global__ void __launch_bounds__(256, 1) gemm_mma(
    const bf16* __restrict__ Ah, const bf16* __restrict__ Al, int lda, long sAz,
    const bf16* __restrict__ Bh, const bf16* __restrict__ Bl, int ldb, long sBz, int bdiv,
    float* __restrict__ Cf, bf16* __restrict__ Ch, bf16* __restrict__ Cl, int ldc, long sCz,
    int K, float scale, const float* __restrict__ epi, int lde,
    const int* __restrict__ counts, const int* __restrict__ offs,
    const int* __restrict__ token_of, int causal)
{
    int z = blockIdx.z;
    int m0 = blockIdx.y * BM, n0 = blockIdx.x * BN;
    if (causal == 1 && n0 >= m0 + BM) return;     // fully masked score block
    int Me = 0x7fffffff, off = 0;
    if (MODE != 0) { Me = counts[z]; if (m0 >= Me) return; off = offs[z]; }
    int Kloc = (causal == 2) ? (m0 + BM < K ? m0 + BM : K) : K;

    const bf16* Ahp = Ah; const bf16* Alp = Al;
    if (MODE == 0) { Ahp += (size_t)z * sAz; Alp += (size_t)z * sAz; }
    const bf16* Bhp = Bh + (size_t)(z / bdiv) * sBz;
    const bf16* Blp = Bl + (size_t)(z / bdiv) * sBz;

    extern __shared__ bf16 smem[];
    uint32_t sbase = (uint32_t)__cvta_generic_to_shared(smem);

    int tid = threadIdx.x;
    int lr = tid >> 2;
    int lc = (tid & 3) * 8;

    int rl0 = m0 + lr, rl1 = m0 + lr + 64;
    bool av0 = true, av1 = true;
    size_t ar0, ar1;
    if (MODE == 1) {
        av0 = rl0 < Me; av1 = rl1 < Me;
        ar0 = av0 ? (size_t)token_of[off + rl0] : 0;
        ar1 = av1 ? (size_t)token_of[off + rl1] : 0;
    } else if (MODE == 2) {
        av0 = rl0 < Me; av1 = rl1 < Me;
        ar0 = av0 ? (size_t)(off + rl0) : 0;
        ar1 = av1 ? (size_t)(off + rl1) : 0;
    } else { ar0 = rl0; ar1 = rl1; }
    size_t offA0 = ar0 * (size_t)lda + lc;
    size_t offA1 = ar1 * (size_t)lda + lc;
    size_t offB0 = (size_t)(n0 + lr) * ldb + lc;
    size_t offB1 = (size_t)(n0 + lr + 64) * ldb + lc;
    int sz0 = av0 ? 16 : 0, sz1 = av1 ? 16 : 0;

    // smem store addresses (per stage add stage*STAGE_ELEMS*2 bytes)
    uint32_t dA0 = sbase + (lr * BKP + lc) * 2;
    uint32_t dA1 = sbase + ((lr + 64) * BKP + lc) * 2;
    const uint32_t OFF_AL = TILE_HALF * 2, OFF_BH = 2 * TILE_HALF * 2, OFF_BL = 3 * TILE_HALF * 2;
    const uint32_t STAGE_B = STAGE_ELEMS * 2;

    const int warp = tid >> 5, lane = tid & 31;
    const int wm = (warp >> 1) * 32;
    const int wn = (warp & 1) * 64;
    const int ldr = lane & 15;
    const int ldc8 = (lane >> 4) * 8;

    float acc[2][8][4];
    #pragma unroll
    for (int i = 0; i < 2; i++)
        #pragma unroll
        for (int j = 0; j < 8; j++)
            #pragma unroll
            for (int q = 0; q < 4; q++) acc[i][j][q] = 0.f;

    // prologue: stage 0 loads tile k=0
    {
        cp16(dA0, Ahp + offA0, sz0);
        cp16(dA1, Ahp + offA1, sz1);
        cp16(dA0 + OFF_AL, Alp + offA0, sz0);
        cp16(dA1 + OFF_AL, Alp + offA1, sz1);
        cp16(dA0 + OFF_BH, Bhp + offB0, 16);
        cp16(dA1 + OFF_BH, Bhp + offB1, 16);
        cp16(dA0 + OFF_BL, Blp + offB0, 16);
        cp16(dA1 + OFF_BL, Blp + offB1, 16);
    }
    cp_commit();

    for (int k0 = 0; k0 < Kloc; k0 += BK) {
        int buf = (k0 >> 5) & 1;
        int kn = k0 + BK;
        if (kn < Kloc) {
            uint32_t nb = (buf ^ 1) * STAGE_B;
            cp16(dA0 + nb, Ahp + offA0 + kn, sz0);
            cp16(dA1 + nb, Ahp + offA1 + kn, sz1);
            cp16(dA0 + nb + OFF_AL, Alp + offA0 + kn, sz0);
            cp16(dA1 + nb + OFF_AL, Alp + offA1 + kn, sz1);
            cp16(dA0 + nb + OFF_BH, Bhp + offB0 + kn, 16);
            cp16(dA1 + nb + OFF_BH, Bhp + offB1 + kn, 16);
            cp16(dA0 + nb + OFF_BL, Blp + offB0 + kn, 16);
            cp16(dA1 + nb + OFF_BL, Blp + offB1 + kn, 16);
        }
        cp_commit();
        cp_wait1();
        __syncthreads();

        uint32_t bA = sbase + buf * STAGE_B;
        uint32_t sAh = bA, sAl = bA + OFF_AL, sBh = bA + OFF_BH, sBl = bA + OFF_BL;
        #pragma unroll
        for (int ks = 0; ks < 2; ks++) {
            int kk = ks * 16 + ldc8;
            uint32_t ah[2][4], al[2][4], bh[8][2], bl[8][2];
            #pragma unroll
            for (int mt = 0; mt < 2; mt++) {
                uint32_t adr = ((wm + mt * 16 + ldr) * BKP + kk) * 2;
                ldsm4(ah[mt], sAh + adr);
                ldsm4(al[mt], sAl + adr);
            }
            #pragma unroll
            for (int np = 0; np < 4; np++) {
                uint32_t adr = ((wn + np * 16 + ldr) * BKP + kk) * 2;
                uint32_t r[4];
                ldsm4(r, sBh + adr);
                bh[np*2][0] = r[0]; bh[np*2+1][0] = r[1]; bh[np*2][1] = r[2]; bh[np*2+1][1] = r[3];
                ldsm4(r, sBl + adr);
                bl[np*2][0] = r[0]; bl[np*2+1][0] = r[1]; bl[np*2][1] = r[2]; bl[np*2+1][1] = r[3];
            }
            #pragma unroll
            for (int mt = 0; mt < 2; mt++)
                #pragma unroll
                for (int nt = 0; nt < 8; nt++) {
                    mma16816(acc[mt][nt], ah[mt], bh[nt]);
                    mma16816(acc[mt][nt], ah[mt], bl[nt]);
                    mma16816(acc[mt][nt], al[mt], bh[nt]);
                }
        }
        __syncthreads();
    }

    int er = lane >> 2;
    int ec = (lane & 3) * 2;
    #pragma unroll
    for (int mt = 0; mt < 2; mt++) {
        #pragma unroll
        for (int h = 0; h < 2; h++) {
            int mloc = m0 + wm + mt * 16 + h * 8 + er;
            bool mvalid = (MODE == 0) || (mloc < Me);
            if (!mvalid) continue;
            size_t crow = (MODE == 0) ? (size_t)mloc : (size_t)(off + mloc);
            #pragma unroll
            for (int nt = 0; nt < 8; nt++) {
                int col = n0 + wn + nt * 8 + ec;
                float v0 = acc[mt][nt][h * 2 + 0];
                float v1 = acc[mt][nt][h * 2 + 1];
                if (EPI == 1) {
                    float2 mk = *(const float2*)(epi + (size_t)mloc * lde + col);
                    v0 = v0 * scale + mk.x;
                    v1 = v1 * scale + mk.y;
                } else if (EPI == 2) {
                    float2 rr = *(const float2*)(epi + (size_t)mloc * lde + col);
                    v0 += rr.x; v1 += rr.y;
                }
                if (EPI == 3) {
                    bf16 h0, l0, h1, l1;
                    splitf(v0, h0, l0); splitf(v1, h1, l1);
                    size_t ci = (size_t)z * sCz + crow * ldc + col;
                    *(__nv_bfloat162*)(Ch + ci) = __nv_bfloat162(h0, h1);
                    *(__nv_bfloat162*)(Cl + ci) = __nv_bfloat162(l0, l1);
                } else {
                    size_t ci = (size_t)z * sCz + crow * ldc + col;
                    *(float2*)(Cf + ci) = make_float2(v0, v1);
                }
            }
        }
    }
}

// ---------------- causal-aware softmax ------------------------------------------
__global__ void softmax_kernel(const float* __restrict__ data, bf16* __restrict__ ph,
                               bf16* __restrict__ pl) {
    int r = blockIdx.x & (SQ - 1);
    int L = ((r >> 7) + 1) << 7;          // row valid length, ceil to 128 block
    size_t base = (size_t)blockIdx.x * SQ;
    __shared__ float srow[SQ];
    float mx = -3.4e38f;
    for (int i = threadIdx.x; i < L; i += 256) {
        float v = data[base + i];
        srow[i] = v;
        mx = fmaxf(mx, v);
    }
    mx = blockReduceMax(mx);
    float sum = 0.f;
    for (int i = threadIdx.x; i < L; i += 256) {
        float e = __expf(srow[i] - mx);
        srow[i] = e;
        sum += e;
    }
    sum = blockReduceSum(sum);
    float inv = 1.f / sum;
    for (int i = threadIdx.x; i < L; i += 256) {
        float p = srow[i] * inv;
        bf16 h, l; splitf(p, h, l);
        ph[base + i] = h;
        pl[base + i] = l;
    }
}

// ---------------- router -----------------------------------------------------------
__global__ void gate_topk_kernel(const float* __restrict__ h2, const float* __restrict__ gw,
                                 int* __restrict__ oidx, float* __restrict__ orw) {
    int t = blockIdx.x;
    int e = threadIdx.x >> 4, l = threadIdx.x & 15;
    const float* hr = h2 + (size_t)t * HDM;
    const float* wr = gw + (size_t)e * HDM;
    float p = 0.f;
    for (int k = l; k < HDM; k += 16) p += hr[k] * wr[k];
    #pragma unroll
    for (int o = 8; o; o >>= 1) p += __shfl_xor_sync(0xffffffffu, p, o);
    __shared__ float slog[NE];
    if (l == 0) slog[e] = p;
    __syncthreads();
    if (threadIdx.x == 0) {
        float pr[NE];
        float mx = -3.4e38f;
        for (int i = 0; i < NE; i++) { pr[i] = slog[i]; mx = fmaxf(mx, pr[i]); }
        float sum = 0.f;
        for (int i = 0; i < NE; i++) { pr[i] = __expf(pr[i] - mx); sum += pr[i]; }
        float inv = 1.f / sum;
        for (int i = 0; i < NE; i++) pr[i] *= inv;
        int sel[TOPK]; float sv[TOPK]; float wsum = 0.f;
        for (int k = 0; k < TOPK; k++) {
            int best = 0; float bv = -1.f;
            for (int i = 0; i < NE; i++)
                if (pr[i] > bv) { bv = pr[i]; best = i; }
            sel[k] = best; sv[k] = bv; wsum += bv; pr[best] = -2.f;
        }
        float winv = 1.f / wsum;
        for (int k = 0; k < TOPK; k++) { oidx[t * TOPK + k] = sel[k]; orw[t * TOPK + k] = sv[k] * winv; }
    }
}

// ---------------- deterministic routing sort ----------------------------------------
__global__ void route_kernel(const int* __restrict__ idx, int* __restrict__ counts,
                             int* __restrict__ offs, int* __restrict__ token_of,
                             int* __restrict__ slot_of) {
    int c = threadIdx.x;
    int start = c * (NSLOT / 32);
    int cnt[NE];
    #pragma unroll
    for (int e = 0; e < NE; e++) cnt[e] = 0;
    for (int i = 0; i < NSLOT / 32; i++) cnt[idx[start + i]]++;
    __shared__ int scnt[32][NE];
    __shared__ int sbase[32][NE];
    for (int e = 0; e < NE; e++) scnt[c][e] = cnt[e];
    __syncthreads();
    if (c == 0) {
        int off = 0;
        for (int e = 0; e < NE; e++) {
            offs[e] = off;
            int run = off;
            for (int cc = 0; cc < 32; cc++) { sbase[cc][e] = run; run += scnt[cc][e]; }
            counts[e] = run - off;
            off = run;
        }
    }
    __syncthreads();
    int base[NE];
    #pragma unroll
    for (int e = 0; e < NE; e++) base[e] = sbase[c][e];
    for (int i = 0; i < NSLOT / 32; i++) {
        int entry = start + i;
        int e = idx[entry];
        int pos = base[e]++;
        token_of[pos] = entry >> 2;
        slot_of[entry] = pos;
    }
}

// ---------------- silu(g)*u --------------------------------------------------------
__global__ void silu_mul_kernel(const float* __restrict__ gu, bf16* __restrict__ gh,
                                bf16* __restrict__ gl) {
    int s = blockIdx.x;
    const float* row = gu + (size_t)s * GUN;
    for (int i = threadIdx.x; i < ID; i += blockDim.x) {
        float x = row[i];
        float u = row[ID + i];
        float v = (x / (1.f + __expf(-x))) * u;
        bf16 h, l; splitf(v, h, l);
        gh[(size_t)s * ID + i] = h;
        gl[(size_t)s * ID + i] = l;
    }
}

// ---------------- final combine ------------------------------------------------------
__global__ void combine_kernel(const float* __restrict__ res, const float* __restrict__ ybuf,
                               const int* __restrict__ slot_of, const float* __restrict__ rw,
                               float* __restrict__ out) {
    int t = blockIdx.x;
    int s0 = slot_of[t*4+0], s1 = slot_of[t*4+1], s2 = slot_of[t*4+2], s3 = slot_of[t*4+3];
    float w0 = rw[t*4+0], w1 = rw[t*4+1], w2 = rw[t*4+2], w3 = rw[t*4+3];
    const float* y0 = ybuf + (size_t)s0 * HDM;
    const float* y1 = ybuf + (size_t)s1 * HDM;
    const float* y2 = ybuf + (size_t)s2 * HDM;
    const float* y3 = ybuf + (size_t)s3 * HDM;
    size_t base = (size_t)t * HDM;
    for (int i = threadIdx.x; i < HDM; i += blockDim.x)
        out[base + i] = res[base + i] + w0 * y0[i] + w1 * y1[i] + w2 * y2[i] + w3 * y3[i];
}

// ========================================================================================
extern "C" void kernel_launch(void* const* d_in, const int* in_sizes, int n_in,
                              void* d_out, int out_size) {
    const float* x    = (const float*)d_in[0];
    const float* pe   = (const float*)d_in[1];
    const float* mask = (const float*)d_in[2];
    const float* q_w  = (const float*)d_in[3];
    const float* k_w  = (const float*)d_in[4];
    const float* v_w  = (const float*)d_in[5];
    const float* o_w  = (const float*)d_in[6];
    const float* q_nw = (const float*)d_in[7];
    const float* k_nw = (const float*)d_in[8];
    const float* ln1  = (const float*)d_in[9];
    const float* ln2  = (const float*)d_in[10];
    const float* gw   = (const float*)d_in[11];
    const float* gpw  = (const float*)d_in[12];
    const float* upw  = (const float*)d_in[13];
    const float* dpw  = (const float*)d_in[14];
    float* out = (float*)d_out;

    #define SYM(T, p, s) T p; cudaGetSymbolAddress((void**)&p, s)
    SYM(bf16*, wqkv_h, g_wqkv_h); SYM(bf16*, wqkv_l, g_wqkv_l);
    SYM(bf16*, wo_h, g_wo_h);     SYM(bf16*, wo_l, g_wo_l);
    SYM(bf16*, wgu_h, g_wgu_h);   SYM(bf16*, wgu_l, g_wgu_l);
    SYM(bf16*, wd_h, g_wd_h);     SYM(bf16*, wd_l, g_wd_l);
    SYM(bf16*, xn_h, g_xn_h);     SYM(bf16*, xn_l, g_xn_l);
    SYM(float*, qkvlin, g_qkvlin);
    SYM(bf16*, qh_h, g_qh_h);     SYM(bf16*, qh_l, g_qh_l);
    SYM(bf16*, kh_h, g_kh_h);     SYM(bf16*, kh_l, g_kh_l);
    SYM(bf16*, vt_h, g_vt_h);     SYM(bf16*, vt_l, g_vt_l);
    SYM(float*, scores, g_scores);
    SYM(bf16*, p_h, g_p_h);       SYM(bf16*, p_l, g_p_l);
    SYM(bf16*, ao_h, g_ao_h);     SYM(bf16*, ao_l, g_ao_l);
    SYM(float*, res, g_res);
    SYM(float*, h2f, g_h2f);
    SYM(bf16*, h2_h, g_h2_h);     SYM(bf16*, h2_l, g_h2_l);
    SYM(float*, gu, g_gu);
    SYM(bf16*, gg_h, g_g_h);      SYM(bf16*, gg_l, g_g_l);
    SYM(float*, ybuf, g_ybuf);
    SYM(int*, tidx, g_tidx);      SYM(float*, trw, g_trw);
    SYM(int*, counts, g_counts);  SYM(int*, offs, g_offs);
    SYM(int*, token_of, g_token_of); SYM(int*, slot_of, g_slot_of);
    #undef SYM

    // raise dynamic smem limits (idempotent; outside stream work)
    static bool attr_done = false;
    if (!attr_done) {
        cudaFuncSetAttribute(gemm_mma<0,0>, cudaFuncAttributeMaxDynamicSharedMemorySize, SMEM_BYTES);
        cudaFuncSetAttribute(gemm_mma<1,0>, cudaFuncAttributeMaxDynamicSharedMemorySize, SMEM_BYTES);
        cudaFuncSetAttribute(gemm_mma<2,0>, cudaFuncAttributeMaxDynamicSharedMemorySize, SMEM_BYTES);
        cudaFuncSetAttribute(gemm_mma<3,0>, cudaFuncAttributeMaxDynamicSharedMemorySize, SMEM_BYTES);
        cudaFuncSetAttribute(gemm_mma<0,1>, cudaFuncAttributeMaxDynamicSharedMemorySize, SMEM_BYTES);
        cudaFuncSetAttribute(gemm_mma<0,2>, cudaFuncAttributeMaxDynamicSharedMemorySize, SMEM_BYTES);
        attr_done = true;
    }

    const float scale = 0.08838834764831845f;

    // ---- weight conversions ----
    {
        size_t nq = (size_t)NH*HD*HDM, nk = (size_t)NKV*HD*HDM;
        split_kernel<<<(unsigned)((nq/4+255)/256), 256>>>(q_w, wqkv_h, wqkv_l, nq);
        split_kernel<<<(unsigned)((nk/4+255)/256), 256>>>(k_w, wqkv_h + nq, wqkv_l + nq, nk);
        split_kernel<<<(unsigned)((nk/4+255)/256), 256>>>(v_w, wqkv_h + nq + nk, wqkv_l + nq + nk, nk);
        size_t no = (size_t)HDM*NH*HD;
        split_kernel<<<(unsigned)((no/4+255)/256), 256>>>(o_w, wo_h, wo_l, no);
        size_t ngu = (size_t)NE*ID*HDM;
        split_gu_kernel<<<(unsigned)((ngu/4+255)/256), 256>>>(gpw, upw, wgu_h, wgu_l);
        size_t nd = (size_t)NE*HDM*ID;
        split_kernel<<<(unsigned)((nd/4+255)/256), 256>>>(dpw, wd_h, wd_l, nd);
    }

    // ---- attention ----
    rmsnorm_kernel<<<SQ, 256>>>(x, ln1, nullptr, xn_h, xn_l, HDM);
    gemm_mma<0,0><<<dim3(QKVN/BN, SQ/BM, 1), 256, SMEM_BYTES>>>(
        xn_h, xn_l, HDM, 0, wqkv_h, wqkv_l, HDM, 0, 1,
        qkvlin, nullptr, nullptr, QKVN, 0, HDM, 0.f, nullptr, 0, nullptr, nullptr, nullptr, 0);
    norm_rope_kernel<<<dim3(SQ, NH), HD>>>(qkvlin, 0, q_nw, pe, qh_h, qh_l);
    norm_rope_kernel<<<dim3(SQ, NKV), HD>>>(qkvlin, NH*HD, k_nw, pe, kh_h, kh_l);
    vtrans_kernel<<<(NKV*HD*SQ)/256, 256>>>(qkvlin, vt_h, vt_l);
    // scores (causal block skip)
    gemm_mma<1,0><<<dim3(SQ/BN, SQ/BM, NH), 256, SMEM_BYTES>>>(
        qh_h, qh_l, HD, (long)SQ*HD, kh_h, kh_l, HD, (long)SQ*HD, 8,
        scores, nullptr, nullptr, SQ, (long)SQ*SQ, HD, scale, mask, SQ, nullptr, nullptr, nullptr, 1);
    softmax_kernel<<<NH*SQ, 256>>>(scores, p_h, p_l);
    // ao = P @ V (causal K bound)
    gemm_mma<3,0><<<dim3(1, SQ/BM, NH), 256, SMEM_BYTES>>>(
        p_h, p_l, SQ, (long)SQ*SQ, vt_h, vt_l, SQ, (long)HD*SQ, 8,
        nullptr, ao_h, ao_l, NH*HD, HD, SQ, 0.f, nullptr, 0, nullptr, nullptr, nullptr, 2);
    gemm_mma<2,0><<<dim3(HDM/BN, SQ/BM, 1), 256, SMEM_BYTES>>>(
        ao_h, ao_l, NH*HD, 0, wo_h, wo_l, NH*HD, 0, 1,
        res, nullptr, nullptr, HDM, 0, NH*HD, 0.f, x, HDM, nullptr, nullptr, nullptr, 0);

    // ---- MoE ----
    rmsnorm_kernel<<<SQ, 256>>>(res, ln2, h2f, h2_h, h2_l, HDM);
    gate_topk_kernel<<<SQ, 256>>>(h2f, gw, tidx, trw);
    route_kernel<<<1, 32>>>(tidx, counts, offs, token_of, slot_of);
    gemm_mma<0,1><<<dim3(GUN/BN, NSLOT/BM, NE), 256, SMEM_BYTES>>>(
        h2_h, h2_l, HDM, 0, wgu_h, wgu_l, HDM, (long)GUN*HDM, 1,
        gu, nullptr, nullptr, GUN, 0, HDM, 0.f, nullptr, 0, counts, offs, token_of, 0);
    silu_mul_kernel<<<NSLOT, 256>>>(gu, gg_h, gg_l);
    gemm_mma<0,2><<<dim3(HDM/BN, NSLOT/BM, NE), 256, SMEM_BYTES>>>(
        gg_h, gg_l, ID, 0, wd_h, wd_l, ID, (long)HDM*ID, 1,
        ybuf, nullptr, nullptr, HDM, 0, ID, 0.f, nullptr, 0, counts, offs, token_of, 0);
    combine_kernel<<<SQ, 256>>>(res, ybuf, slot_of, trw, out);
}

// round 5
// speedup vs baseline: 2.8950x; 1.1787x over previous
#include <cuda_runtime.h>
#include <cuda_bf16.h>
#include <cstdint>

#define SQ    2048
#define HDM   2048
#define NH    32
#define NKV   4
#define HD    128
#define NE    16
#define ID    768
#define TOPK  4
#define NSLOT (SQ*TOPK)
#define QKVN  (NH*HD + 2*NKV*HD)   // 5120
#define GUN   (2*ID)               // 1536

typedef __nv_bfloat16 bf16;

// ---------------- device scratch -------------------------------------------
__device__ __align__(16) bf16 g_wqkv_h[(size_t)QKVN*HDM],  g_wqkv_l[(size_t)QKVN*HDM];
__device__ __align__(16) bf16 g_wo_h[(size_t)HDM*NH*HD],   g_wo_l[(size_t)HDM*NH*HD];
__device__ __align__(16) bf16 g_wgu_h[(size_t)NE*GUN*HDM], g_wgu_l[(size_t)NE*GUN*HDM];
__device__ __align__(16) bf16 g_wd_h[(size_t)NE*HDM*ID],   g_wd_l[(size_t)NE*HDM*ID];
__device__ __align__(16) bf16 g_xn_h[(size_t)SQ*HDM],      g_xn_l[(size_t)SQ*HDM];
__device__ __align__(16) float g_qkvlin[(size_t)SQ*QKVN];
__device__ __align__(16) bf16 g_qh_h[(size_t)NH*SQ*HD],    g_qh_l[(size_t)NH*SQ*HD];
__device__ __align__(16) bf16 g_kh_h[(size_t)NKV*SQ*HD],   g_kh_l[(size_t)NKV*SQ*HD];
__device__ __align__(16) bf16 g_vt_h[(size_t)NKV*HD*SQ],   g_vt_l[(size_t)NKV*HD*SQ];
__device__ __align__(16) bf16 g_ao_h[(size_t)SQ*NH*HD],    g_ao_l[(size_t)SQ*NH*HD];
__device__ __align__(16) float g_res[SQ*HDM];
__device__ __align__(16) float g_h2f[SQ*HDM];
__device__ __align__(16) bf16 g_h2_h[(size_t)SQ*HDM],      g_h2_l[(size_t)SQ*HDM];
__device__ __align__(16) float g_gu[(size_t)NSLOT*GUN];
__device__ __align__(16) bf16 g_g_h[(size_t)NSLOT*ID],     g_g_l[(size_t)NSLOT*ID];
__device__ __align__(16) float g_ybuf[(size_t)NSLOT*HDM];
__device__ int   g_tidx[NSLOT];
__device__ float g_trw[NSLOT];
__device__ int   g_counts[NE];
__device__ int   g_offs[NE];
__device__ int   g_token_of[NSLOT];
__device__ int   g_slot_of[NSLOT];

// ---------------- helpers ----------------------------------------------------
__device__ __forceinline__ void splitf(float v, bf16& h, bf16& l) {
    h = __float2bfloat16(v);
    l = __float2bfloat16(v - __bfloat162float(h));
}
__device__ __forceinline__ uint32_t packbf2(bf16 a, bf16 b) {
    __nv_bfloat162 t(a, b);
    return *(uint32_t*)&t;
}
__device__ __forceinline__ void ldsm4(uint32_t r[4], uint32_t addr) {
    asm volatile("ldmatrix.sync.aligned.m8n8.x4.shared.b16 {%0,%1,%2,%3},[%4];"
        : "=r"(r[0]), "=r"(r[1]), "=r"(r[2]), "=r"(r[3]) : "r"(addr));
}
__device__ __forceinline__ void mma16816(float c[4], const uint32_t a[4], const uint32_t b[2]) {
    asm volatile("mma.sync.aligned.m16n8k16.row.col.f32.bf16.bf16.f32 "
        "{%0,%1,%2,%3},{%4,%5,%6,%7},{%8,%9},{%0,%1,%2,%3};"
        : "+f"(c[0]), "+f"(c[1]), "+f"(c[2]), "+f"(c[3])
        : "r"(a[0]), "r"(a[1]), "r"(a[2]), "r"(a[3]), "r"(b[0]), "r"(b[1]));
}
__device__ __forceinline__ void cp16(uint32_t dst, const void* src, int sz) {
    asm volatile("cp.async.cg.shared.global [%0],[%1],16,%2;\n" :: "r"(dst), "l"(src), "r"(sz));
}
__device__ __forceinline__ void cp_commit() { asm volatile("cp.async.commit_group;\n"); }
__device__ __forceinline__ void cp_wait1() { asm volatile("cp.async.wait_group 1;\n"); }
__device__ __forceinline__ void cp_wait2() { asm volatile("cp.async.wait_group 2;\n"); }

__device__ __forceinline__ float blockReduceSum(float v) {
    __shared__ float sh[8];
    int lane = threadIdx.x & 31, w = threadIdx.x >> 5;
    #pragma unroll
    for (int o = 16; o; o >>= 1) v += __shfl_xor_sync(0xffffffffu, v, o);
    if (lane == 0) sh[w] = v;
    __syncthreads();
    float r = (threadIdx.x < (blockDim.x >> 5)) ? sh[threadIdx.x] : 0.f;
    if (w == 0) {
        #pragma unroll
        for (int o = 4; o; o >>= 1) r += __shfl_xor_sync(0xffffffffu, r, o);
        if (lane == 0) sh[0] = r;
    }
    __syncthreads();
    r = sh[0];
    __syncthreads();
    return r;
}

// ---------------- weight split conversions ------------------------------------
__global__ void split_kernel(const float* __restrict__ in, bf16* __restrict__ hi,
                             bf16* __restrict__ lo, size_t n) {
    size_t i = ((size_t)blockIdx.x * blockDim.x + threadIdx.x) * 4;
    if (i >= n) return;
    float4 v = *(const float4*)(in + i);
    bf16 h0, l0, h1, l1, h2, l2, h3, l3;
    splitf(v.x, h0, l0); splitf(v.y, h1, l1); splitf(v.z, h2, l2); splitf(v.w, h3, l3);
    *(__nv_bfloat162*)(hi + i)     = __nv_bfloat162(h0, h1);
    *(__nv_bfloat162*)(hi + i + 2) = __nv_bfloat162(h2, h3);
    *(__nv_bfloat162*)(lo + i)     = __nv_bfloat162(l0, l1);
    *(__nv_bfloat162*)(lo + i + 2) = __nv_bfloat162(l2, l3);
}

__global__ void split_gu_kernel(const float* __restrict__ gp, const float* __restrict__ up,
                                bf16* __restrict__ hi, bf16* __restrict__ lo) {
    size_t i = ((size_t)blockIdx.x * blockDim.x + threadIdx.x) * 4;
    if (i >= (size_t)NE * ID * HDM) return;
    size_t e = i / ((size_t)ID * HDM);
    size_t rem = i - e * (size_t)ID * HDM;
    size_t dg = e * (size_t)GUN * HDM + rem;
    size_t du = dg + (size_t)ID * HDM;
    float4 vg = *(const float4*)(gp + i);
    float4 vu = *(const float4*)(up + i);
    bf16 h, l;
    splitf(vg.x, h, l); hi[dg] = h; lo[dg] = l;
    splitf(vg.y, h, l); hi[dg+1] = h; lo[dg+1] = l;
    splitf(vg.z, h, l); hi[dg+2] = h; lo[dg+2] = l;
    splitf(vg.w, h, l); hi[dg+3] = h; lo[dg+3] = l;
    splitf(vu.x, h, l); hi[du] = h; lo[du] = l;
    splitf(vu.y, h, l); hi[du+1] = h; lo[du+1] = l;
    splitf(vu.z, h, l); hi[du+2] = h; lo[du+2] = l;
    splitf(vu.w, h, l); hi[du+3] = h; lo[du+3] = l;
}

// ---------------- rms norm ------------------------------------------------------
__global__ void rmsnorm_kernel(const float* __restrict__ x, const float* __restrict__ w,
                               float* __restrict__ outf, bf16* __restrict__ oh,
                               bf16* __restrict__ ol, int ncols) {
    size_t base = (size_t)blockIdx.x * ncols;
    float ss = 0.f;
    for (int i = threadIdx.x; i < ncols; i += blockDim.x) { float v = x[base + i]; ss += v * v; }
    ss = blockReduceSum(ss);
    float r = rsqrtf(ss / ncols + 1e-6f);
    for (int i = threadIdx.x; i < ncols; i += blockDim.x) {
        float v = w[i] * x[base + i] * r;
        if (outf) outf[base + i] = v;
        if (oh) { bf16 h, l; splitf(v, h, l); oh[base + i] = h; ol[base + i] = l; }
    }
}

// ---------------- per-head rmsnorm + rope --------------------------------------
__global__ void norm_rope_kernel(const float* __restrict__ lin, int colbase,
                                 const float* __restrict__ nw, const float* __restrict__ pe,
                                 bf16* __restrict__ oh, bf16* __restrict__ ol) {
    int t = blockIdx.x, h = blockIdx.y, d = threadIdx.x;
    float v = lin[(size_t)t * QKVN + colbase + h * HD + d];
    float ss = v * v;
    #pragma unroll
    for (int o = 16; o; o >>= 1) ss += __shfl_xor_sync(0xffffffffu, ss, o);
    __shared__ float wsum[4];
    if ((d & 31) == 0) wsum[d >> 5] = ss;
    __syncthreads();
    float tot = wsum[0] + wsum[1] + wsum[2] + wsum[3];
    float xn = nw[d] * v * rsqrtf(tot * (1.f / HD) + 1e-6f);
    __shared__ float sh[HD];
    sh[d] = xn;
    __syncthreads();
    float c = pe[(size_t)t * HD + d];
    float s = pe[(size_t)SQ * HD + (size_t)t * HD + d];
    float rot = (d < HD / 2) ? -sh[d + HD / 2] : sh[d - HD / 2];
    float o = xn * c + rot * s;
    size_t idx = ((size_t)h * SQ + t) * HD + d;
    bf16 hh, ll; splitf(o, hh, ll);
    oh[idx] = hh; ol[idx] = ll;
}

// ---------------- V transpose + split -------------------------------------------
__global__ void vtrans_kernel(const float* __restrict__ qkvlin, bf16* __restrict__ vh,
                              bf16* __restrict__ vl) {
    int i = blockIdx.x * blockDim.x + threadIdx.x;
    int t = i & (SQ - 1);
    int d = (i >> 11) & (HD - 1);
    int kv = i >> 18;
    float v = qkvlin[(size_t)t * QKVN + (NH * HD + NKV * HD) + kv * HD + d];
    bf16 h, l; splitf(v, h, l);
    vh[i] = h; vl[i] = l;
}

// =================================================================================
// bf16x3 mma.sync GEMM, 4-stage cp.async pipeline, 1 sync per k-tile.
// MODE 0 dense / 1 gather rows / 2 direct ragged rows
// EPI 0 fp32 store / 2 fp32 + residual
// =================================================================================
#define BM 128
#define BN 128
#define BK 32
#define BKP 40
#define TILE_HALF (BM * BKP)
#define STAGE_ELEMS (4 * TILE_HALF)
#define NSTAGE 4
#define STAGE_B (STAGE_ELEMS * 2)
#define SMEM_BYTES (NSTAGE * STAGE_B)     // 163840

template<int EPI, int MODE>
__global__ void __launch_bounds__(256, 1) gemm_mma(
    const bf16* __restrict__ Ah, const bf16* __restrict__ Al, int lda, long sAz,
    const bf16* __restrict__ Bh, const bf16* __restrict__ Bl, int ldb, long sBz,
    float* __restrict__ Cf, int ldc, long sCz,
    int K, const float* __restrict__ epi, int lde,
    const int* __restrict__ counts, const int* __restrict__ offs,
    const int* __restrict__ token_of)
{
    int z = blockIdx.z;
    int m0 = blockIdx.y * BM, n0 = blockIdx.x * BN;
    int Me = 0x7fffffff, off = 0;
    if (MODE != 0) { Me = counts[z]; if (m0 >= Me) return; off = offs[z]; }
    int nkt = K / BK;

    const bf16* Ahp = Ah; const bf16* Alp = Al;
    if (MODE == 0) { Ahp += (size_t)z * sAz; Alp += (size_t)z * sAz; }
    const bf16* Bhp = Bh + (size_t)z * sBz;
    const bf16* Blp = Bl + (size_t)z * sBz;

    extern __shared__ bf16 smem[];
    uint32_t sbase = (uint32_t)__cvta_generic_to_shared(smem);

    int tid = threadIdx.x;
    int lr = tid >> 2;
    int lc = (tid & 3) * 8;

    int rl0 = m0 + lr, rl1 = m0 + lr + 64;
    bool av0 = true, av1 = true;
    size_t ar0, ar1;
    if (MODE == 1) {
        av0 = rl0 < Me; av1 = rl1 < Me;
        ar0 = av0 ? (size_t)token_of[off + rl0] : 0;
        ar1 = av1 ? (size_t)token_of[off + rl1] : 0;
    } else if (MODE == 2) {
        av0 = rl0 < Me; av1 = rl1 < Me;
        ar0 = av0 ? (size_t)(off + rl0) : 0;
        ar1 = av1 ? (size_t)(off + rl1) : 0;
    } else { ar0 = rl0; ar1 = rl1; }
    size_t offA0 = ar0 * (size_t)lda + lc;
    size_t offA1 = ar1 * (size_t)lda + lc;
    size_t offB0 = (size_t)(n0 + lr) * ldb + lc;
    size_t offB1 = (size_t)(n0 + lr + 64) * ldb + lc;
    int sz0 = av0 ? 16 : 0, sz1 = av1 ? 16 : 0;

    uint32_t dA0 = sbase + (lr * BKP + lc) * 2;
    uint32_t dA1 = sbase + ((lr + 64) * BKP + lc) * 2;
    const uint32_t OFF_AL = TILE_HALF * 2, OFF_BH = 2 * TILE_HALF * 2, OFF_BL = 3 * TILE_HALF * 2;

    const int warp = tid >> 5, lane = tid & 31;
    const int wm = (warp >> 1) * 32;
    const int wn = (warp & 1) * 64;
    const int ldr = lane & 15;
    const int ldc8 = (lane >> 4) * 8;

    float acc[2][8][4];
    #pragma unroll
    for (int i = 0; i < 2; i++)
        #pragma unroll
        for (int j = 0; j < 8; j++)
            #pragma unroll
            for (int q = 0; q < 4; q++) acc[i][j][q] = 0.f;

    #define LOAD_STAGE(kt) do {                                        \
        uint32_t nb = (uint32_t)((kt) & 3) * STAGE_B;                   \
        int k0_ = (kt) * BK;                                            \
        cp16(dA0 + nb, Ahp + offA0 + k0_, sz0);                         \
        cp16(dA1 + nb, Ahp + offA1 + k0_, sz1);                         \
        cp16(dA0 + nb + OFF_AL, Alp + offA0 + k0_, sz0);                \
        cp16(dA1 + nb + OFF_AL, Alp + offA1 + k0_, sz1);                \
        cp16(dA0 + nb + OFF_BH, Bhp + offB0 + k0_, 16);                 \
        cp16(dA1 + nb + OFF_BH, Bhp + offB1 + k0_, 16);                 \
        cp16(dA0 + nb + OFF_BL, Blp + offB0 + k0_, 16);                 \
        cp16(dA1 + nb + OFF_BL, Blp + offB1 + k0_, 16);                 \
    } while (0)

    LOAD_STAGE(0);
    cp_commit();
    if (nkt > 1) LOAD_STAGE(1);
    cp_commit();

    for (int kt = 0; kt < nkt; kt++) {
        if (kt + 2 < nkt) LOAD_STAGE(kt + 2);
        cp_commit();
        cp_wait2();
        __syncthreads();

        uint32_t bA = sbase + (uint32_t)(kt & 3) * STAGE_B;
        uint32_t sAh = bA, sAl = bA + OFF_AL, sBh = bA + OFF_BH, sBl = bA + OFF_BL;
        #pragma unroll
        for (int ks = 0; ks < 2; ks++) {
            int kk = ks * 16 + ldc8;
            uint32_t ah[2][4], al[2][4], bh[8][2], bl[8][2];
            #pragma unroll
            for (int mt = 0; mt < 2; mt++) {
                uint32_t adr = ((wm + mt * 16 + ldr) * BKP + kk) * 2;
                ldsm4(ah[mt], sAh + adr);
                ldsm4(al[mt], sAl + adr);
            }
            #pragma unroll
            for (int np = 0; np < 4; np++) {
                uint32_t adr = ((wn + np * 16 + ldr) * BKP + kk) * 2;
                uint32_t r[4];
                ldsm4(r, sBh + adr);
                bh[np*2][0] = r[0]; bh[np*2+1][0] = r[1]; bh[np*2][1] = r[2]; bh[np*2+1][1] = r[3];
                ldsm4(r, sBl + adr);
                bl[np*2][0] = r[0]; bl[np*2+1][0] = r[1]; bl[np*2][1] = r[2]; bl[np*2+1][1] = r[3];
            }
            #pragma unroll
            for (int mt = 0; mt < 2; mt++)
                #pragma unroll
                for (int nt = 0; nt < 8; nt++) {
                    mma16816(acc[mt][nt], ah[mt], bh[nt]);
                    mma16816(acc[mt][nt], ah[mt], bl[nt]);
                    mma16816(acc[mt][nt], al[mt], bh[nt]);
                }
        }
    }
    #undef LOAD_STAGE

    int er = lane >> 2;
    int ec = (lane & 3) * 2;
    #pragma unroll
    for (int mt = 0; mt < 2; mt++) {
        #pragma unroll
        for (int h = 0; h < 2; h++) {
            int mloc = m0 + wm + mt * 16 + h * 8 + er;
            bool mvalid = (MODE == 0) || (mloc < Me);
            if (!mvalid) continue;
            size_t crow = (MODE == 0) ? (size_t)mloc : (size_t)(off + mloc);
            #pragma unroll
            for (int nt = 0; nt < 8; nt++) {
                int col = n0 + wn + nt * 8 + ec;
                float v0 = acc[mt][nt][h * 2 + 0];
                float v1 = acc[mt][nt][h * 2 + 1];
                if (EPI == 2) {
                    float2 rr = *(const float2*)(epi + (size_t)mloc * lde + col);
                    v0 += rr.x; v1 += rr.y;
                }
                size_t ci = (size_t)z * sCz + crow * ldc + col;
                *(float2*)(Cf + ci) = make_float2(v0, v1);
            }
        }
    }
}

// =================================================================================
// Fused flash attention: per CTA one head h, 128 q rows. bf16x3 QK and PV,
// online softmax in fp32. KV streamed in 64-row blocks, cp.async double buffer.
// Each warp owns 16 q rows end-to-end (no cross-warp reduction).
// =================================================================================
#define FQH 0
#define FQL 17408
#define FKOFF 34816     /* + s*17408 ; KH at 0, KL at +8704 */
#define FVOFF 69632     /* + s*18432 ; VH at 0, VL at +9216 */
#define FSMEM (106496 * 2)   /* 212992 B */

__global__ void __launch_bounds__(256, 1) flash_kernel(
    const bf16* __restrict__ qh_h, const bf16* __restrict__ qh_l,
    const bf16* __restrict__ kh_h, const bf16* __restrict__ kh_l,
    const bf16* __restrict__ vt_h, const bf16* __restrict__ vt_l,
    bf16* __restrict__ ao_h, bf16* __restrict__ ao_l, float scale)
{
    int m0 = blockIdx.x * 128;
    int h = blockIdx.y;
    int kvh = h >> 3;

    extern __shared__ bf16 fsm[];
    uint32_t sb = (uint32_t)__cvta_generic_to_shared(fsm);

    int tid = threadIdx.x, wid = tid >> 5, lane = tid & 31;
    const int ldr = lane & 15, ldc8 = (lane >> 4) * 8;

    // ---- load Q block (hi+lo), group 0 ----
    {
        const bf16* qs_h = qh_h + ((size_t)h * SQ + m0) * HD;
        const bf16* qs_l = qh_l + ((size_t)h * SQ + m0) * HD;
        for (int c = tid; c < 2048; c += 256) {
            int r = c >> 4, col = (c & 15) * 8;
            size_t go = (size_t)r * HD + col;
            cp16(sb + (uint32_t)(FQH + r * 136 + col) * 2, qs_h + go, 16);
            cp16(sb + (uint32_t)(FQL + r * 136 + col) * 2, qs_l + go, 16);
        }
    }
    cp_commit();

    int nj = (m0 + 128) >> 6;

    #define LOAD_KV(jj, stg) do {                                                     \
        for (int c = tid; c < 1024; c += 256) {                                        \
            int kr = c >> 4, kc = (c & 15) * 8;                                        \
            size_t kgo = ((size_t)kvh * SQ + (jj) * 64 + kr) * HD + kc;                \
            uint32_t kd = sb + (uint32_t)(FKOFF + (stg) * 17408 + kr * 136 + kc) * 2;  \
            cp16(kd, kh_h + kgo, 16);                                                  \
            cp16(kd + 8704 * 2, kh_l + kgo, 16);                                       \
            int vr = c >> 3, vc = (c & 7) * 8;                                         \
            size_t vgo = ((size_t)kvh * HD + vr) * SQ + (jj) * 64 + vc;                \
            uint32_t vd = sb + (uint32_t)(FVOFF + (stg) * 18432 + vr * 72 + vc) * 2;   \
            cp16(vd, vt_h + vgo, 16);                                                  \
            cp16(vd + 9216 * 2, vt_l + vgo, 16);                                       \
        }                                                                               \
    } while (0)

    LOAD_KV(0, 0);
    cp_commit();

    int rbase = wid * 16;
    float m_r0 = -1e30f, m_r1 = -1e30f, l_r0 = 0.f, l_r1 = 0.f;
    float o[16][4];
    #pragma unroll
    for (int i = 0; i < 16; i++)
        #pragma unroll
        for (int q = 0; q < 4; q++) o[i][q] = 0.f;

    int grow0 = m0 + rbase + (lane >> 2);
    int ar = rbase + ldr;

    for (int j = 0; j < nj; j++) {
        if (j + 1 < nj) LOAD_KV(j + 1, (j + 1) & 1);
        cp_commit();
        cp_wait1();
        __syncthreads();

        bool skip = (j * 64 > m0 + rbase + 15);
        if (!skip) {
            int st = j & 1;
            uint32_t kst = (uint32_t)(FKOFF + st * 17408);
            uint32_t vst = (uint32_t)(FVOFF + st * 18432);

            // ---- S = Q K^T (bf16x3) ----
            float s[8][4];
            #pragma unroll
            for (int nt = 0; nt < 8; nt++)
                #pragma unroll
                for (int q = 0; q < 4; q++) s[nt][q] = 0.f;

            #pragma unroll
            for (int kt = 0; kt < 8; kt++) {
                int kk = kt * 16 + ldc8;
                uint32_t aqh[4], aql[4];
                ldsm4(aqh, sb + (uint32_t)(FQH + ar * 136 + kk) * 2);
                ldsm4(aql, sb + (uint32_t)(FQL + ar * 136 + kk) * 2);
                #pragma unroll
                for (int np = 0; np < 4; np++) {
                    uint32_t kadr = sb + (kst + (np * 16 + ldr) * 136 + kk) * 2;
                    uint32_t rh[4], rl[4];
                    ldsm4(rh, kadr);
                    ldsm4(rl, kadr + 8704 * 2);
                    uint32_t b0h[2] = {rh[0], rh[2]}, b1h[2] = {rh[1], rh[3]};
                    uint32_t b0l[2] = {rl[0], rl[2]}, b1l[2] = {rl[1], rl[3]};
                    mma16816(s[np*2],   aqh, b0h);
                    mma16816(s[np*2],   aqh, b0l);
                    mma16816(s[np*2],   aql, b0h);
                    mma16816(s[np*2+1], aqh, b1h);
                    mma16816(s[np*2+1], aqh, b1l);
                    mma16816(s[np*2+1], aql, b1h);
                }
            }

            // ---- scale + causal mask + online softmax ----
            float mx0 = -1e30f, mx1 = -1e30f;
            #pragma unroll
            for (int nt = 0; nt < 8; nt++) {
                int gc = j * 64 + nt * 8 + (lane & 3) * 2;
                float v0 = s[nt][0] * scale; if (gc     > grow0)     v0 = -1e30f;
                float v1 = s[nt][1] * scale; if (gc + 1 > grow0)     v1 = -1e30f;
                float v2 = s[nt][2] * scale; if (gc     > grow0 + 8) v2 = -1e30f;
                float v3 = s[nt][3] * scale; if (gc + 1 > grow0 + 8) v3 = -1e30f;
                s[nt][0] = v0; s[nt][1] = v1; s[nt][2] = v2; s[nt][3] = v3;
                mx0 = fmaxf(mx0, fmaxf(v0, v1));
                mx1 = fmaxf(mx1, fmaxf(v2, v3));
            }
            mx0 = fmaxf(mx0, __shfl_xor_sync(0xffffffffu, mx0, 1));
            mx0 = fmaxf(mx0, __shfl_xor_sync(0xffffffffu, mx0, 2));
            mx1 = fmaxf(mx1, __shfl_xor_sync(0xffffffffu, mx1, 1));
            mx1 = fmaxf(mx1, __shfl_xor_sync(0xffffffffu, mx1, 2));
            float mn0 = fmaxf(m_r0, mx0), mn1 = fmaxf(m_r1, mx1);
            float al0 = __expf(m_r0 - mn0), al1 = __expf(m_r1 - mn1);
            float sm0 = 0.f, sm1 = 0.f;
            #pragma unroll
            for (int nt = 0; nt < 8; nt++) {
                float p0 = __expf(s[nt][0] - mn0);
                float p1 = __expf(s[nt][1] - mn0);
                float p2 = __expf(s[nt][2] - mn1);
                float p3 = __expf(s[nt][3] - mn1);
                s[nt][0] = p0; s[nt][1] = p1; s[nt][2] = p2; s[nt][3] = p3;
                sm0 += p0 + p1; sm1 += p2 + p3;
            }
            sm0 += __shfl_xor_sync(0xffffffffu, sm0, 1);
            sm0 += __shfl_xor_sync(0xffffffffu, sm0, 2);
            sm1 += __shfl_xor_sync(0xffffffffu, sm1, 1);
            sm1 += __shfl_xor_sync(0xffffffffu, sm1, 2);
            l_r0 = l_r0 * al0 + sm0;
            l_r1 = l_r1 * al1 + sm1;
            m_r0 = mn0; m_r1 = mn1;
            #pragma unroll
            for (int i = 0; i < 16; i++) {
                o[i][0] *= al0; o[i][1] *= al0;
                o[i][2] *= al1; o[i][3] *= al1;
            }

            // ---- O += P V (bf16x3) ----
            #pragma unroll
            for (int kt2 = 0; kt2 < 4; kt2++) {
                uint32_t ah[4], apl[4];
                {
                    bf16 h0, lo0, h1, lo1;
                    splitf(s[2*kt2][0], h0, lo0); splitf(s[2*kt2][1], h1, lo1);
                    ah[0] = packbf2(h0, h1); apl[0] = packbf2(lo0, lo1);
                    splitf(s[2*kt2][2], h0, lo0); splitf(s[2*kt2][3], h1, lo1);
                    ah[1] = packbf2(h0, h1); apl[1] = packbf2(lo0, lo1);
                    splitf(s[2*kt2+1][0], h0, lo0); splitf(s[2*kt2+1][1], h1, lo1);
                    ah[2] = packbf2(h0, h1); apl[2] = packbf2(lo0, lo1);
                    splitf(s[2*kt2+1][2], h0, lo0); splitf(s[2*kt2+1][3], h1, lo1);
                    ah[3] = packbf2(h0, h1); apl[3] = packbf2(lo0, lo1);
                }
                int kk2 = kt2 * 16 + ldc8;
                #pragma unroll
                for (int np = 0; np < 8; np++) {
                    uint32_t vadr = sb + (vst + (np * 16 + ldr) * 72 + kk2) * 2;
                    uint32_t rh[4], rl[4];
                    ldsm4(rh, vadr);
                    ldsm4(rl, vadr + 9216 * 2);
                    uint32_t b0h[2] = {rh[0], rh[2]}, b1h[2] = {rh[1], rh[3]};
                    uint32_t b0l[2] = {rl[0], rl[2]}, b1l[2] = {rl[1], rl[3]};
                    mma16816(o[np*2],   ah,  b0h);
                    mma16816(o[np*2],   ah,  b0l);
                    mma16816(o[np*2],   apl, b0h);
                    mma16816(o[np*2+1], ah,  b1h);
                    mma16816(o[np*2+1], ah,  b1l);
                    mma16816(o[np*2+1], apl, b1h);
                }
            }
        }
        __syncthreads();
    }
    #undef LOAD_KV

    // ---- normalize + write ao (bf16 hi/lo) ----
    float inv0 = 1.f / l_r0, inv1 = 1.f / l_r1;
    int row0 = m0 + rbase + (lane >> 2);
    size_t base0 = (size_t)row0 * (NH * HD) + (size_t)h * HD;
    size_t base1 = base0 + (size_t)8 * (NH * HD);
    #pragma unroll
    for (int nt = 0; nt < 16; nt++) {
        int col = nt * 8 + (lane & 3) * 2;
        bf16 h0, lo0, h1, lo1;
        splitf(o[nt][0] * inv0, h0, lo0); splitf(o[nt][1] * inv0, h1, lo1);
        *(__nv_bfloat162*)(ao_h + base0 + col) = __nv_bfloat162(h0, h1);
        *(__nv_bfloat162*)(ao_l + base0 + col) = __nv_bfloat162(lo0, lo1);
        splitf(o[nt][2] * inv1, h0, lo0); splitf(o[nt][3] * inv1, h1, lo1);
        *(__nv_bfloat162*)(ao_h + base1 + col) = __nv_bfloat162(h0, h1);
        *(__nv_bfloat162*)(ao_l + base1 + col) = __nv_bfloat162(lo0, lo1);
    }
}

// ---------------- router -----------------------------------------------------------
__global__ void gate_topk_kernel(const float* __restrict__ h2, const float* __restrict__ gw,
                                 int* __restrict__ oidx, float* __restrict__ orw) {
    int t = blockIdx.x;
    int e = threadIdx.x >> 4, l = threadIdx.x & 15;
    const float* hr = h2 + (size_t)t * HDM;
    const float* wr = gw + (size_t)e * HDM;
    float p = 0.f;
    for (int k = l; k < HDM; k += 16) p += hr[k] * wr[k];
    #pragma unroll
    for (int o = 8; o; o >>= 1) p += __shfl_xor_sync(0xffffffffu, p, o);
    __shared__ float slog[NE];
    if (l == 0) slog[e] = p;
    __syncthreads();
    if (threadIdx.x == 0) {
        float pr[NE];
        float mx = -3.4e38f;
        for (int i = 0; i < NE; i++) { pr[i] = slog[i]; mx = fmaxf(mx, pr[i]); }
        float sum = 0.f;
        for (int i = 0; i < NE; i++) { pr[i] = __expf(pr[i] - mx); sum += pr[i]; }
        float inv = 1.f / sum;
        for (int i = 0; i < NE; i++) pr[i] *= inv;
        int sel[TOPK]; float sv[TOPK]; float wsum = 0.f;
        for (int k = 0; k < TOPK; k++) {
            int best = 0; float bv = -1.f;
            for (int i = 0; i < NE; i++)
                if (pr[i] > bv) { bv = pr[i]; best = i; }
            sel[k] = best; sv[k] = bv; wsum += bv; pr[best] = -2.f;
        }
        float winv = 1.f / wsum;
        for (int k = 0; k < TOPK; k++) { oidx[t * TOPK + k] = sel[k]; orw[t * TOPK + k] = sv[k] * winv; }
    }
}

// ---------------- deterministic routing sort ----------------------------------------
__global__ void route_kernel(const int* __restrict__ idx, int* __restrict__ counts,
                             int* __restrict__ offs, int* __restrict__ token_of,
                             int* __restrict__ slot_of) {
    int c = threadIdx.x;
    int start = c * (NSLOT / 32);
    int cnt[NE];
    #pragma unroll
    for (int e = 0; e < NE; e++) cnt[e] = 0;
    for (int i = 0; i < NSLOT / 32; i++) cnt[idx[start + i]]++;
    __shared__ int scnt[32][NE];
    __shared__ int sbase[32][NE];
    for (int e = 0; e < NE; e++) scnt[c][e] = cnt[e];
    __syncthreads();
    if (c == 0) {
        int off = 0;
        for (int e = 0; e < NE; e++) {
            offs[e] = off;
            int run = off;
            for (int cc = 0; cc < 32; cc++) { sbase[cc][e] = run; run += scnt[cc][e]; }
            counts[e] = run - off;
            off = run;
        }
    }
    __syncthreads();
    int base[NE];
    #pragma unroll
    for (int e = 0; e < NE; e++) base[e] = sbase[c][e];
    for (int i = 0; i < NSLOT / 32; i++) {
        int entry = start + i;
        int e = idx[entry];
        int pos = base[e]++;
        token_of[pos] = entry >> 2;
        slot_of[entry] = pos;
    }
}

// ---------------- silu(g)*u --------------------------------------------------------
__global__ void silu_mul_kernel(const float* __restrict__ gu, bf16* __restrict__ gh,
                                bf16* __restrict__ gl) {
    int s = blockIdx.x;
    const float* row = gu + (size_t)s * GUN;
    for (int i = threadIdx.x; i < ID; i += blockDim.x) {
        float x = row[i];
        float u = row[ID + i];
        float v = (x / (1.f + __expf(-x))) * u;
        bf16 h, l; splitf(v, h, l);
        gh[(size_t)s * ID + i] = h;
        gl[(size_t)s * ID + i] = l;
    }
}

// ---------------- final combine ------------------------------------------------------
__global__ void combine_kernel(const float* __restrict__ res, const float* __restrict__ ybuf,
                               const int* __restrict__ slot_of, const float* __restrict__ rw,
                               float* __restrict__ out) {
    int t = blockIdx.x;
    int s0 = slot_of[t*4+0], s1 = slot_of[t*4+1], s2 = slot_of[t*4+2], s3 = slot_of[t*4+3];
    float w0 = rw[t*4+0], w1 = rw[t*4+1], w2 = rw[t*4+2], w3 = rw[t*4+3];
    const float* y0 = ybuf + (size_t)s0 * HDM;
    const float* y1 = ybuf + (size_t)s1 * HDM;
    const float* y2 = ybuf + (size_t)s2 * HDM;
    const float* y3 = ybuf + (size_t)s3 * HDM;
    size_t base = (size_t)t * HDM;
    for (int i = threadIdx.x; i < HDM; i += blockDim.x)
        out[base + i] = res[base + i] + w0 * y0[i] + w1 * y1[i] + w2 * y2[i] + w3 * y3[i];
}

// ========================================================================================
extern "C" void kernel_launch(void* const* d_in, const int* in_sizes, int n_in,
                              void* d_out, int out_size) {
    const float* x    = (const float*)d_in[0];
    const float* pe   = (const float*)d_in[1];
    const float* q_w  = (const float*)d_in[3];
    const float* k_w  = (const float*)d_in[4];
    const float* v_w  = (const float*)d_in[5];
    const float* o_w  = (const float*)d_in[6];
    const float* q_nw = (const float*)d_in[7];
    const float* k_nw = (const float*)d_in[8];
    const float* ln1  = (const float*)d_in[9];
    const float* ln2  = (const float*)d_in[10];
    const float* gw   = (const float*)d_in[11];
    const float* gpw  = (const float*)d_in[12];
    const float* upw  = (const float*)d_in[13];
    const float* dpw  = (const float*)d_in[14];
    float* out = (float*)d_out;

    #define SYM(T, p, s) T p; cudaGetSymbolAddress((void**)&p, s)
    SYM(bf16*, wqkv_h, g_wqkv_h); SYM(bf16*, wqkv_l, g_wqkv_l);
    SYM(bf16*, wo_h, g_wo_h);     SYM(bf16*, wo_l, g_wo_l);
    SYM(bf16*, wgu_h, g_wgu_h);   SYM(bf16*, wgu_l, g_wgu_l);
    SYM(bf16*, wd_h, g_wd_h);     SYM(bf16*, wd_l, g_wd_l);
    SYM(bf16*, xn_h, g_xn_h);     SYM(bf16*, xn_l, g_xn_l);
    SYM(float*, qkvlin, g_qkvlin);
    SYM(bf16*, qh_h, g_qh_h);     SYM(bf16*, qh_l, g_qh_l);
    SYM(bf16*, kh_h, g_kh_h);     SYM(bf16*, kh_l, g_kh_l);
    SYM(bf16*, vt_h, g_vt_h);     SYM(bf16*, vt_l, g_vt_l);
    SYM(bf16*, ao_h, g_ao_h);     SYM(bf16*, ao_l, g_ao_l);
    SYM(float*, res, g_res);
    SYM(float*, h2f, g_h2f);
    SYM(bf16*, h2_h, g_h2_h);     SYM(bf16*, h2_l, g_h2_l);
    SYM(float*, gu, g_gu);
    SYM(bf16*, gg_h, g_g_h);      SYM(bf16*, gg_l, g_g_l);
    SYM(float*, ybuf, g_ybuf);
    SYM(int*, tidx, g_tidx);      SYM(float*, trw, g_trw);
    SYM(int*, counts, g_counts);  SYM(int*, offs, g_offs);
    SYM(int*, token_of, g_token_of); SYM(int*, slot_of, g_slot_of);
    #undef SYM

    static bool attr_done = false;
    if (!attr_done) {
        cudaFuncSetAttribute(gemm_mma<0,0>, cudaFuncAttributeMaxDynamicSharedMemorySize, SMEM_BYTES);
        cudaFuncSetAttribute(gemm_mma<2,0>, cudaFuncAttributeMaxDynamicSharedMemorySize, SMEM_BYTES);
        cudaFuncSetAttribute(gemm_mma<0,1>, cudaFuncAttributeMaxDynamicSharedMemorySize, SMEM_BYTES);
        cudaFuncSetAttribute(gemm_mma<0,2>, cudaFuncAttributeMaxDynamicSharedMemorySize, SMEM_BYTES);
        cudaFuncSetAttribute(flash_kernel, cudaFuncAttributeMaxDynamicSharedMemorySize, FSMEM);
        attr_done = true;
    }

    const float scale = 0.08838834764831845f;

    // ---- weight conversions ----
    {
        size_t nq = (size_t)NH*HD*HDM, nk = (size_t)NKV*HD*HDM;
        split_kernel<<<(unsigned)((nq/4+255)/256), 256>>>(q_w, wqkv_h, wqkv_l, nq);
        split_kernel<<<(unsigned)((nk/4+255)/256), 256>>>(k_w, wqkv_h + nq, wqkv_l + nq, nk);
        split_kernel<<<(unsigned)((nk/4+255)/256), 256>>>(v_w, wqkv_h + nq + nk, wqkv_l + nq + nk, nk);
        size_t no = (size_t)HDM*NH*HD;
        split_kernel<<<(unsigned)((no/4+255)/256), 256>>>(o_w, wo_h, wo_l, no);
        size_t ngu = (size_t)NE*ID*HDM;
        split_gu_kernel<<<(unsigned)((ngu/4+255)/256), 256>>>(gpw, upw, wgu_h, wgu_l);
        size_t nd = (size_t)NE*HDM*ID;
        split_kernel<<<(unsigned)((nd/4+255)/256), 256>>>(dpw, wd_h, wd_l, nd);
    }

    // ---- attention ----
    rmsnorm_kernel<<<SQ, 256>>>(x, ln1, nullptr, xn_h, xn_l, HDM);
    gemm_mma<0,0><<<dim3(QKVN/BN, SQ/BM, 1), 256, SMEM_BYTES>>>(
        xn_h, xn_l, HDM, 0, wqkv_h, wqkv_l, HDM, 0,
        qkvlin, QKVN, 0, HDM, nullptr, 0, nullptr, nullptr, nullptr);
    norm_rope_kernel<<<dim3(SQ, NH), HD>>>(qkvlin, 0, q_nw, pe, qh_h, qh_l);
    norm_rope_kernel<<<dim3(SQ, NKV), HD>>>(qkvlin, NH*HD, k_nw, pe, kh_h, kh_l);
    vtrans_kernel<<<(NKV*HD*SQ)/256, 256>>>(qkvlin, vt_h, vt_l);
    flash_kernel<<<dim3(SQ/128, NH), 256, FSMEM>>>(
        qh_h, qh_l, kh_h, kh_l, vt_h, vt_l, ao_h, ao_l, scale);
    gemm_mma<2,0><<<dim3(HDM/BN, SQ/BM, 1), 256, SMEM_BYTES>>>(
        ao_h, ao_l, NH*HD, 0, wo_h, wo_l, NH*HD, 0,
        res, HDM, 0, NH*HD, x, HDM, nullptr, nullptr, nullptr);

    // ---- MoE ----
    rmsnorm_kernel<<<SQ, 256>>>(res, ln2, h2f, h2_h, h2_l, HDM);
    gate_topk_kernel<<<SQ, 256>>>(h2f, gw, tidx, trw);
    route_kernel<<<1, 32>>>(tidx, counts, offs, token_of, slot_of);
    gemm_mma<0,1><<<dim3(GUN/BN, NSLOT/BM, NE), 256, SMEM_BYTES>>>(
        h2_h, h2_l, HDM, 0, wgu_h, wgu_l, HDM, (long)GUN*HDM,
        gu, GUN, 0, HDM, nullptr, 0, counts, offs, token_of);
    silu_mul_kernel<<<NSLOT, 256>>>(gu, gg_h, gg_l);
    gemm_mma<0,2><<<dim3(HDM/BN, NSLOT/BM, NE), 256, SMEM_BYTES>>>(
        gg_h, gg_l, ID, 0, wd_h, wd_l, ID, (long)HDM*ID,
        ybuf, HDM, 0, ID, nullptr, 0, counts, offs, token_of);
    combine_kernel<<<SQ, 256>>>(res, ybuf, slot_of, trw, out);
}

// round 6
// speedup vs baseline: 2.9524x; 1.0198x over previous
#include <cuda_runtime.h>
#include <cuda_bf16.h>
#include <cstdint>

#define SQ    2048
#define HDM   2048
#define NH    32
#define NKV   4
#define HD    128
#define NE    16
#define ID    768
#define TOPK  4
#define NSLOT (SQ*TOPK)
#define QKVN  (NH*HD + 2*NKV*HD)   // 5120
#define GUN   (2*ID)               // 1536

typedef __nv_bfloat16 bf16;

// ---------------- device scratch -------------------------------------------
__device__ __align__(16) bf16 g_wqkv_h[(size_t)QKVN*HDM],  g_wqkv_l[(size_t)QKVN*HDM];
__device__ __align__(16) bf16 g_wo_h[(size_t)HDM*NH*HD],   g_wo_l[(size_t)HDM*NH*HD];
__device__ __align__(16) bf16 g_wgu_h[(size_t)NE*GUN*HDM], g_wgu_l[(size_t)NE*GUN*HDM];
__device__ __align__(16) bf16 g_wd_h[(size_t)NE*HDM*ID],   g_wd_l[(size_t)NE*HDM*ID];
__device__ __align__(16) bf16 g_xn_h[(size_t)SQ*HDM],      g_xn_l[(size_t)SQ*HDM];
__device__ __align__(16) float g_qkvlin[(size_t)SQ*QKVN];
__device__ __align__(16) bf16 g_qh_h[(size_t)NH*SQ*HD],    g_qh_l[(size_t)NH*SQ*HD];
__device__ __align__(16) bf16 g_kh_h[(size_t)NKV*SQ*HD],   g_kh_l[(size_t)NKV*SQ*HD];
__device__ __align__(16) bf16 g_vt_h[(size_t)NKV*HD*SQ],   g_vt_l[(size_t)NKV*HD*SQ];
__device__ __align__(16) bf16 g_ao_h[(size_t)SQ*NH*HD],    g_ao_l[(size_t)SQ*NH*HD];
__device__ __align__(16) float g_res[SQ*HDM];
__device__ __align__(16) float g_h2f[SQ*HDM];
__device__ __align__(16) bf16 g_h2_h[(size_t)SQ*HDM],      g_h2_l[(size_t)SQ*HDM];
__device__ __align__(16) float g_gu[(size_t)NSLOT*GUN];
__device__ __align__(16) bf16 g_g_h[(size_t)NSLOT*ID],     g_g_l[(size_t)NSLOT*ID];
__device__ __align__(16) float g_ybuf[(size_t)NSLOT*HDM];
__device__ int   g_tidx[NSLOT];
__device__ float g_trw[NSLOT];
__device__ int   g_counts[NE];
__device__ int   g_offs[NE];
__device__ int   g_token_of[NSLOT];
__device__ int   g_slot_of[NSLOT];

// ---------------- helpers ----------------------------------------------------
__device__ __forceinline__ void splitf(float v, bf16& h, bf16& l) {
    h = __float2bfloat16(v);
    l = __float2bfloat16(v - __bfloat162float(h));
}
__device__ __forceinline__ uint32_t packbf2(bf16 a, bf16 b) {
    __nv_bfloat162 t(a, b);
    return *(uint32_t*)&t;
}
__device__ __forceinline__ void ldsm4(uint32_t r[4], uint32_t addr) {
    asm volatile("ldmatrix.sync.aligned.m8n8.x4.shared.b16 {%0,%1,%2,%3},[%4];"
        : "=r"(r[0]), "=r"(r[1]), "=r"(r[2]), "=r"(r[3]) : "r"(addr));
}
__device__ __forceinline__ void mma16816(float c[4], const uint32_t a[4], const uint32_t b[2]) {
    asm volatile("mma.sync.aligned.m16n8k16.row.col.f32.bf16.bf16.f32 "
        "{%0,%1,%2,%3},{%4,%5,%6,%7},{%8,%9},{%0,%1,%2,%3};"
        : "+f"(c[0]), "+f"(c[1]), "+f"(c[2]), "+f"(c[3])
        : "r"(a[0]), "r"(a[1]), "r"(a[2]), "r"(a[3]), "r"(b[0]), "r"(b[1]));
}
__device__ __forceinline__ void cp16(uint32_t dst, const void* src, int sz) {
    asm volatile("cp.async.cg.shared.global [%0],[%1],16,%2;\n" :: "r"(dst), "l"(src), "r"(sz));
}
__device__ __forceinline__ void cp_commit() { asm volatile("cp.async.commit_group;\n"); }
__device__ __forceinline__ void cp_wait1() { asm volatile("cp.async.wait_group 1;\n"); }

__device__ __forceinline__ float blockReduceSum(float v) {
    __shared__ float sh[8];
    int lane = threadIdx.x & 31, w = threadIdx.x >> 5;
    #pragma unroll
    for (int o = 16; o; o >>= 1) v += __shfl_xor_sync(0xffffffffu, v, o);
    if (lane == 0) sh[w] = v;
    __syncthreads();
    float r = (threadIdx.x < (blockDim.x >> 5)) ? sh[threadIdx.x] : 0.f;
    if (w == 0) {
        #pragma unroll
        for (int o = 4; o; o >>= 1) r += __shfl_xor_sync(0xffffffffu, r, o);
        if (lane == 0) sh[0] = r;
    }
    __syncthreads();
    r = sh[0];
    __syncthreads();
    return r;
}

// ---------------- weight split conversions (16 floats/thread) -------------------
__global__ void split_kernel(const float* __restrict__ in, bf16* __restrict__ hi,
                             bf16* __restrict__ lo, size_t n) {
    size_t base = (size_t)blockIdx.x * 4096 + threadIdx.x * 4;
    #pragma unroll
    for (int u = 0; u < 4; u++) {
        size_t i = base + u * 1024;
        if (i >= n) return;
        float4 v = *(const float4*)(in + i);
        bf16 h0, l0, h1, l1, h2, l2, h3, l3;
        splitf(v.x, h0, l0); splitf(v.y, h1, l1); splitf(v.z, h2, l2); splitf(v.w, h3, l3);
        *(__nv_bfloat162*)(hi + i)     = __nv_bfloat162(h0, h1);
        *(__nv_bfloat162*)(hi + i + 2) = __nv_bfloat162(h2, h3);
        *(__nv_bfloat162*)(lo + i)     = __nv_bfloat162(l0, l1);
        *(__nv_bfloat162*)(lo + i + 2) = __nv_bfloat162(l2, l3);
    }
}

__global__ void split_gu_kernel(const float* __restrict__ gp, const float* __restrict__ up,
                                bf16* __restrict__ hi, bf16* __restrict__ lo) {
    size_t base = (size_t)blockIdx.x * 4096 + threadIdx.x * 4;
    #pragma unroll
    for (int u = 0; u < 4; u++) {
        size_t i = base + u * 1024;
        if (i >= (size_t)NE * ID * HDM) return;
        size_t e = i / ((size_t)ID * HDM);
        size_t rem = i - e * (size_t)ID * HDM;
        size_t dg = e * (size_t)GUN * HDM + rem;
        size_t du = dg + (size_t)ID * HDM;
        float4 vg = *(const float4*)(gp + i);
        float4 vu = *(const float4*)(up + i);
        bf16 h, l;
        splitf(vg.x, h, l); hi[dg] = h; lo[dg] = l;
        splitf(vg.y, h, l); hi[dg+1] = h; lo[dg+1] = l;
        splitf(vg.z, h, l); hi[dg+2] = h; lo[dg+2] = l;
        splitf(vg.w, h, l); hi[dg+3] = h; lo[dg+3] = l;
        splitf(vu.x, h, l); hi[du] = h; lo[du] = l;
        splitf(vu.y, h, l); hi[du+1] = h; lo[du+1] = l;
        splitf(vu.z, h, l); hi[du+2] = h; lo[du+2] = l;
        splitf(vu.w, h, l); hi[du+3] = h; lo[du+3] = l;
    }
}

// ---------------- rms norm ------------------------------------------------------
__global__ void rmsnorm_kernel(const float* __restrict__ x, const float* __restrict__ w,
                               float* __restrict__ outf, bf16* __restrict__ oh,
                               bf16* __restrict__ ol, int ncols) {
    size_t base = (size_t)blockIdx.x * ncols;
    float ss = 0.f;
    for (int i = threadIdx.x; i < ncols; i += blockDim.x) { float v = x[base + i]; ss += v * v; }
    ss = blockReduceSum(ss);
    float r = rsqrtf(ss / ncols + 1e-6f);
    for (int i = threadIdx.x; i < ncols; i += blockDim.x) {
        float v = w[i] * x[base + i] * r;
        if (outf) outf[base + i] = v;
        if (oh) { bf16 h, l; splitf(v, h, l); oh[base + i] = h; ol[base + i] = l; }
    }
}

// ---------------- per-head rmsnorm + rope --------------------------------------
__global__ void norm_rope_kernel(const float* __restrict__ lin, int colbase,
                                 const float* __restrict__ nw, const float* __restrict__ pe,
                                 bf16* __restrict__ oh, bf16* __restrict__ ol) {
    int t = blockIdx.x, h = blockIdx.y, d = threadIdx.x;
    float v = lin[(size_t)t * QKVN + colbase + h * HD + d];
    float ss = v * v;
    #pragma unroll
    for (int o = 16; o; o >>= 1) ss += __shfl_xor_sync(0xffffffffu, ss, o);
    __shared__ float wsum[4];
    if ((d & 31) == 0) wsum[d >> 5] = ss;
    __syncthreads();
    float tot = wsum[0] + wsum[1] + wsum[2] + wsum[3];
    float xn = nw[d] * v * rsqrtf(tot * (1.f / HD) + 1e-6f);
    __shared__ float sh[HD];
    sh[d] = xn;
    __syncthreads();
    float c = pe[(size_t)t * HD + d];
    float s = pe[(size_t)SQ * HD + (size_t)t * HD + d];
    float rot = (d < HD / 2) ? -sh[d + HD / 2] : sh[d - HD / 2];
    float o = xn * c + rot * s;
    size_t idx = ((size_t)h * SQ + t) * HD + d;
    bf16 hh, ll; splitf(o, hh, ll);
    oh[idx] = hh; ol[idx] = ll;
}

// ---------------- V transpose + split -------------------------------------------
__global__ void vtrans_kernel(const float* __restrict__ qkvlin, bf16* __restrict__ vh,
                              bf16* __restrict__ vl) {
    int i = blockIdx.x * blockDim.x + threadIdx.x;
    int t = i & (SQ - 1);
    int d = (i >> 11) & (HD - 1);
    int kv = i >> 18;
    float v = qkvlin[(size_t)t * QKVN + (NH * HD + NKV * HD) + kv * HD + d];
    bf16 h, l; splitf(v, h, l);
    vh[i] = h; vl[i] = l;
}

// =================================================================================
// bf16x3 mma.sync GEMM, 2-stage cp.async, 2 syncs/tile, 2 CTAs/SM.
// MODE 0 dense / 1 gather rows / 2 direct ragged rows
// EPI 0 fp32 store / 2 fp32 + residual
// =================================================================================
#define BM 128
#define BN 128
#define BK 32
#define BKP 40
#define TILE_HALF (BM * BKP)
#define STAGE_ELEMS (4 * TILE_HALF)
#define STAGE_B (STAGE_ELEMS * 2)
#define SMEM_BYTES (2 * STAGE_B)     // 81920

template<int EPI, int MODE>
__global__ void __launch_bounds__(256, 2) gemm_mma(
    const bf16* __restrict__ Ah, const bf16* __restrict__ Al, int lda, long sAz,
    const bf16* __restrict__ Bh, const bf16* __restrict__ Bl, int ldb, long sBz,
    float* __restrict__ Cf, int ldc, long sCz,
    int K, const float* __restrict__ epi, int lde,
    const int* __restrict__ counts, const int* __restrict__ offs,
    const int* __restrict__ token_of)
{
    int z = blockIdx.z;
    int m0 = blockIdx.y * BM, n0 = blockIdx.x * BN;
    int Me = 0x7fffffff, off = 0;
    if (MODE != 0) { Me = counts[z]; if (m0 >= Me) return; off = offs[z]; }
    int nkt = K / BK;

    const bf16* Ahp = Ah; const bf16* Alp = Al;
    if (MODE == 0) { Ahp += (size_t)z * sAz; Alp += (size_t)z * sAz; }
    const bf16* Bhp = Bh + (size_t)z * sBz;
    const bf16* Blp = Bl + (size_t)z * sBz;

    extern __shared__ bf16 smem[];
    uint32_t sbase = (uint32_t)__cvta_generic_to_shared(smem);

    int tid = threadIdx.x;
    int lr = tid >> 2;
    int lc = (tid & 3) * 8;

    int rl0 = m0 + lr, rl1 = m0 + lr + 64;
    bool av0 = true, av1 = true;
    size_t ar0, ar1;
    if (MODE == 1) {
        av0 = rl0 < Me; av1 = rl1 < Me;
        ar0 = av0 ? (size_t)token_of[off + rl0] : 0;
        ar1 = av1 ? (size_t)token_of[off + rl1] : 0;
    } else if (MODE == 2) {
        av0 = rl0 < Me; av1 = rl1 < Me;
        ar0 = av0 ? (size_t)(off + rl0) : 0;
        ar1 = av1 ? (size_t)(off + rl1) : 0;
    } else { ar0 = rl0; ar1 = rl1; }
    size_t offA0 = ar0 * (size_t)lda + lc;
    size_t offA1 = ar1 * (size_t)lda + lc;
    size_t offB0 = (size_t)(n0 + lr) * ldb + lc;
    size_t offB1 = (size_t)(n0 + lr + 64) * ldb + lc;
    int sz0 = av0 ? 16 : 0, sz1 = av1 ? 16 : 0;

    uint32_t dA0 = sbase + (lr * BKP + lc) * 2;
    uint32_t dA1 = sbase + ((lr + 64) * BKP + lc) * 2;
    const uint32_t OFF_AL = TILE_HALF * 2, OFF_BH = 2 * TILE_HALF * 2, OFF_BL = 3 * TILE_HALF * 2;

    const int warp = tid >> 5, lane = tid & 31;
    const int wm = (warp >> 1) * 32;
    const int wn = (warp & 1) * 64;
    const int ldr = lane & 15;
    const int ldc8 = (lane >> 4) * 8;

    float acc[2][8][4];
    #pragma unroll
    for (int i = 0; i < 2; i++)
        #pragma unroll
        for (int j = 0; j < 8; j++)
            #pragma unroll
            for (int q = 0; q < 4; q++) acc[i][j][q] = 0.f;

    #define LOAD_STAGE(kt) do {                                        \
        uint32_t nb = (uint32_t)((kt) & 1) * STAGE_B;                   \
        int k0_ = (kt) * BK;                                            \
        cp16(dA0 + nb, Ahp + offA0 + k0_, sz0);                         \
        cp16(dA1 + nb, Ahp + offA1 + k0_, sz1);                         \
        cp16(dA0 + nb + OFF_AL, Alp + offA0 + k0_, sz0);                \
        cp16(dA1 + nb + OFF_AL, Alp + offA1 + k0_, sz1);                \
        cp16(dA0 + nb + OFF_BH, Bhp + offB0 + k0_, 16);                 \
        cp16(dA1 + nb + OFF_BH, Bhp + offB1 + k0_, 16);                 \
        cp16(dA0 + nb + OFF_BL, Blp + offB0 + k0_, 16);                 \
        cp16(dA1 + nb + OFF_BL, Blp + offB1 + k0_, 16);                 \
    } while (0)

    LOAD_STAGE(0);
    cp_commit();

    for (int kt = 0; kt < nkt; kt++) {
        if (kt + 1 < nkt) LOAD_STAGE(kt + 1);
        cp_commit();
        cp_wait1();
        __syncthreads();

        uint32_t bA = sbase + (uint32_t)(kt & 1) * STAGE_B;
        uint32_t sAh = bA, sAl = bA + OFF_AL, sBh = bA + OFF_BH, sBl = bA + OFF_BL;
        #pragma unroll
        for (int ks = 0; ks < 2; ks++) {
            int kk = ks * 16 + ldc8;
            uint32_t ah[2][4], al[2][4], bh[8][2], bl[8][2];
            #pragma unroll
            for (int mt = 0; mt < 2; mt++) {
                uint32_t adr = ((wm + mt * 16 + ldr) * BKP + kk) * 2;
                ldsm4(ah[mt], sAh + adr);
                ldsm4(al[mt], sAl + adr);
            }
            #pragma unroll
            for (int np = 0; np < 4; np++) {
                uint32_t adr = ((wn + np * 16 + ldr) * BKP + kk) * 2;
                uint32_t r[4];
                ldsm4(r, sBh + adr);
                bh[np*2][0] = r[0]; bh[np*2+1][0] = r[1]; bh[np*2][1] = r[2]; bh[np*2+1][1] = r[3];
                ldsm4(r, sBl + adr);
                bl[np*2][0] = r[0]; bl[np*2+1][0] = r[1]; bl[np*2][1] = r[2]; bl[np*2+1][1] = r[3];
            }
            #pragma unroll
            for (int mt = 0; mt < 2; mt++)
                #pragma unroll
                for (int nt = 0; nt < 8; nt++) {
                    mma16816(acc[mt][nt], ah[mt], bh[nt]);
                    mma16816(acc[mt][nt], ah[mt], bl[nt]);
                    mma16816(acc[mt][nt], al[mt], bh[nt]);
                }
        }
        __syncthreads();
    }
    #undef LOAD_STAGE

    int er = lane >> 2;
    int ec = (lane & 3) * 2;
    #pragma unroll
    for (int mt = 0; mt < 2; mt++) {
        #pragma unroll
        for (int h = 0; h < 2; h++) {
            int mloc = m0 + wm + mt * 16 + h * 8 + er;
            bool mvalid = (MODE == 0) || (mloc < Me);
            if (!mvalid) continue;
            size_t crow = (MODE == 0) ? (size_t)mloc : (size_t)(off + mloc);
            #pragma unroll
            for (int nt = 0; nt < 8; nt++) {
                int col = n0 + wn + nt * 8 + ec;
                float v0 = acc[mt][nt][h * 2 + 0];
                float v1 = acc[mt][nt][h * 2 + 1];
                if (EPI == 2) {
                    float2 rr = *(const float2*)(epi + (size_t)mloc * lde + col);
                    v0 += rr.x; v1 += rr.y;
                }
                size_t ci = (size_t)z * sCz + crow * ldc + col;
                *(float2*)(Cf + ci) = make_float2(v0, v1);
            }
        }
    }
}

// =================================================================================
// Fused flash attention (reversed m-block order: heavy CTAs first)
// =================================================================================
#define FQH 0
#define FQL 17408
#define FKOFF 34816
#define FVOFF 69632
#define FSMEM (106496 * 2)

__global__ void __launch_bounds__(256, 1) flash_kernel(
    const bf16* __restrict__ qh_h, const bf16* __restrict__ qh_l,
    const bf16* __restrict__ kh_h, const bf16* __restrict__ kh_l,
    const bf16* __restrict__ vt_h, const bf16* __restrict__ vt_l,
    bf16* __restrict__ ao_h, bf16* __restrict__ ao_l, float scale)
{
    int m0 = (gridDim.x - 1 - blockIdx.x) * 128;
    int h = blockIdx.y;
    int kvh = h >> 3;

    extern __shared__ bf16 fsm[];
    uint32_t sb = (uint32_t)__cvta_generic_to_shared(fsm);

    int tid = threadIdx.x, wid = tid >> 5, lane = tid & 31;
    const int ldr = lane & 15, ldc8 = (lane >> 4) * 8;

    {
        const bf16* qs_h = qh_h + ((size_t)h * SQ + m0) * HD;
        const bf16* qs_l = qh_l + ((size_t)h * SQ + m0) * HD;
        for (int c = tid; c < 2048; c += 256) {
            int r = c >> 4, col = (c & 15) * 8;
            size_t go = (size_t)r * HD + col;
            cp16(sb + (uint32_t)(FQH + r * 136 + col) * 2, qs_h + go, 16);
            cp16(sb + (uint32_t)(FQL + r * 136 + col) * 2, qs_l + go, 16);
        }
    }
    cp_commit();

    int nj = (m0 + 128) >> 6;

    #define LOAD_KV(jj, stg) do {                                                     \
        for (int c = tid; c < 1024; c += 256) {                                        \
            int kr = c >> 4, kc = (c & 15) * 8;                                        \
            size_t kgo = ((size_t)kvh * SQ + (jj) * 64 + kr) * HD + kc;                \
            uint32_t kd = sb + (uint32_t)(FKOFF + (stg) * 17408 + kr * 136 + kc) * 2;  \
            cp16(kd, kh_h + kgo, 16);                                                  \
            cp16(kd + 8704 * 2, kh_l + kgo, 16);                                       \
            int vr = c >> 3, vc = (c & 7) * 8;                                         \
            size_t vgo = ((size_t)kvh * HD + vr) * SQ + (jj) * 64 + vc;                \
            cp16(sb + (uint32_t)(FVOFF + (stg) * 18432 + vr * 72 + vc) * 2, vt_h + vgo, 16); \
            cp16(sb + (uint32_t)(FVOFF + (stg) * 18432 + vr * 72 + vc) * 2 + 9216 * 2, vt_l + vgo, 16); \
        }                                                                               \
    } while (0)

    LOAD_KV(0, 0);
    cp_commit();

    int rbase = wid * 16;
    float m_r0 = -1e30f, m_r1 = -1e30f, l_r0 = 0.f, l_r1 = 0.f;
    float o[16][4];
    #pragma unroll
    for (int i = 0; i < 16; i++)
        #pragma unroll
        for (int q = 0; q < 4; q++) o[i][q] = 0.f;

    int grow0 = m0 + rbase + (lane >> 2);
    int ar = rbase + ldr;

    for (int j = 0; j < nj; j++) {
        if (j + 1 < nj) LOAD_KV(j + 1, (j + 1) & 1);
        cp_commit();
        cp_wait1();
        __syncthreads();

        bool skip = (j * 64 > m0 + rbase + 15);
        if (!skip) {
            int st = j & 1;
            uint32_t kst = (uint32_t)(FKOFF + st * 17408);
            uint32_t vst = (uint32_t)(FVOFF + st * 18432);

            float s[8][4];
            #pragma unroll
            for (int nt = 0; nt < 8; nt++)
                #pragma unroll
                for (int q = 0; q < 4; q++) s[nt][q] = 0.f;

            #pragma unroll
            for (int kt = 0; kt < 8; kt++) {
                int kk = kt * 16 + ldc8;
                uint32_t aqh[4], aql[4];
                ldsm4(aqh, sb + (uint32_t)(FQH + ar * 136 + kk) * 2);
                ldsm4(aql, sb + (uint32_t)(FQL + ar * 136 + kk) * 2);
                #pragma unroll
                for (int np = 0; np < 4; np++) {
                    uint32_t kadr = sb + (kst + (np * 16 + ldr) * 136 + kk) * 2;
                    uint32_t rh[4], rl[4];
                    ldsm4(rh, kadr);
                    ldsm4(rl, kadr + 8704 * 2);
                    uint32_t b0h[2] = {rh[0], rh[2]}, b1h[2] = {rh[1], rh[3]};
                    uint32_t b0l[2] = {rl[0], rl[2]}, b1l[2] = {rl[1], rl[3]};
                    mma16816(s[np*2],   aqh, b0h);
                    mma16816(s[np*2],   aqh, b0l);
                    mma16816(s[np*2],   aql, b0h);
                    mma16816(s[np*2+1], aqh, b1h);
                    mma16816(s[np*2+1], aqh, b1l);
                    mma16816(s[np*2+1], aql, b1h);
                }
            }

            float mx0 = -1e30f, mx1 = -1e30f;
            #pragma unroll
            for (int nt = 0; nt < 8; nt++) {
                int gc = j * 64 + nt * 8 + (lane & 3) * 2;
                float v0 = s[nt][0] * scale; if (gc     > grow0)     v0 = -1e30f;
                float v1 = s[nt][1] * scale; if (gc + 1 > grow0)     v1 = -1e30f;
                float v2 = s[nt][2] * scale; if (gc     > grow0 + 8) v2 = -1e30f;
                float v3 = s[nt][3] * scale; if (gc + 1 > grow0 + 8) v3 = -1e30f;
                s[nt][0] = v0; s[nt][1] = v1; s[nt][2] = v2; s[nt][3] = v3;
                mx0 = fmaxf(mx0, fmaxf(v0, v1));
                mx1 = fmaxf(mx1, fmaxf(v2, v3));
            }
            mx0 = fmaxf(mx0, __shfl_xor_sync(0xffffffffu, mx0, 1));
            mx0 = fmaxf(mx0, __shfl_xor_sync(0xffffffffu, mx0, 2));
            mx1 = fmaxf(mx1, __shfl_xor_sync(0xffffffffu, mx1, 1));
            mx1 = fmaxf(mx1, __shfl_xor_sync(0xffffffffu, mx1, 2));
            float mn0 = fmaxf(m_r0, mx0), mn1 = fmaxf(m_r1, mx1);
            float al0 = __expf(m_r0 - mn0), al1 = __expf(m_r1 - mn1);
            float sm0 = 0.f, sm1 = 0.f;
            #pragma unroll
            for (int nt = 0; nt < 8; nt++) {
                float p0 = __expf(s[nt][0] - mn0);
                float p1 = __expf(s[nt][1] - mn0);
                float p2 = __expf(s[nt][2] - mn1);
                float p3 = __expf(s[nt][3] - mn1);
                s[nt][0] = p0; s[nt][1] = p1; s[nt][2] = p2; s[nt][3] = p3;
                sm0 += p0 + p1; sm1 += p2 + p3;
            }
            sm0 += __shfl_xor_sync(0xffffffffu, sm0, 1);
            sm0 += __shfl_xor_sync(0xffffffffu, sm0, 2);
            sm1 += __shfl_xor_sync(0xffffffffu, sm1, 1);
            sm1 += __shfl_xor_sync(0xffffffffu, sm1, 2);
            l_r0 = l_r0 * al0 + sm0;
            l_r1 = l_r1 * al1 + sm1;
            m_r0 = mn0; m_r1 = mn1;
            #pragma unroll
            for (int i = 0; i < 16; i++) {
                o[i][0] *= al0; o[i][1] *= al0;
                o[i][2] *= al1; o[i][3] *= al1;
            }

            #pragma unroll
            for (int kt2 = 0; kt2 < 4; kt2++) {
                uint32_t ah[4], apl[4];
                {
                    bf16 h0, lo0, h1, lo1;
                    splitf(s[2*kt2][0], h0, lo0); splitf(s[2*kt2][1], h1, lo1);
                    ah[0] = packbf2(h0, h1); apl[0] = packbf2(lo0, lo1);
                    splitf(s[2*kt2][2], h0, lo0); splitf(s[2*kt2][3], h1, lo1);
                    ah[1] = packbf2(h0, h1); apl[1] = packbf2(lo0, lo1);
                    splitf(s[2*kt2+1][0], h0, lo0); splitf(s[2*kt2+1][1], h1, lo1);
                    ah[2] = packbf2(h0, h1); apl[2] = packbf2(lo0, lo1);
                    splitf(s[2*kt2+1][2], h0, lo0); splitf(s[2*kt2+1][3], h1, lo1);
                    ah[3] = packbf2(h0, h1); apl[3] = packbf2(lo0, lo1);
                }
                int kk2 = kt2 * 16 + ldc8;
                #pragma unroll
                for (int np = 0; np < 8; np++) {
                    uint32_t vadr = sb + (vst + (np * 16 + ldr) * 72 + kk2) * 2;
                    uint32_t rh[4], rl[4];
                    ldsm4(rh, vadr);
                    ldsm4(rl, vadr + 9216 * 2);
                    uint32_t b0h[2] = {rh[0], rh[2]}, b1h[2] = {rh[1], rh[3]};
                    uint32_t b0l[2] = {rl[0], rl[2]}, b1l[2] = {rl[1], rl[3]};
                    mma16816(o[np*2],   ah,  b0h);
                    mma16816(o[np*2],   ah,  b0l);
                    mma16816(o[np*2],   apl, b0h);
                    mma16816(o[np*2+1], ah,  b1h);
                    mma16816(o[np*2+1], ah,  b1l);
                    mma16816(o[np*2+1], apl, b1h);
                }
            }
        }
        __syncthreads();
    }
    #undef LOAD_KV

    float inv0 = 1.f / l_r0, inv1 = 1.f / l_r1;
    int row0 = m0 + rbase + (lane >> 2);
    size_t base0 = (size_t)row0 * (NH * HD) + (size_t)h * HD;
    size_t base1 = base0 + (size_t)8 * (NH * HD);
    #pragma unroll
    for (int nt = 0; nt < 16; nt++) {
        int col = nt * 8 + (lane & 3) * 2;
        bf16 h0, lo0, h1, lo1;
        splitf(o[nt][0] * inv0, h0, lo0); splitf(o[nt][1] * inv0, h1, lo1);
        *(__nv_bfloat162*)(ao_h + base0 + col) = __nv_bfloat162(h0, h1);
        *(__nv_bfloat162*)(ao_l + base0 + col) = __nv_bfloat162(lo0, lo1);
        splitf(o[nt][2] * inv1, h0, lo0); splitf(o[nt][3] * inv1, h1, lo1);
        *(__nv_bfloat162*)(ao_h + base1 + col) = __nv_bfloat162(h0, h1);
        *(__nv_bfloat162*)(ao_l + base1 + col) = __nv_bfloat162(lo0, lo1);
    }
}

// ---------------- router -----------------------------------------------------------
__global__ void gate_topk_kernel(const float* __restrict__ h2, const float* __restrict__ gw,
                                 int* __restrict__ oidx, float* __restrict__ orw) {
    int t = blockIdx.x;
    int e = threadIdx.x >> 4, l = threadIdx.x & 15;
    const float* hr = h2 + (size_t)t * HDM;
    const float* wr = gw + (size_t)e * HDM;
    float p = 0.f;
    for (int k = l; k < HDM; k += 16) p += hr[k] * wr[k];
    #pragma unroll
    for (int o = 8; o; o >>= 1) p += __shfl_xor_sync(0xffffffffu, p, o);
    __shared__ float slog[NE];
    if (l == 0) slog[e] = p;
    __syncthreads();
    if (threadIdx.x == 0) {
        float pr[NE];
        float mx = -3.4e38f;
        for (int i = 0; i < NE; i++) { pr[i] = slog[i]; mx = fmaxf(mx, pr[i]); }
        float sum = 0.f;
        for (int i = 0; i < NE; i++) { pr[i] = __expf(pr[i] - mx); sum += pr[i]; }
        float inv = 1.f / sum;
        for (int i = 0; i < NE; i++) pr[i] *= inv;
        int sel[TOPK]; float sv[TOPK]; float wsum = 0.f;
        for (int k = 0; k < TOPK; k++) {
            int best = 0; float bv = -1.f;
            for (int i = 0; i < NE; i++)
                if (pr[i] > bv) { bv = pr[i]; best = i; }
            sel[k] = best; sv[k] = bv; wsum += bv; pr[best] = -2.f;
        }
        float winv = 1.f / wsum;
        for (int k = 0; k < TOPK; k++) { oidx[t * TOPK + k] = sel[k]; orw[t * TOPK + k] = sv[k] * winv; }
    }
}

// ---------------- deterministic routing sort ----------------------------------------
__global__ void route_kernel(const int* __restrict__ idx, int* __restrict__ counts,
                             int* __restrict__ offs, int* __restrict__ token_of,
                             int* __restrict__ slot_of) {
    int c = threadIdx.x;
    int start = c * (NSLOT / 32);
    int cnt[NE];
    #pragma unroll
    for (int e = 0; e < NE; e++) cnt[e] = 0;
    for (int i = 0; i < NSLOT / 32; i++) cnt[idx[start + i]]++;
    __shared__ int scnt[32][NE];
    __shared__ int sbase[32][NE];
    for (int e = 0; e < NE; e++) scnt[c][e] = cnt[e];
    __syncthreads();
    if (c == 0) {
        int off = 0;
        for (int e = 0; e < NE; e++) {
            offs[e] = off;
            int run = off;
            for (int cc = 0; cc < 32; cc++) { sbase[cc][e] = run; run += scnt[cc][e]; }
            counts[e] = run - off;
            off = run;
        }
    }
    __syncthreads();
    int base[NE];
    #pragma unroll
    for (int e = 0; e < NE; e++) base[e] = sbase[c][e];
    for (int i = 0; i < NSLOT / 32; i++) {
        int entry = start + i;
        int e = idx[entry];
        int pos = base[e]++;
        token_of[pos] = entry >> 2;
        slot_of[entry] = pos;
    }
}

// ---------------- silu(g)*u --------------------------------------------------------
__global__ void silu_mul_kernel(const float* __restrict__ gu, bf16* __restrict__ gh,
                                bf16* __restrict__ gl) {
    int s = blockIdx.x;
    const float* row = gu + (size_t)s * GUN;
    for (int i = threadIdx.x; i < ID; i += blockDim.x) {
        float x = row[i];
        float u = row[ID + i];
        float v = (x / (1.f + __expf(-x))) * u;
        bf16 h, l; splitf(v, h, l);
        gh[(size_t)s * ID + i] = h;
        gl[(size_t)s * ID + i] = l;
    }
}

// ---------------- final combine ------------------------------------------------------
__global__ void combine_kernel(const float* __restrict__ res, const float* __restrict__ ybuf,
                               const int* __restrict__ slot_of, const float* __restrict__ rw,
                               float* __restrict__ out) {
    int t = blockIdx.x;
    int s0 = slot_of[t*4+0], s1 = slot_of[t*4+1], s2 = slot_of[t*4+2], s3 = slot_of[t*4+3];
    float w0 = rw[t*4+0], w1 = rw[t*4+1], w2 = rw[t*4+2], w3 = rw[t*4+3];
    const float* y0 = ybuf + (size_t)s0 * HDM;
    const float* y1 = ybuf + (size_t)s1 * HDM;
    const float* y2 = ybuf + (size_t)s2 * HDM;
    const float* y3 = ybuf + (size_t)s3 * HDM;
    size_t base = (size_t)t * HDM;
    for (int i = threadIdx.x; i < HDM; i += blockDim.x)
        out[base + i] = res[base + i] + w0 * y0[i] + w1 * y1[i] + w2 * y2[i] + w3 * y3[i];
}

// ========================================================================================
extern "C" void kernel_launch(void* const* d_in, const int* in_sizes, int n_in,
                              void* d_out, int out_size) {
    const float* x    = (const float*)d_in[0];
    const float* pe   = (const float*)d_in[1];
    const float* q_w  = (const float*)d_in[3];
    const float* k_w  = (const float*)d_in[4];
    const float* v_w  = (const float*)d_in[5];
    const float* o_w  = (const float*)d_in[6];
    const float* q_nw = (const float*)d_in[7];
    const float* k_nw = (const float*)d_in[8];
    const float* ln1  = (const float*)d_in[9];
    const float* ln2  = (const float*)d_in[10];
    const float* gw   = (const float*)d_in[11];
    const float* gpw  = (const float*)d_in[12];
    const float* upw  = (const float*)d_in[13];
    const float* dpw  = (const float*)d_in[14];
    float* out = (float*)d_out;

    #define SYM(T, p, s) T p; cudaGetSymbolAddress((void**)&p, s)
    SYM(bf16*, wqkv_h, g_wqkv_h); SYM(bf16*, wqkv_l, g_wqkv_l);
    SYM(bf16*, wo_h, g_wo_h);     SYM(bf16*, wo_l, g_wo_l);
    SYM(bf16*, wgu_h, g_wgu_h);   SYM(bf16*, wgu_l, g_wgu_l);
    SYM(bf16*, wd_h, g_wd_h);     SYM(bf16*, wd_l, g_wd_l);
    SYM(bf16*, xn_h, g_xn_h);     SYM(bf16*, xn_l, g_xn_l);
    SYM(float*, qkvlin, g_qkvlin);
    SYM(bf16*, qh_h, g_qh_h);     SYM(bf16*, qh_l, g_qh_l);
    SYM(bf16*, kh_h, g_kh_h);     SYM(bf16*, kh_l, g_kh_l);
    SYM(bf16*, vt_h, g_vt_h);     SYM(bf16*, vt_l, g_vt_l);
    SYM(bf16*, ao_h, g_ao_h);     SYM(bf16*, ao_l, g_ao_l);
    SYM(float*, res, g_res);
    SYM(float*, h2f, g_h2f);
    SYM(bf16*, h2_h, g_h2_h);     SYM(bf16*, h2_l, g_h2_l);
    SYM(float*, gu, g_gu);
    SYM(bf16*, gg_h, g_g_h);      SYM(bf16*, gg_l, g_g_l);
    SYM(float*, ybuf, g_ybuf);
    SYM(int*, tidx, g_tidx);      SYM(float*, trw, g_trw);
    SYM(int*, counts, g_counts);  SYM(int*, offs, g_offs);
    SYM(int*, token_of, g_token_of); SYM(int*, slot_of, g_slot_of);
    #undef SYM

    static bool attr_done = false;
    if (!attr_done) {
        cudaFuncSetAttribute(gemm_mma<0,0>, cudaFuncAttributeMaxDynamicSharedMemorySize, SMEM_BYTES);
        cudaFuncSetAttribute(gemm_mma<2,0>, cudaFuncAttributeMaxDynamicSharedMemorySize, SMEM_BYTES);
        cudaFuncSetAttribute(gemm_mma<0,1>, cudaFuncAttributeMaxDynamicSharedMemorySize, SMEM_BYTES);
        cudaFuncSetAttribute(gemm_mma<0,2>, cudaFuncAttributeMaxDynamicSharedMemorySize, SMEM_BYTES);
        cudaFuncSetAttribute(flash_kernel, cudaFuncAttributeMaxDynamicSharedMemorySize, FSMEM);
        attr_done = true;
    }

    const float scale = 0.08838834764831845f;

    // ---- weight conversions ----
    {
        size_t nq = (size_t)NH*HD*HDM, nk = (size_t)NKV*HD*HDM;
        split_kernel<<<(unsigned)((nq+4095)/4096), 256>>>(q_w, wqkv_h, wqkv_l, nq);
        split_kernel<<<(unsigned)((nk+4095)/4096), 256>>>(k_w, wqkv_h + nq, wqkv_l + nq, nk);
        split_kernel<<<(unsigned)((nk+4095)/4096), 256>>>(v_w, wqkv_h + nq + nk, wqkv_l + nq + nk, nk);
        size_t no = (size_t)HDM*NH*HD;
        split_kernel<<<(unsigned)((no+4095)/4096), 256>>>(o_w, wo_h, wo_l, no);
        size_t ngu = (size_t)NE*ID*HDM;
        split_gu_kernel<<<(unsigned)((ngu+4095)/4096), 256>>>(gpw, upw, wgu_h, wgu_l);
        size_t nd = (size_t)NE*HDM*ID;
        split_kernel<<<(unsigned)((nd+4095)/4096), 256>>>(dpw, wd_h, wd_l, nd);
    }

    // ---- attention ----
    rmsnorm_kernel<<<SQ, 256>>>(x, ln1, nullptr, xn_h, xn_l, HDM);
    gemm_mma<0,0><<<dim3(QKVN/BN, SQ/BM, 1), 256, SMEM_BYTES>>>(
        xn_h, xn_l, HDM, 0, wqkv_h, wqkv_l, HDM, 0,
        qkvlin, QKVN, 0, HDM, nullptr, 0, nullptr, nullptr, nullptr);
    norm_rope_kernel<<<dim3(SQ, NH), HD>>>(qkvlin, 0, q_nw, pe, qh_h, qh_l);
    norm_rope_kernel<<<dim3(SQ, NKV), HD>>>(qkvlin, NH*HD, k_nw, pe, kh_h, kh_l);
    vtrans_kernel<<<(NKV*HD*SQ)/256, 256>>>(qkvlin, vt_h, vt_l);
    flash_kernel<<<dim3(SQ/128, NH), 256, FSMEM>>>(
        qh_h, qh_l, kh_h, kh_l, vt_h, vt_l, ao_h, ao_l, scale);
    gemm_mma<2,0><<<dim3(HDM/BN, SQ/BM, 1), 256, SMEM_BYTES>>>(
        ao_h, ao_l, NH*HD, 0, wo_h, wo_l, NH*HD, 0,
        res, HDM, 0, NH*HD, x, HDM, nullptr, nullptr, nullptr);

    // ---- MoE ----
    rmsnorm_kernel<<<SQ, 256>>>(res, ln2, h2f, h2_h, h2_l, HDM);
    gate_topk_kernel<<<SQ, 256>>>(h2f, gw, tidx, trw);
    route_kernel<<<1, 32>>>(tidx, counts, offs, token_of, slot_of);
    gemm_mma<0,1><<<dim3(GUN/BN, NSLOT/BM, NE), 256, SMEM_BYTES>>>(
        h2_h, h2_l, HDM, 0, wgu_h, wgu_l, HDM, (long)GUN*HDM,
        gu, GUN, 0, HDM, nullptr, 0, counts, offs, token_of);
    silu_mul_kernel<<<NSLOT, 256>>>(gu, gg_h, gg_l);
    gemm_mma<0,2><<<dim3(HDM/BN, NSLOT/BM, NE), 256, SMEM_BYTES>>>(
        gg_h, gg_l, ID, 0, wd_h, wd_l, ID, (long)HDM*ID,
        ybuf, HDM, 0, ID, nullptr, 0, counts, offs, token_of);
    combine_kernel<<<SQ, 256>>>(res, ybuf, slot_of, trw, out);
}

// round 7
// speedup vs baseline: 3.7897x; 1.2836x over previous
#include <cuda_runtime.h>
#include <cuda_fp16.h>
#include <cstdint>

#define SQ    2048
#define HDM   2048
#define NH    32
#define NKV   4
#define HD    128
#define NE    16
#define ID    768
#define TOPK  4
#define NSLOT (SQ*TOPK)
#define QKVN  (NH*HD + 2*NKV*HD)   // 5120
#define GUN   (2*ID)               // 1536
#define WSC   64.0f
#define WSCI  (1.0f/64.0f)

typedef __half h16;

// ---------------- device scratch -------------------------------------------
__device__ __align__(16) h16 g_wqkv_h[(size_t)QKVN*HDM],  g_wqkv_l[(size_t)QKVN*HDM];
__device__ __align__(16) h16 g_wo_h[(size_t)HDM*NH*HD],   g_wo_l[(size_t)HDM*NH*HD];
__device__ __align__(16) h16 g_wgu_h[(size_t)NE*GUN*HDM];
__device__ __align__(16) h16 g_wd_h[(size_t)NE*HDM*ID];
__device__ __align__(16) h16 g_xn_h[(size_t)SQ*HDM],      g_xn_l[(size_t)SQ*HDM];
__device__ __align__(16) float g_qkvlin[(size_t)SQ*QKVN];
__device__ __align__(16) h16 g_qh_h[(size_t)NH*SQ*HD],    g_qh_l[(size_t)NH*SQ*HD];
__device__ __align__(16) h16 g_kh_h[(size_t)NKV*SQ*HD],   g_kh_l[(size_t)NKV*SQ*HD];
__device__ __align__(16) h16 g_vt_h[(size_t)NKV*HD*SQ],   g_vt_l[(size_t)NKV*HD*SQ];
__device__ __align__(16) h16 g_ao_h[(size_t)SQ*NH*HD],    g_ao_l[(size_t)SQ*NH*HD];
__device__ __align__(16) float g_res[SQ*HDM];
__device__ __align__(16) float g_h2f[SQ*HDM];
__device__ __align__(16) h16 g_h2_h[(size_t)SQ*HDM];
__device__ __align__(16) float g_gu[(size_t)NSLOT*GUN];
__device__ __align__(16) h16 g_g_h[(size_t)NSLOT*ID];
__device__ __align__(16) float g_ybuf[(size_t)NSLOT*HDM];
__device__ int   g_tidx[NSLOT];
__device__ float g_trw[NSLOT];
__device__ int   g_counts[NE];
__device__ int   g_offs[NE];
__device__ int   g_token_of[NSLOT];
__device__ int   g_slot_of[NSLOT];

// ---------------- helpers ----------------------------------------------------
__device__ __forceinline__ void splitf(float v, h16& h, h16& l) {
    h = __float2half(v);
    l = __float2half(v - __half2float(h));
}
__device__ __forceinline__ uint32_t pack2h(h16 a, h16 b) {
    __half2 t(a, b);
    return *(uint32_t*)&t;
}
__device__ __forceinline__ void ldsm4(uint32_t r[4], uint32_t addr) {
    asm volatile("ldmatrix.sync.aligned.m8n8.x4.shared.b16 {%0,%1,%2,%3},[%4];"
        : "=r"(r[0]), "=r"(r[1]), "=r"(r[2]), "=r"(r[3]) : "r"(addr));
}
__device__ __forceinline__ void mma16816(float c[4], const uint32_t a[4], const uint32_t b[2]) {
    asm volatile("mma.sync.aligned.m16n8k16.row.col.f32.f16.f16.f32 "
        "{%0,%1,%2,%3},{%4,%5,%6,%7},{%8,%9},{%0,%1,%2,%3};"
        : "+f"(c[0]), "+f"(c[1]), "+f"(c[2]), "+f"(c[3])
        : "r"(a[0]), "r"(a[1]), "r"(a[2]), "r"(a[3]), "r"(b[0]), "r"(b[1]));
}
__device__ __forceinline__ void cp16(uint32_t dst, const void* src, int sz) {
    asm volatile("cp.async.cg.shared.global [%0],[%1],16,%2;\n" :: "r"(dst), "l"(src), "r"(sz));
}
__device__ __forceinline__ void cp_commit() { asm volatile("cp.async.commit_group;\n"); }
__device__ __forceinline__ void cp_wait1() { asm volatile("cp.async.wait_group 1;\n"); }

__device__ __forceinline__ float blockReduceSum(float v) {
    __shared__ float sh[8];
    int lane = threadIdx.x & 31, w = threadIdx.x >> 5;
    #pragma unroll
    for (int o = 16; o; o >>= 1) v += __shfl_xor_sync(0xffffffffu, v, o);
    if (lane == 0) sh[w] = v;
    __syncthreads();
    float r = (threadIdx.x < (blockDim.x >> 5)) ? sh[threadIdx.x] : 0.f;
    if (w == 0) {
        #pragma unroll
        for (int o = 4; o; o >>= 1) r += __shfl_xor_sync(0xffffffffu, r, o);
        if (lane == 0) sh[0] = r;
    }
    __syncthreads();
    r = sh[0];
    __syncthreads();
    return r;
}

// ---------------- weight split conversions (weights pre-scaled by WSC) ----------
__global__ void split_kernel(const float* __restrict__ in, h16* __restrict__ hi,
                             h16* __restrict__ lo, size_t n) {
    size_t base = (size_t)blockIdx.x * 4096 + threadIdx.x * 4;
    #pragma unroll
    for (int u = 0; u < 4; u++) {
        size_t i = base + u * 1024;
        if (i >= n) return;
        float4 v = *(const float4*)(in + i);
        h16 h0, l0, h1, l1, h2, l2, h3, l3;
        splitf(v.x * WSC, h0, l0); splitf(v.y * WSC, h1, l1);
        splitf(v.z * WSC, h2, l2); splitf(v.w * WSC, h3, l3);
        *(__half2*)(hi + i)     = __half2(h0, h1);
        *(__half2*)(hi + i + 2) = __half2(h2, h3);
        if (lo) {
            *(__half2*)(lo + i)     = __half2(l0, l1);
            *(__half2*)(lo + i + 2) = __half2(l2, l3);
        }
    }
}

// gate+up interleave, hi only (single-stream MoE), scaled
__global__ void split_gu_kernel(const float* __restrict__ gp, const float* __restrict__ up,
                                h16* __restrict__ hi) {
    size_t base = (size_t)blockIdx.x * 4096 + threadIdx.x * 4;
    #pragma unroll
    for (int u = 0; u < 4; u++) {
        size_t i = base + u * 1024;
        if (i >= (size_t)NE * ID * HDM) return;
        size_t e = i / ((size_t)ID * HDM);
        size_t rem = i - e * (size_t)ID * HDM;
        size_t dg = e * (size_t)GUN * HDM + rem;
        size_t du = dg + (size_t)ID * HDM;
        float4 vg = *(const float4*)(gp + i);
        float4 vu = *(const float4*)(up + i);
        *(__half2*)(hi + dg)     = __half2(__float2half(vg.x * WSC), __float2half(vg.y * WSC));
        *(__half2*)(hi + dg + 2) = __half2(__float2half(vg.z * WSC), __float2half(vg.w * WSC));
        *(__half2*)(hi + du)     = __half2(__float2half(vu.x * WSC), __float2half(vu.y * WSC));
        *(__half2*)(hi + du + 2) = __half2(__float2half(vu.z * WSC), __float2half(vu.w * WSC));
    }
}

// ---------------- rms norm ------------------------------------------------------
__global__ void rmsnorm_kernel(const float* __restrict__ x, const float* __restrict__ w,
                               float* __restrict__ outf, h16* __restrict__ oh,
                               h16* __restrict__ ol, int ncols) {
    size_t base = (size_t)blockIdx.x * ncols;
    float ss = 0.f;
    for (int i = threadIdx.x; i < ncols; i += blockDim.x) { float v = x[base + i]; ss += v * v; }
    ss = blockReduceSum(ss);
    float r = rsqrtf(ss / ncols + 1e-6f);
    for (int i = threadIdx.x; i < ncols; i += blockDim.x) {
        float v = w[i] * x[base + i] * r;
        if (outf) outf[base + i] = v;
        if (oh) {
            h16 h, l; splitf(v, h, l);
            oh[base + i] = h;
            if (ol) ol[base + i] = l;
        }
    }
}

// ---------------- per-head rmsnorm + rope --------------------------------------
__global__ void norm_rope_kernel(const float* __restrict__ lin, int colbase,
                                 const float* __restrict__ nw, const float* __restrict__ pe,
                                 h16* __restrict__ oh, h16* __restrict__ ol) {
    int t = blockIdx.x, h = blockIdx.y, d = threadIdx.x;
    float v = lin[(size_t)t * QKVN + colbase + h * HD + d];
    float ss = v * v;
    #pragma unroll
    for (int o = 16; o; o >>= 1) ss += __shfl_xor_sync(0xffffffffu, ss, o);
    __shared__ float wsum[4];
    if ((d & 31) == 0) wsum[d >> 5] = ss;
    __syncthreads();
    float tot = wsum[0] + wsum[1] + wsum[2] + wsum[3];
    float xn = nw[d] * v * rsqrtf(tot * (1.f / HD) + 1e-6f);
    __shared__ float sh[HD];
    sh[d] = xn;
    __syncthreads();
    float c = pe[(size_t)t * HD + d];
    float s = pe[(size_t)SQ * HD + (size_t)t * HD + d];
    float rot = (d < HD / 2) ? -sh[d + HD / 2] : sh[d - HD / 2];
    float o = xn * c + rot * s;
    size_t idx = ((size_t)h * SQ + t) * HD + d;
    h16 hh, ll; splitf(o, hh, ll);
    oh[idx] = hh; ol[idx] = ll;
}

// ---------------- V transpose + split -------------------------------------------
__global__ void vtrans_kernel(const float* __restrict__ qkvlin, h16* __restrict__ vh,
                              h16* __restrict__ vl) {
    int i = blockIdx.x * blockDim.x + threadIdx.x;
    int t = i & (SQ - 1);
    int d = (i >> 11) & (HD - 1);
    int kv = i >> 18;
    float v = qkvlin[(size_t)t * QKVN + (NH * HD + NKV * HD) + kv * HD + d];
    h16 h, l; splitf(v, h, l);
    vh[i] = h; vl[i] = l;
}

// =================================================================================
// fp16 mma.sync GEMM, 2-stage cp.async, NS=3 (x3 split) or NS=1 (single stream).
// MODE 0 dense / 1 gather rows / 2 direct ragged rows
// EPI 0 fp32*cscale / 2 fp32*cscale + residual
// =================================================================================
#define BM 128
#define BN 128
#define BK 32
#define BKP 40
#define TILE_HALF (BM * BKP)

template<int EPI, int MODE, int NS>
__global__ void __launch_bounds__(256, 2) gemm_mma(
    const h16* __restrict__ Ah, const h16* __restrict__ Al, int lda, long sAz,
    const h16* __restrict__ Bh, const h16* __restrict__ Bl, int ldb, long sBz,
    float* __restrict__ Cf, int ldc, long sCz,
    int K, float cscale, const float* __restrict__ epi, int lde,
    const int* __restrict__ counts, const int* __restrict__ offs,
    const int* __restrict__ token_of)
{
    constexpr uint32_t STB = (uint32_t)((NS == 3 ? 4 : 2) * TILE_HALF * 2);
    constexpr uint32_t OFF_AL = TILE_HALF * 2;
    constexpr uint32_t OFF_BH = (NS == 3 ? 2 : 1) * TILE_HALF * 2;
    constexpr uint32_t OFF_BL = 3 * TILE_HALF * 2;

    int z = blockIdx.z;
    int m0 = blockIdx.y * BM, n0 = blockIdx.x * BN;
    int Me = 0x7fffffff, off = 0;
    if (MODE != 0) { Me = counts[z]; if (m0 >= Me) return; off = offs[z]; }
    int nkt = K / BK;

    const h16* Ahp = Ah; const h16* Alp = Al;
    if (MODE == 0) { Ahp += (size_t)z * sAz; if (NS == 3) Alp += (size_t)z * sAz; }
    const h16* Bhp = Bh + (size_t)z * sBz;
    const h16* Blp = (NS == 3) ? (Bl + (size_t)z * sBz) : nullptr;

    extern __shared__ h16 smem[];
    uint32_t sbase = (uint32_t)__cvta_generic_to_shared(smem);

    int tid = threadIdx.x;
    int lr = tid >> 2;
    int lc = (tid & 3) * 8;

    int rl0 = m0 + lr, rl1 = m0 + lr + 64;
    bool av0 = true, av1 = true;
    size_t ar0, ar1;
    if (MODE == 1) {
        av0 = rl0 < Me; av1 = rl1 < Me;
        ar0 = av0 ? (size_t)token_of[off + rl0] : 0;
        ar1 = av1 ? (size_t)token_of[off + rl1] : 0;
    } else if (MODE == 2) {
        av0 = rl0 < Me; av1 = rl1 < Me;
        ar0 = av0 ? (size_t)(off + rl0) : 0;
        ar1 = av1 ? (size_t)(off + rl1) : 0;
    } else { ar0 = rl0; ar1 = rl1; }
    size_t offA0 = ar0 * (size_t)lda + lc;
    size_t offA1 = ar1 * (size_t)lda + lc;
    size_t offB0 = (size_t)(n0 + lr) * ldb + lc;
    size_t offB1 = (size_t)(n0 + lr + 64) * ldb + lc;
    int sz0 = av0 ? 16 : 0, sz1 = av1 ? 16 : 0;

    uint32_t dA0 = sbase + (lr * BKP + lc) * 2;
    uint32_t dA1 = sbase + ((lr + 64) * BKP + lc) * 2;

    const int warp = tid >> 5, lane = tid & 31;
    const int wm = (warp >> 1) * 32;
    const int wn = (warp & 1) * 64;
    const int ldr = lane & 15;
    const int ldc8 = (lane >> 4) * 8;

    float acc[2][8][4];
    #pragma unroll
    for (int i = 0; i < 2; i++)
        #pragma unroll
        for (int j = 0; j < 8; j++)
            #pragma unroll
            for (int q = 0; q < 4; q++) acc[i][j][q] = 0.f;

    #define LOAD_STAGE(kt) do {                                          \
        uint32_t nb = (uint32_t)((kt) & 1) * STB;                         \
        int k0_ = (kt) * BK;                                              \
        cp16(dA0 + nb, Ahp + offA0 + k0_, sz0);                           \
        cp16(dA1 + nb, Ahp + offA1 + k0_, sz1);                           \
        cp16(dA0 + nb + OFF_BH, Bhp + offB0 + k0_, 16);                   \
        cp16(dA1 + nb + OFF_BH, Bhp + offB1 + k0_, 16);                   \
        if (NS == 3) {                                                    \
            cp16(dA0 + nb + OFF_AL, Alp + offA0 + k0_, sz0);              \
            cp16(dA1 + nb + OFF_AL, Alp + offA1 + k0_, sz1);              \
            cp16(dA0 + nb + OFF_BL, Blp + offB0 + k0_, 16);               \
            cp16(dA1 + nb + OFF_BL, Blp + offB1 + k0_, 16);               \
        }                                                                 \
    } while (0)

    LOAD_STAGE(0);
    cp_commit();

    for (int kt = 0; kt < nkt; kt++) {
        if (kt + 1 < nkt) LOAD_STAGE(kt + 1);
        cp_commit();
        cp_wait1();
        __syncthreads();

        uint32_t bA = sbase + (uint32_t)(kt & 1) * STB;
        #pragma unroll
        for (int ks = 0; ks < 2; ks++) {
            int kk = ks * 16 + ldc8;
            uint32_t ah[2][4], al[2][4], bh[8][2], bl[8][2];
            #pragma unroll
            for (int mt = 0; mt < 2; mt++) {
                uint32_t adr = ((wm + mt * 16 + ldr) * BKP + kk) * 2;
                ldsm4(ah[mt], bA + adr);
                if (NS == 3) ldsm4(al[mt], bA + OFF_AL + adr);
            }
            #pragma unroll
            for (int np = 0; np < 4; np++) {
                uint32_t adr = ((wn + np * 16 + ldr) * BKP + kk) * 2;
                uint32_t r[4];
                ldsm4(r, bA + OFF_BH + adr);
                bh[np*2][0] = r[0]; bh[np*2+1][0] = r[1]; bh[np*2][1] = r[2]; bh[np*2+1][1] = r[3];
                if (NS == 3) {
                    ldsm4(r, bA + OFF_BL + adr);
                    bl[np*2][0] = r[0]; bl[np*2+1][0] = r[1]; bl[np*2][1] = r[2]; bl[np*2+1][1] = r[3];
                }
            }
            #pragma unroll
            for (int mt = 0; mt < 2; mt++)
                #pragma unroll
                for (int nt = 0; nt < 8; nt++) {
                    mma16816(acc[mt][nt], ah[mt], bh[nt]);
                    if (NS == 3) {
                        mma16816(acc[mt][nt], ah[mt], bl[nt]);
                        mma16816(acc[mt][nt], al[mt], bh[nt]);
                    }
                }
        }
        __syncthreads();
    }
    #undef LOAD_STAGE

    int er = lane >> 2;
    int ec = (lane & 3) * 2;
    #pragma unroll
    for (int mt = 0; mt < 2; mt++) {
        #pragma unroll
        for (int h = 0; h < 2; h++) {
            int mloc = m0 + wm + mt * 16 + h * 8 + er;
            bool mvalid = (MODE == 0) || (mloc < Me);
            if (!mvalid) continue;
            size_t crow = (MODE == 0) ? (size_t)mloc : (size_t)(off + mloc);
            #pragma unroll
            for (int nt = 0; nt < 8; nt++) {
                int col = n0 + wn + nt * 8 + ec;
                float v0 = acc[mt][nt][h * 2 + 0] * cscale;
                float v1 = acc[mt][nt][h * 2 + 1] * cscale;
                if (EPI == 2) {
                    float2 rr = *(const float2*)(epi + (size_t)mloc * lde + col);
                    v0 += rr.x; v1 += rr.y;
                }
                size_t ci = (size_t)z * sCz + crow * ldc + col;
                *(float2*)(Cf + ci) = make_float2(v0, v1);
            }
        }
    }
}

// =================================================================================
// Fused flash attention (fp16x3, reversed m-block order)
// =================================================================================
#define FQH 0
#define FQL 17408
#define FKOFF 34816
#define FVOFF 69632
#define FSMEM (106496 * 2)

__global__ void __launch_bounds__(256, 1) flash_kernel(
    const h16* __restrict__ qh_h, const h16* __restrict__ qh_l,
    const h16* __restrict__ kh_h, const h16* __restrict__ kh_l,
    const h16* __restrict__ vt_h, const h16* __restrict__ vt_l,
    h16* __restrict__ ao_h, h16* __restrict__ ao_l, float scale)
{
    int m0 = (gridDim.x - 1 - blockIdx.x) * 128;
    int h = blockIdx.y;
    int kvh = h >> 3;

    extern __shared__ h16 fsm[];
    uint32_t sb = (uint32_t)__cvta_generic_to_shared(fsm);

    int tid = threadIdx.x, wid = tid >> 5, lane = tid & 31;
    const int ldr = lane & 15, ldc8 = (lane >> 4) * 8;

    {
        const h16* qs_h = qh_h + ((size_t)h * SQ + m0) * HD;
        const h16* qs_l = qh_l + ((size_t)h * SQ + m0) * HD;
        for (int c = tid; c < 2048; c += 256) {
            int r = c >> 4, col = (c & 15) * 8;
            size_t go = (size_t)r * HD + col;
            cp16(sb + (uint32_t)(FQH + r * 136 + col) * 2, qs_h + go, 16);
            cp16(sb + (uint32_t)(FQL + r * 136 + col) * 2, qs_l + go, 16);
        }
    }
    cp_commit();

    int nj = (m0 + 128) >> 6;

    #define LOAD_KV(jj, stg) do {                                                     \
        for (int c = tid; c < 1024; c += 256) {                                        \
            int kr = c >> 4, kc = (c & 15) * 8;                                        \
            size_t kgo = ((size_t)kvh * SQ + (jj) * 64 + kr) * HD + kc;                \
            uint32_t kd = sb + (uint32_t)(FKOFF + (stg) * 17408 + kr * 136 + kc) * 2;  \
            cp16(kd, kh_h + kgo, 16);                                                  \
            cp16(kd + 8704 * 2, kh_l + kgo, 16);                                       \
            int vr = c >> 3, vc = (c & 7) * 8;                                         \
            size_t vgo = ((size_t)kvh * HD + vr) * SQ + (jj) * 64 + vc;                \
            cp16(sb + (uint32_t)(FVOFF + (stg) * 18432 + vr * 72 + vc) * 2, vt_h + vgo, 16); \
            cp16(sb + (uint32_t)(FVOFF + (stg) * 18432 + vr * 72 + vc) * 2 + 9216 * 2, vt_l + vgo, 16); \
        }                                                                               \
    } while (0)

    LOAD_KV(0, 0);
    cp_commit();

    int rbase = wid * 16;
    float m_r0 = -1e30f, m_r1 = -1e30f, l_r0 = 0.f, l_r1 = 0.f;
    float o[16][4];
    #pragma unroll
    for (int i = 0; i < 16; i++)
        #pragma unroll
        for (int q = 0; q < 4; q++) o[i][q] = 0.f;

    int grow0 = m0 + rbase + (lane >> 2);
    int ar = rbase + ldr;

    for (int j = 0; j < nj; j++) {
        if (j + 1 < nj) LOAD_KV(j + 1, (j + 1) & 1);
        cp_commit();
        cp_wait1();
        __syncthreads();

        bool skip = (j * 64 > m0 + rbase + 15);
        if (!skip) {
            int st = j & 1;
            uint32_t kst = (uint32_t)(FKOFF + st * 17408);
            uint32_t vst = (uint32_t)(FVOFF + st * 18432);

            float s[8][4];
            #pragma unroll
            for (int nt = 0; nt < 8; nt++)
                #pragma unroll
                for (int q = 0; q < 4; q++) s[nt][q] = 0.f;

            #pragma unroll
            for (int kt = 0; kt < 8; kt++) {
                int kk = kt * 16 + ldc8;
                uint32_t aqh[4], aql[4];
                ldsm4(aqh, sb + (uint32_t)(FQH + ar * 136 + kk) * 2);
                ldsm4(aql, sb + (uint32_t)(FQL + ar * 136 + kk) * 2);
                #pragma unroll
                for (int np = 0; np < 4; np++) {
                    uint32_t kadr = sb + (kst + (np * 16 + ldr) * 136 + kk) * 2;
                    uint32_t rh[4], rl[4];
                    ldsm4(rh, kadr);
                    ldsm4(rl, kadr + 8704 * 2);
                    uint32_t b0h[2] = {rh[0], rh[2]}, b1h[2] = {rh[1], rh[3]};
                    uint32_t b0l[2] = {rl[0], rl[2]}, b1l[2] = {rl[1], rl[3]};
                    mma16816(s[np*2],   aqh, b0h);
                    mma16816(s[np*2],   aqh, b0l);
                    mma16816(s[np*2],   aql, b0h);
                    mma16816(s[np*2+1], aqh, b1h);
                    mma16816(s[np*2+1], aqh, b1l);
                    mma16816(s[np*2+1], aql, b1h);
                }
            }

            float mx0 = -1e30f, mx1 = -1e30f;
            #pragma unroll
            for (int nt = 0; nt < 8; nt++) {
                int gc = j * 64 + nt * 8 + (lane & 3) * 2;
                float v0 = s[nt][0] * scale; if (gc     > grow0)     v0 = -1e30f;
                float v1 = s[nt][1] * scale; if (gc + 1 > grow0)     v1 = -1e30f;
                float v2 = s[nt][2] * scale; if (gc     > grow0 + 8) v2 = -1e30f;
                float v3 = s[nt][3] * scale; if (gc + 1 > grow0 + 8) v3 = -1e30f;
                s[nt][0] = v0; s[nt][1] = v1; s[nt][2] = v2; s[nt][3] = v3;
                mx0 = fmaxf(mx0, fmaxf(v0, v1));
                mx1 = fmaxf(mx1, fmaxf(v2, v3));
            }
            mx0 = fmaxf(mx0, __shfl_xor_sync(0xffffffffu, mx0, 1));
            mx0 = fmaxf(mx0, __shfl_xor_sync(0xffffffffu, mx0, 2));
            mx1 = fmaxf(mx1, __shfl_xor_sync(0xffffffffu, mx1, 1));
            mx1 = fmaxf(mx1, __shfl_xor_sync(0xffffffffu, mx1, 2));
            float mn0 = fmaxf(m_r0, mx0), mn1 = fmaxf(m_r1, mx1);
            float al0 = __expf(m_r0 - mn0), al1 = __expf(m_r1 - mn1);
            float sm0 = 0.f, sm1 = 0.f;
            #pragma unroll
            for (int nt = 0; nt < 8; nt++) {
                float p0 = __expf(s[nt][0] - mn0);
                float p1 = __expf(s[nt][1] - mn0);
                float p2 = __expf(s[nt][2] - mn1);
                float p3 = __expf(s[nt][3] - mn1);
                s[nt][0] = p0; s[nt][1] = p1; s[nt][2] = p2; s[nt][3] = p3;
                sm0 += p0 + p1; sm1 += p2 + p3;
            }
            sm0 += __shfl_xor_sync(0xffffffffu, sm0, 1);
            sm0 += __shfl_xor_sync(0xffffffffu, sm0, 2);
            sm1 += __shfl_xor_sync(0xffffffffu, sm1, 1);
            sm1 += __shfl_xor_sync(0xffffffffu, sm1, 2);
            l_r0 = l_r0 * al0 + sm0;
            l_r1 = l_r1 * al1 + sm1;
            m_r0 = mn0; m_r1 = mn1;
            #pragma unroll
            for (int i = 0; i < 16; i++) {
                o[i][0] *= al0; o[i][1] *= al0;
                o[i][2] *= al1; o[i][3] *= al1;
            }

            #pragma unroll
            for (int kt2 = 0; kt2 < 4; kt2++) {
                uint32_t ah[4], apl[4];
                {
                    h16 h0, lo0, h1, lo1;
                    splitf(s[2*kt2][0], h0, lo0); splitf(s[2*kt2][1], h1, lo1);
                    ah[0] = pack2h(h0, h1); apl[0] = pack2h(lo0, lo1);
                    splitf(s[2*kt2][2], h0, lo0); splitf(s[2*kt2][3], h1, lo1);
                    ah[1] = pack2h(h0, h1); apl[1] = pack2h(lo0, lo1);
                    splitf(s[2*kt2+1][0], h0, lo0); splitf(s[2*kt2+1][1], h1, lo1);
                    ah[2] = pack2h(h0, h1); apl[2] = pack2h(lo0, lo1);
                    splitf(s[2*kt2+1][2], h0, lo0); splitf(s[2*kt2+1][3], h1, lo1);
                    ah[3] = pack2h(h0, h1); apl[3] = pack2h(lo0, lo1);
                }
                int kk2 = kt2 * 16 + ldc8;
                #pragma unroll
                for (int np = 0; np < 8; np++) {
                    uint32_t vadr = sb + (vst + (np * 16 + ldr) * 72 + kk2) * 2;
                    uint32_t rh[4], rl[4];
                    ldsm4(rh, vadr);
                    ldsm4(rl, vadr + 9216 * 2);
                    uint32_t b0h[2] = {rh[0], rh[2]}, b1h[2] = {rh[1], rh[3]};
                    uint32_t b0l[2] = {rl[0], rl[2]}, b1l[2] = {rl[1], rl[3]};
                    mma16816(o[np*2],   ah,  b0h);
                    mma16816(o[np*2],   ah,  b0l);
                    mma16816(o[np*2],   apl, b0h);
                    mma16816(o[np*2+1], ah,  b1h);
                    mma16816(o[np*2+1], ah,  b1l);
                    mma16816(o[np*2+1], apl, b1h);
                }
            }
        }
        __syncthreads();
    }
    #undef LOAD_KV

    float inv0 = 1.f / l_r0, inv1 = 1.f / l_r1;
    int row0 = m0 + rbase + (lane >> 2);
    size_t base0 = (size_t)row0 * (NH * HD) + (size_t)h * HD;
    size_t base1 = base0 + (size_t)8 * (NH * HD);
    #pragma unroll
    for (int nt = 0; nt < 16; nt++) {
        int col = nt * 8 + (lane & 3) * 2;
        h16 h0, lo0, h1, lo1;
        splitf(o[nt][0] * inv0, h0, lo0); splitf(o[nt][1] * inv0, h1, lo1);
        *(__half2*)(ao_h + base0 + col) = __half2(h0, h1);
        *(__half2*)(ao_l + base0 + col) = __half2(lo0, lo1);
        splitf(o[nt][2] * inv1, h0, lo0); splitf(o[nt][3] * inv1, h1, lo1);
        *(__half2*)(ao_h + base1 + col) = __half2(h0, h1);
        *(__half2*)(ao_l + base1 + col) = __half2(lo0, lo1);
    }
}

// ---------------- router -----------------------------------------------------------
__global__ void gate_topk_kernel(const float* __restrict__ h2, const float* __restrict__ gw,
                                 int* __restrict__ oidx, float* __restrict__ orw) {
    int t = blockIdx.x;
    int e = threadIdx.x >> 4, l = threadIdx.x & 15;
    const float* hr = h2 + (size_t)t * HDM;
    const float* wr = gw + (size_t)e * HDM;
    float p = 0.f;
    for (int k = l; k < HDM; k += 16) p += hr[k] * wr[k];
    #pragma unroll
    for (int o = 8; o; o >>= 1) p += __shfl_xor_sync(0xffffffffu, p, o);
    __shared__ float slog[NE];
    if (l == 0) slog[e] = p;
    __syncthreads();
    if (threadIdx.x == 0) {
        float pr[NE];
        float mx = -3.4e38f;
        for (int i = 0; i < NE; i++) { pr[i] = slog[i]; mx = fmaxf(mx, pr[i]); }
        float sum = 0.f;
        for (int i = 0; i < NE; i++) { pr[i] = __expf(pr[i] - mx); sum += pr[i]; }
        float inv = 1.f / sum;
        for (int i = 0; i < NE; i++) pr[i] *= inv;
        int sel[TOPK]; float sv[TOPK]; float wsum = 0.f;
        for (int k = 0; k < TOPK; k++) {
            int best = 0; float bv = -1.f;
            for (int i = 0; i < NE; i++)
                if (pr[i] > bv) { bv = pr[i]; best = i; }
            sel[k] = best; sv[k] = bv; wsum += bv; pr[best] = -2.f;
        }
        float winv = 1.f / wsum;
        for (int k = 0; k < TOPK; k++) { oidx[t * TOPK + k] = sel[k]; orw[t * TOPK + k] = sv[k] * winv; }
    }
}

// ---------------- deterministic routing sort ----------------------------------------
__global__ void route_kernel(const int* __restrict__ idx, int* __restrict__ counts,
                             int* __restrict__ offs, int* __restrict__ token_of,
                             int* __restrict__ slot_of) {
    int c = threadIdx.x;
    int start = c * (NSLOT / 32);
    int cnt[NE];
    #pragma unroll
    for (int e = 0; e < NE; e++) cnt[e] = 0;
    for (int i = 0; i < NSLOT / 32; i++) cnt[idx[start + i]]++;
    __shared__ int scnt[32][NE];
    __shared__ int sbase[32][NE];
    for (int e = 0; e < NE; e++) scnt[c][e] = cnt[e];
    __syncthreads();
    if (c == 0) {
        int off = 0;
        for (int e = 0; e < NE; e++) {
            offs[e] = off;
            int run = off;
            for (int cc = 0; cc < 32; cc++) { sbase[cc][e] = run; run += scnt[cc][e]; }
            counts[e] = run - off;
            off = run;
        }
    }
    __syncthreads();
    int base[NE];
    #pragma unroll
    for (int e = 0; e < NE; e++) base[e] = sbase[c][e];
    for (int i = 0; i < NSLOT / 32; i++) {
        int entry = start + i;
        int e = idx[entry];
        int pos = base[e]++;
        token_of[pos] = entry >> 2;
        slot_of[entry] = pos;
    }
}

// ---------------- silu(g)*u (single fp16 out) ---------------------------------------
__global__ void silu_mul_kernel(const float* __restrict__ gu, h16* __restrict__ gh) {
    int s = blockIdx.x;
    const float* row = gu + (size_t)s * GUN;
    for (int i = threadIdx.x; i < ID; i += blockDim.x) {
        float x = row[i];
        float u = row[ID + i];
        float v = (x / (1.f + __expf(-x))) * u;
        gh[(size_t)s * ID + i] = __float2half(v);
    }
}

// ---------------- final combine ------------------------------------------------------
__global__ void combine_kernel(const float* __restrict__ res, const float* __restrict__ ybuf,
                               const int* __restrict__ slot_of, const float* __restrict__ rw,
                               float* __restrict__ out) {
    int t = blockIdx.x;
    int s0 = slot_of[t*4+0], s1 = slot_of[t*4+1], s2 = slot_of[t*4+2], s3 = slot_of[t*4+3];
    float w0 = rw[t*4+0], w1 = rw[t*4+1], w2 = rw[t*4+2], w3 = rw[t*4+3];
    const float* y0 = ybuf + (size_t)s0 * HDM;
    const float* y1 = ybuf + (size_t)s1 * HDM;
    const float* y2 = ybuf + (size_t)s2 * HDM;
    const float* y3 = ybuf + (size_t)s3 * HDM;
    size_t base = (size_t)t * HDM;
    for (int i = threadIdx.x; i < HDM; i += blockDim.x)
        out[base + i] = res[base + i] + w0 * y0[i] + w1 * y1[i] + w2 * y2[i] + w3 * y3[i];
}

// ========================================================================================
extern "C" void kernel_launch(void* const* d_in, const int* in_sizes, int n_in,
                              void* d_out, int out_size) {
    const float* x    = (const float*)d_in[0];
    const float* pe   = (const float*)d_in[1];
    const float* q_w  = (const float*)d_in[3];
    const float* k_w  = (const float*)d_in[4];
    const float* v_w  = (const float*)d_in[5];
    const float* o_w  = (const float*)d_in[6];
    const float* q_nw = (const float*)d_in[7];
    const float* k_nw = (const float*)d_in[8];
    const float* ln1  = (const float*)d_in[9];
    const float* ln2  = (const float*)d_in[10];
    const float* gw   = (const float*)d_in[11];
    const float* gpw  = (const float*)d_in[12];
    const float* upw  = (const float*)d_in[13];
    const float* dpw  = (const float*)d_in[14];
    float* out = (float*)d_out;

    #define SYM(T, p, s) T p; cudaGetSymbolAddress((void**)&p, s)
    SYM(h16*, wqkv_h, g_wqkv_h); SYM(h16*, wqkv_l, g_wqkv_l);
    SYM(h16*, wo_h, g_wo_h);     SYM(h16*, wo_l, g_wo_l);
    SYM(h16*, wgu_h, g_wgu_h);
    SYM(h16*, wd_h, g_wd_h);
    SYM(h16*, xn_h, g_xn_h);     SYM(h16*, xn_l, g_xn_l);
    SYM(float*, qkvlin, g_qkvlin);
    SYM(h16*, qh_h, g_qh_h);     SYM(h16*, qh_l, g_qh_l);
    SYM(h16*, kh_h, g_kh_h);     SYM(h16*, kh_l, g_kh_l);
    SYM(h16*, vt_h, g_vt_h);     SYM(h16*, vt_l, g_vt_l);
    SYM(h16*, ao_h, g_ao_h);     SYM(h16*, ao_l, g_ao_l);
    SYM(float*, res, g_res);
    SYM(float*, h2f, g_h2f);
    SYM(h16*, h2_h, g_h2_h);
    SYM(float*, gu, g_gu);
    SYM(h16*, gg_h, g_g_h);
    SYM(float*, ybuf, g_ybuf);
    SYM(int*, tidx, g_tidx);      SYM(float*, trw, g_trw);
    SYM(int*, counts, g_counts);  SYM(int*, offs, g_offs);
    SYM(int*, token_of, g_token_of); SYM(int*, slot_of, g_slot_of);
    #undef SYM

    constexpr int SMEM3 = 4 * TILE_HALF * 2 * 2;   // 81920
    constexpr int SMEM1 = 2 * TILE_HALF * 2 * 2;   // 40960
    static bool attr_done = false;
    if (!attr_done) {
        cudaFuncSetAttribute(gemm_mma<0,0,3>, cudaFuncAttributeMaxDynamicSharedMemorySize, SMEM3);
        cudaFuncSetAttribute(gemm_mma<2,0,3>, cudaFuncAttributeMaxDynamicSharedMemorySize, SMEM3);
        cudaFuncSetAttribute(gemm_mma<0,1,1>, cudaFuncAttributeMaxDynamicSharedMemorySize, SMEM1);
        cudaFuncSetAttribute(gemm_mma<0,2,1>, cudaFuncAttributeMaxDynamicSharedMemorySize, SMEM1);
        cudaFuncSetAttribute(flash_kernel, cudaFuncAttributeMaxDynamicSharedMemorySize, FSMEM);
        attr_done = true;
    }

    const float scale = 0.08838834764831845f;

    // ---- launches 1-5: QKV weight splits + O split + ln1 (QKV GEMM lands at #6 for ncu) ----
    size_t nq = (size_t)NH*HD*HDM, nk = (size_t)NKV*HD*HDM;
    split_kernel<<<(unsigned)((nq+4095)/4096), 256>>>(q_w, wqkv_h, wqkv_l, nq);
    split_kernel<<<(unsigned)((nk+4095)/4096), 256>>>(k_w, wqkv_h + nq, wqkv_l + nq, nk);
    split_kernel<<<(unsigned)((nk+4095)/4096), 256>>>(v_w, wqkv_h + nq + nk, wqkv_l + nq + nk, nk);
    size_t no = (size_t)HDM*NH*HD;
    split_kernel<<<(unsigned)((no+4095)/4096), 256>>>(o_w, wo_h, wo_l, no);
    rmsnorm_kernel<<<SQ, 256>>>(x, ln1, nullptr, xn_h, xn_l, HDM);

    // #6: QKV GEMM (profiled)
    gemm_mma<0,0,3><<<dim3(QKVN/BN, SQ/BM, 1), 256, SMEM3>>>(
        xn_h, xn_l, HDM, 0, wqkv_h, wqkv_l, HDM, 0,
        qkvlin, QKVN, 0, HDM, WSCI, nullptr, 0, nullptr, nullptr, nullptr);

    norm_rope_kernel<<<dim3(SQ, NH), HD>>>(qkvlin, 0, q_nw, pe, qh_h, qh_l);
    norm_rope_kernel<<<dim3(SQ, NKV), HD>>>(qkvlin, NH*HD, k_nw, pe, kh_h, kh_l);
    vtrans_kernel<<<(NKV*HD*SQ)/256, 256>>>(qkvlin, vt_h, vt_l);
    flash_kernel<<<dim3(SQ/128, NH), 256, FSMEM>>>(
        qh_h, qh_l, kh_h, kh_l, vt_h, vt_l, ao_h, ao_l, scale);
    gemm_mma<2,0,3><<<dim3(HDM/BN, SQ/BM, 1), 256, SMEM3>>>(
        ao_h, ao_l, NH*HD, 0, wo_h, wo_l, NH*HD, 0,
        res, HDM, 0, NH*HD, WSCI, x, HDM, nullptr, nullptr, nullptr);

    // ---- MoE (expert weights hi-only, single-stream fp16) ----
    size_t ngu = (size_t)NE*ID*HDM;
    split_gu_kernel<<<(unsigned)((ngu+4095)/4096), 256>>>(gpw, upw, wgu_h);
    size_t nd = (size_t)NE*HDM*ID;
    split_kernel<<<(unsigned)((nd+4095)/4096), 256>>>(dpw, wd_h, nullptr, nd);
    rmsnorm_kernel<<<SQ, 256>>>(res, ln2, h2f, h2_h, nullptr, HDM);
    gate_topk_kernel<<<SQ, 256>>>(h2f, gw, tidx, trw);
    route_kernel<<<1, 32>>>(tidx, counts, offs, token_of, slot_of);
    gemm_mma<0,1,1><<<dim3(GUN/BN, NSLOT/BM, NE), 256, SMEM1>>>(
        h2_h, nullptr, HDM, 0, wgu_h, nullptr, HDM, (long)GUN*HDM,
        gu, GUN, 0, HDM, WSCI, nullptr, 0, counts, offs, token_of);
    silu_mul_kernel<<<NSLOT, 256>>>(gu, gg_h);
    gemm_mma<0,2,1><<<dim3(HDM/BN, NSLOT/BM, NE), 256, SMEM1>>>(
        gg_h, nullptr, ID, 0, wd_h, nullptr, ID, (long)HDM*ID,
        ybuf, HDM, 0, ID, WSCI, nullptr, 0, counts, offs, token_of);
    combine_kernel<<<SQ, 256>>>(res, ybuf, slot_of, trw, out);
}